// round 5
// baseline (speedup 1.0000x reference)
#include <cuda_runtime.h>
#include <cuda_bf16.h>
#include <math.h>
#include <stdint.h>

#define L_  4
#define H_  12
#define E_  768
#define HS_ 64
#define V_  32000
#define B_  2
#define T_  1024
#define BT  2048
#define FF  3072
#define NQKV 2304

// ---- weight scratch offsets (elements) ----
#define WPL 7077888ull
#define OFF_QKV(l) ((size_t)(l) * WPL)
#define OFF_O(l)   (OFF_QKV(l) + 1769472ull)
#define OFF_W1(l)  (OFF_QKV(l) + 2359296ull)
#define OFF_W2(l)  (OFF_QKV(l) + 4718592ull)
#define OFF_LM     ((size_t)4 * WPL)
#define WTOT       (OFF_LM + 24576000ull)

// ---------------- scratch (static device globals) ----------------------------
__device__ float g_x[BT * E_];
__device__ float g_qkv[BT * NQKV];
__device__ __nv_bfloat16 g_hhi[BT * E_];
__device__ __nv_bfloat16 g_hlo[BT * E_];
__device__ __nv_bfloat16 g_ohi[BT * E_];
__device__ __nv_bfloat16 g_olo[BT * E_];
__device__ __nv_bfloat16 g_ffhi[BT * FF];
__device__ __nv_bfloat16 g_fflo[BT * FF];
__device__ float g_bqkv[L_ * NQKV];
__device__ __nv_bfloat16 g_wthi[WTOT];
__device__ __nv_bfloat16 g_wtlo[WTOT];
__device__ float g_rowloss[BT];
__device__ float g_logits_scratch[(size_t)BT * V_];

// ---------------- PTX helpers (all non-'a' features) -------------------------
__device__ __forceinline__ uint32_t smem_u32(const void* p) {
    uint32_t a;
    asm("{ .reg .u64 t; cvta.to.shared.u64 t, %1; cvt.u32.u64 %0, t; }" : "=r"(a) : "l"(p));
    return a;
}
__device__ __forceinline__ void mma16816(float* c, const uint32_t* a, uint32_t b0, uint32_t b1) {
    asm volatile(
        "mma.sync.aligned.m16n8k16.row.col.f32.bf16.bf16.f32 "
        "{%0,%1,%2,%3}, {%4,%5,%6,%7}, {%8,%9}, {%0,%1,%2,%3};"
        : "+f"(c[0]), "+f"(c[1]), "+f"(c[2]), "+f"(c[3])
        : "r"(a[0]), "r"(a[1]), "r"(a[2]), "r"(a[3]), "r"(b0), "r"(b1));
}
__device__ __forceinline__ void ldsm4(uint32_t* r, uint32_t addr) {
    asm volatile("ldmatrix.sync.aligned.m8n8.x4.shared.b16 {%0,%1,%2,%3}, [%4];"
                 : "=r"(r[0]), "=r"(r[1]), "=r"(r[2]), "=r"(r[3]) : "r"(addr));
}
__device__ __forceinline__ void cpasync16(uint32_t dst, const void* src) {
    asm volatile("cp.async.cg.shared.global [%0], [%1], 16;" :: "r"(dst), "l"(src));
}

// ---------------- fused QKV weight repack+transpose+split --------------------
// (L,H,E,HS) fp32 -> [N=2304, K=E] bf16 hi/lo for one layer.
__global__ __launch_bounds__(256) void wconv_qkv_kernel(const float* __restrict__ Wq,
                                                        const float* __restrict__ Wk,
                                                        const float* __restrict__ Wv,
                                                        __nv_bfloat16* __restrict__ Whi,
                                                        __nv_bfloat16* __restrict__ Wlo,
                                                        int l) {
    __shared__ float s[32][33];
    int n0 = blockIdx.y * 32, e0 = blockIdx.x * 32;
    int tx = threadIdx.x, ty = threadIdx.y;
    int sel = n0 / E_;                 // 0:q 1:k 2:v
    int nn = n0 % E_;
    int h = nn >> 6, hs0 = nn & 63;    // hs0 in {0,32}
    const float* src = sel == 0 ? Wq : (sel == 1 ? Wk : Wv);
    const float* base = src + ((size_t)(l * H_ + h) * E_) * 64;
#pragma unroll
    for (int i = 0; i < 4; i++) {
        int e = ty + 8 * i;
        s[e][tx] = base[(size_t)(e0 + e) * 64 + hs0 + tx];
    }
    __syncthreads();
#pragma unroll
    for (int i = 0; i < 4; i++) {
        int nl = ty + 8 * i;
        float x = s[tx][nl];
        __nv_bfloat16 hh = __float2bfloat16(x);
        __nv_bfloat16 ll = __float2bfloat16(x - __bfloat162float(hh));
        size_t oi = (size_t)(n0 + nl) * E_ + e0 + tx;
        Whi[oi] = hh;
        Wlo[oi] = ll;
    }
}

// ---------------- weight transpose + bf16 hi/lo split ------------------------
__global__ __launch_bounds__(256) void wconvt_kernel(const float* __restrict__ W,
                                                     __nv_bfloat16* __restrict__ Whi,
                                                     __nv_bfloat16* __restrict__ Wlo,
                                                     int K, int N) {
    __shared__ float s[32][33];
    int k0 = blockIdx.y * 32, n0 = blockIdx.x * 32;
    int tx = threadIdx.x, ty = threadIdx.y;
#pragma unroll
    for (int i = 0; i < 4; i++)
        s[ty + 8 * i][tx] = W[(size_t)(k0 + ty + 8 * i) * N + n0 + tx];
    __syncthreads();
#pragma unroll
    for (int i = 0; i < 4; i++) {
        int n = ty + 8 * i;
        float x = s[tx][n];
        __nv_bfloat16 h = __float2bfloat16(x);
        __nv_bfloat16 l = __float2bfloat16(x - __bfloat162float(h));
        size_t oi = (size_t)(n0 + n) * K + k0 + tx;
        Whi[oi] = h;
        Wlo[oi] = l;
    }
}

// ---------------- concat qkv bias -------------------------------------------
__global__ __launch_bounds__(256) void biascat_kernel(const float* __restrict__ bq,
                                                      const float* __restrict__ bk,
                                                      const float* __restrict__ bv,
                                                      float* __restrict__ out) {
    int i = blockIdx.x * 256 + threadIdx.x;
    if (i >= L_ * NQKV) return;
    int l = i / NQKV, c = i % NQKV;
    float v;
    if (c < E_)            v = bq[l * E_ + c];
    else if (c < 2 * E_)   v = bk[l * E_ + c - E_];
    else                   v = bv[l * E_ + c - 2 * E_];
    out[i] = v;
}

// ---------------- embedding -------------------------------------------------
__global__ __launch_bounds__(256) void embed_kernel(const int* __restrict__ idx,
                                                    const float* __restrict__ tok,
                                                    const float* __restrict__ pos,
                                                    float* __restrict__ x) {
    int i = blockIdx.x * 256 + threadIdx.x;
    int e = i % E_;
    int t = i / E_;
    int token = idx[t];
    x[i] = tok[(size_t)token * E_ + e] + pos[(t % T_) * E_ + e];
}

// ---------------- layernorm -> bf16 hi/lo ------------------------------------
__global__ __launch_bounds__(256) void ln_kernel(const float* __restrict__ x,
                                                 const float* __restrict__ g,
                                                 const float* __restrict__ b,
                                                 __nv_bfloat16* __restrict__ hi,
                                                 __nv_bfloat16* __restrict__ lo) {
    int row = blockIdx.x;
    int tid = threadIdx.x;
    const float* xr = x + (size_t)row * E_;
    float v[3], s = 0.f, sq = 0.f;
#pragma unroll
    for (int i = 0; i < 3; i++) {
        v[i] = xr[tid + i * 256];
        s += v[i];
        sq += v[i] * v[i];
    }
#pragma unroll
    for (int o = 16; o > 0; o >>= 1) {
        s  += __shfl_xor_sync(0xffffffffu, s, o);
        sq += __shfl_xor_sync(0xffffffffu, sq, o);
    }
    __shared__ float ss[8], ssq[8];
    if ((tid & 31) == 0) { ss[tid >> 5] = s; ssq[tid >> 5] = sq; }
    __syncthreads();
    s = 0.f; sq = 0.f;
#pragma unroll
    for (int i = 0; i < 8; i++) { s += ss[i]; sq += ssq[i]; }
    float mean = s * (1.f / E_);
    float var  = sq * (1.f / E_) - mean * mean;
    float rstd = rsqrtf(var + 1e-5f);
    size_t rb = (size_t)row * E_;
#pragma unroll
    for (int i = 0; i < 3; i++) {
        int e = tid + i * 256;
        float y = (v[i] - mean) * rstd * g[e] + b[e];
        __nv_bfloat16 h = __float2bfloat16(y);
        hi[rb + e] = h;
        lo[rb + e] = __float2bfloat16(y - __bfloat162float(h));
    }
}

// ---------------- tensor-core GEMM (bf16 hi/lo, all-cp.async, 3 stages) ------
// C[M,N] = A @ Wt^T; A,B pre-split bf16 hi/lo, row-major [M,K]/[N,K].
// CTA 128x256, BK=32, 256 thr (8 warps 2x4), warp tile 64x64.
// Stage (48KB): Ahi@0(8K), Alo@8192, Bhi@16384(16K), Blo@32768.
// 64B rows, 16B-chunk swizzle: phys = chunk ^ ((row>>1)&3).  3 stages.
#define STGB 49152
#define GEMM_SMEM (3 * STGB)
__global__ __launch_bounds__(256, 1)
void gemm_tc_kernel(const __nv_bfloat16* __restrict__ Ahi,
                    const __nv_bfloat16* __restrict__ Alo,
                    const __nv_bfloat16* __restrict__ Bhi,
                    const __nv_bfloat16* __restrict__ Blo,
                    const float* __restrict__ bias,
                    const float* __restrict__ resid,
                    float* __restrict__ C,
                    __nv_bfloat16* __restrict__ Chi,
                    __nv_bfloat16* __restrict__ Clo,
                    int N, int K, int relu) {
    extern __shared__ __align__(16) char smem[];
    int tid = threadIdx.x, lane = tid & 31, wid = tid >> 5;
    int wm = wid >> 2, wn = wid & 3;
    int row0 = blockIdx.y << 7, col0 = blockIdx.x << 8;
    uint32_t sb = smem_u32(smem);

    float acc[4][8][4] = {};

    const int nCh = K >> 5;
    // A fill: frow = tid>>1 (0..127), 2 chunks
    int frow = tid >> 1;
    int fc0 = (tid & 1) << 1;
    uint32_t fsw = (uint32_t)((frow >> 1) & 3);
    // B fill: brow = tid (0..255), 4 chunks
    uint32_t bfsw = (uint32_t)((tid >> 1) & 3);

    auto loadStage = [&](int stg, int c) {
        if (c < nCh) {
            uint32_t st = sb + stg * STGB;
            int k0 = c << 5;
            size_t abase = (size_t)(row0 + frow) * K + k0;
#pragma unroll
            for (int cc = 0; cc < 2; cc++) {
                int cl = fc0 + cc;
                uint32_t doff = (uint32_t)(frow << 6) + (((uint32_t)cl ^ fsw) << 4);
                cpasync16(st + doff,        Ahi + abase + (cl << 3));
                cpasync16(st + 8192 + doff, Alo + abase + (cl << 3));
            }
            size_t bbase = (size_t)(col0 + tid) * K + k0;
#pragma unroll
            for (int cl = 0; cl < 4; cl++) {
                uint32_t doff = (uint32_t)(tid << 6) + (((uint32_t)cl ^ bfsw) << 4);
                cpasync16(st + 16384 + doff, Bhi + bbase + (cl << 3));
                cpasync16(st + 32768 + doff, Blo + bbase + (cl << 3));
            }
        }
        asm volatile("cp.async.commit_group;" ::: "memory");
    };

    // per-lane ldsm row indices
    int arow[4], brow[4];
    uint32_t asw[4], bsw[4];
#pragma unroll
    for (int mf = 0; mf < 4; mf++) {
        arow[mf] = (wm << 6) + (mf << 4) + (lane & 15);
        asw[mf] = (uint32_t)((arow[mf] >> 1) & 3);
    }
#pragma unroll
    for (int g = 0; g < 4; g++) {
        brow[g] = (wn << 6) + (g << 4) + (lane & 7) + (((lane >> 3) & 1) << 3);
        bsw[g] = (uint32_t)((brow[g] >> 1) & 3);
    }
    int kc = lane >> 4;

    loadStage(0, 0);
    loadStage(1, 1);

    int stg = 0;
    for (int c = 0; c < nCh; ++c) {
        asm volatile("cp.async.wait_group 1;" ::: "memory");
        __syncthreads();
        uint32_t st = sb + stg * STGB;
#pragma unroll
        for (int ks = 0; ks < 2; ks++) {
            int cl = (ks << 1) + kc;
            uint32_t ah[4][4], al[4][4];
#pragma unroll
            for (int mf = 0; mf < 4; mf++) {
                uint32_t ad = st + (uint32_t)(arow[mf] << 6) + (((uint32_t)cl ^ asw[mf]) << 4);
                ldsm4(ah[mf], ad);
                ldsm4(al[mf], ad + 8192);
            }
            uint32_t bh[4][4], bl[4][4];
#pragma unroll
            for (int g = 0; g < 4; g++) {
                uint32_t bd = st + 16384 + (uint32_t)(brow[g] << 6) + (((uint32_t)cl ^ bsw[g]) << 4);
                ldsm4(bh[g], bd);
                ldsm4(bl[g], bd + 16384);
            }
            // 3 sweeps; each acc reused only once per 32 MMAs
#pragma unroll
            for (int mf = 0; mf < 4; mf++)
#pragma unroll
                for (int nf = 0; nf < 8; nf++)
                    mma16816(acc[mf][nf], ah[mf], bh[nf >> 1][nf & 1], bh[nf >> 1][(nf & 1) + 2]);
#pragma unroll
            for (int mf = 0; mf < 4; mf++)
#pragma unroll
                for (int nf = 0; nf < 8; nf++)
                    mma16816(acc[mf][nf], ah[mf], bl[nf >> 1][nf & 1], bl[nf >> 1][(nf & 1) + 2]);
#pragma unroll
            for (int mf = 0; mf < 4; mf++)
#pragma unroll
                for (int nf = 0; nf < 8; nf++)
                    mma16816(acc[mf][nf], al[mf], bh[nf >> 1][nf & 1], bh[nf >> 1][(nf & 1) + 2]);
        }
        loadStage(stg == 0 ? 2 : stg - 1, c + 2);
        stg = (stg == 2) ? 0 : stg + 1;
    }

    // ---- epilogue ----
#pragma unroll
    for (int mf = 0; mf < 4; mf++) {
        int rbase = row0 + (wm << 6) + (mf << 4) + (lane >> 2);
#pragma unroll
        for (int nf = 0; nf < 8; nf++) {
            int cb = col0 + (wn << 6) + (nf << 3) + ((lane & 3) << 1);
            float b0 = bias ? bias[cb] : 0.f;
            float b1 = bias ? bias[cb + 1] : 0.f;
#pragma unroll
            for (int half = 0; half < 2; half++) {
                int r = rbase + (half << 3);
                float v0 = acc[mf][nf][half * 2 + 0] + b0;
                float v1 = acc[mf][nf][half * 2 + 1] + b1;
                size_t gi = (size_t)r * N + cb;
                if (relu) { v0 = fmaxf(v0, 0.f); v1 = fmaxf(v1, 0.f); }
                if (Chi) {
                    __nv_bfloat162 h = __floats2bfloat162_rn(v0, v1);
                    float2 hf = __bfloat1622float2(h);
                    __nv_bfloat162 l = __floats2bfloat162_rn(v0 - hf.x, v1 - hf.y);
                    *(__nv_bfloat162*)(Chi + gi) = h;
                    *(__nv_bfloat162*)(Clo + gi) = l;
                } else {
                    if (resid) { v0 += resid[gi]; v1 += resid[gi + 1]; }
                    *(float2*)(C + gi) = make_float2(v0, v1);
                }
            }
        }
    }
}

// ---------------- flash-style causal attention (fp32 -> bf16 hi/lo out) ------
__global__ __launch_bounds__(256) void attn_kernel(const float* __restrict__ qkv,
                                                   __nv_bfloat16* __restrict__ ohi,
                                                   __nv_bfloat16* __restrict__ olo) {
    __shared__ float sQP[64][64];
    __shared__ float sK[64][64];
    __shared__ float sVt[64][64];
    int tid = threadIdx.x;
    int qt = blockIdx.x;
    int bh = blockIdx.y;
    int bb = bh / H_, hh = bh % H_;
    int r = tid >> 2, quarter = tid & 3;
    int cbase = quarter << 4;
    size_t rowbase = (size_t)(bb * T_ + (qt << 6));
    const float* q = qkv + hh * 64;
    const float* k = qkv + E_ + hh * 64;
    const float* v = qkv + 2 * E_ + hh * 64;

    for (int i = tid; i < 4096; i += 256) {
        int rr = i >> 6, cc = i & 63;
        sQP[rr][cc] = q[(rowbase + rr) * (size_t)NQKV + cc];
    }
    __syncthreads();
    float qreg[64];
#pragma unroll
    for (int i = 0; i < 16; i++) {
        float4 t4 = *(const float4*)&sQP[r][i << 2];
        qreg[i * 4 + 0] = t4.x * 0.125f; qreg[i * 4 + 1] = t4.y * 0.125f;
        qreg[i * 4 + 2] = t4.z * 0.125f; qreg[i * 4 + 3] = t4.w * 0.125f;
    }
    float m = -INFINITY, lsum = 0.f;
    float oacc[16];
#pragma unroll
    for (int j = 0; j < 16; j++) oacc[j] = 0.f;
    int qi = (qt << 6) + r;

    for (int kt = 0; kt <= qt; kt++) {
        __syncthreads();
        size_t kbase = (size_t)(bb * T_ + (kt << 6));
        for (int i = tid; i < 4096; i += 256) {
            int rr = i >> 6, cc = i & 63;
            sK[rr][cc]  = k[(kbase + rr) * (size_t)NQKV + cc];
            sVt[cc][rr] = v[(kbase + rr) * (size_t)NQKV + cc];
        }
        __syncthreads();

        float s[16];
#pragma unroll
        for (int j = 0; j < 16; j++) s[j] = 0.f;
#pragma unroll
        for (int kk = 0; kk < 64; kk += 4) {
#pragma unroll
            for (int j = 0; j < 16; j++) {
                float4 k4 = *(const float4*)&sK[cbase + j][kk];
                s[j] += qreg[kk] * k4.x + qreg[kk + 1] * k4.y +
                        qreg[kk + 2] * k4.z + qreg[kk + 3] * k4.w;
            }
        }
        if (kt == qt) {
#pragma unroll
            for (int j = 0; j < 16; j++)
                if ((kt << 6) + cbase + j > qi) s[j] = -INFINITY;
        }
        float mt = s[0];
#pragma unroll
        for (int j = 1; j < 16; j++) mt = fmaxf(mt, s[j]);
        mt = fmaxf(mt, __shfl_xor_sync(0xffffffffu, mt, 1));
        mt = fmaxf(mt, __shfl_xor_sync(0xffffffffu, mt, 2));
        float mnew = fmaxf(m, mt);
        float alpha = __expf(m - mnew);
        float psum = 0.f;
        float p[16];
#pragma unroll
        for (int j = 0; j < 16; j++) { p[j] = __expf(s[j] - mnew); psum += p[j]; }
        psum += __shfl_xor_sync(0xffffffffu, psum, 1);
        psum += __shfl_xor_sync(0xffffffffu, psum, 2);
        lsum = lsum * alpha + psum;
        m = mnew;
#pragma unroll
        for (int j = 0; j < 16; j++) oacc[j] *= alpha;
#pragma unroll
        for (int j = 0; j < 16; j++) sQP[r][cbase + j] = p[j];
        __syncthreads();
#pragma unroll
        for (int c0 = 0; c0 < 64; c0 += 16) {
            float pc[16];
#pragma unroll
            for (int ii = 0; ii < 4; ii++) {
                float4 p4 = *(const float4*)&sQP[r][c0 + (ii << 2)];
                pc[ii * 4 + 0] = p4.x; pc[ii * 4 + 1] = p4.y;
                pc[ii * 4 + 2] = p4.z; pc[ii * 4 + 3] = p4.w;
            }
#pragma unroll
            for (int j = 0; j < 16; j++) {
                int d = cbase + j;
#pragma unroll
                for (int cc = 0; cc < 16; cc += 4) {
                    float4 v4 = *(const float4*)&sVt[d][c0 + cc];
                    oacc[j] += pc[cc] * v4.x + pc[cc + 1] * v4.y +
                               pc[cc + 2] * v4.z + pc[cc + 3] * v4.w;
                }
            }
        }
    }
    float linv = 1.f / lsum;
    size_t obase = (rowbase + r) * (size_t)E_ + hh * 64 + cbase;
#pragma unroll
    for (int j = 0; j < 16; j += 2) {
        float v0 = oacc[j] * linv, v1 = oacc[j + 1] * linv;
        __nv_bfloat162 h = __floats2bfloat162_rn(v0, v1);
        float2 hf = __bfloat1622float2(h);
        __nv_bfloat162 l = __floats2bfloat162_rn(v0 - hf.x, v1 - hf.y);
        *(__nv_bfloat162*)(ohi + obase + j) = h;
        *(__nv_bfloat162*)(olo + obase + j) = l;
    }
}

// ---------------- loss ------------------------------------------------------
__global__ __launch_bounds__(256) void row_lse_kernel(const float* __restrict__ logits,
                                                      const int* __restrict__ targets,
                                                      float* __restrict__ rowloss) {
    int row = blockIdx.x, tid = threadIdx.x;
    const float* lr = logits + (size_t)row * V_;
    float mx = -INFINITY;
    for (int i = tid; i < V_; i += 256) mx = fmaxf(mx, lr[i]);
#pragma unroll
    for (int o = 16; o > 0; o >>= 1) mx = fmaxf(mx, __shfl_xor_sync(0xffffffffu, mx, o));
    __shared__ float sm[8];
    if ((tid & 31) == 0) sm[tid >> 5] = mx;
    __syncthreads();
    float m2 = -INFINITY;
#pragma unroll
    for (int i = 0; i < 8; i++) m2 = fmaxf(m2, sm[i]);
    float se = 0.f;
    for (int i = tid; i < V_; i += 256) se += __expf(lr[i] - m2);
#pragma unroll
    for (int o = 16; o > 0; o >>= 1) se += __shfl_xor_sync(0xffffffffu, se, o);
    __shared__ float ssum[8];
    if ((tid & 31) == 0) ssum[tid >> 5] = se;
    __syncthreads();
    if (tid == 0) {
        float tot = 0.f;
#pragma unroll
        for (int i = 0; i < 8; i++) tot += ssum[i];
        rowloss[row] = (logf(tot) + m2) - lr[targets[row]];
    }
}

__global__ __launch_bounds__(256) void loss_reduce_kernel(const float* __restrict__ rowloss,
                                                          float* __restrict__ out) {
    int tid = threadIdx.x;
    float s = 0.f;
    for (int i = tid; i < BT; i += 256) s += rowloss[i];
#pragma unroll
    for (int o = 16; o > 0; o >>= 1) s += __shfl_xor_sync(0xffffffffu, s, o);
    __shared__ float sm[8];
    if ((tid & 31) == 0) sm[tid >> 5] = s;
    __syncthreads();
    if (tid == 0) {
        float t = 0.f;
#pragma unroll
        for (int i = 0; i < 8; i++) t += sm[i];
        out[0] = t * (1.f / BT);
    }
}

// ---------------- launch ----------------------------------------------------
extern "C" void kernel_launch(void* const* d_in, const int* in_sizes, int n_in,
                              void* d_out, int out_size) {
    const int*   idx     = (const int*)d_in[0];
    const int*   targets = (const int*)d_in[1];
    const float* tok_emb = (const float*)d_in[2];
    const float* pos_emb = (const float*)d_in[3];
    const float* Wq  = (const float*)d_in[4];
    const float* bq  = (const float*)d_in[5];
    const float* Wk  = (const float*)d_in[6];
    const float* bk  = (const float*)d_in[7];
    const float* Wv  = (const float*)d_in[8];
    const float* bv  = (const float*)d_in[9];
    const float* Wo  = (const float*)d_in[10];
    const float* bo  = (const float*)d_in[11];
    const float* ln1g = (const float*)d_in[12];
    const float* ln1b = (const float*)d_in[13];
    const float* W1  = (const float*)d_in[14];
    const float* b1  = (const float*)d_in[15];
    const float* W2  = (const float*)d_in[16];
    const float* b2  = (const float*)d_in[17];
    const float* ln2g = (const float*)d_in[18];
    const float* ln2b = (const float*)d_in[19];
    const float* lnfg = (const float*)d_in[20];
    const float* lnfb = (const float*)d_in[21];
    const float* Wlm = (const float*)d_in[22];
    const float* blm = (const float*)d_in[23];
    float* out = (float*)d_out;

    float *px, *pqkv, *pbqkv, *prl, *plg;
    __nv_bfloat16 *phhi, *phlo, *pohi, *polo, *pffhi, *pfflo, *pwthi, *pwtlo;
    cudaGetSymbolAddress((void**)&px,    g_x);
    cudaGetSymbolAddress((void**)&pqkv,  g_qkv);
    cudaGetSymbolAddress((void**)&phhi,  g_hhi);
    cudaGetSymbolAddress((void**)&phlo,  g_hlo);
    cudaGetSymbolAddress((void**)&pohi,  g_ohi);
    cudaGetSymbolAddress((void**)&polo,  g_olo);
    cudaGetSymbolAddress((void**)&pffhi, g_ffhi);
    cudaGetSymbolAddress((void**)&pfflo, g_fflo);
    cudaGetSymbolAddress((void**)&pbqkv, g_bqkv);
    cudaGetSymbolAddress((void**)&pwthi, g_wthi);
    cudaGetSymbolAddress((void**)&pwtlo, g_wtlo);
    cudaGetSymbolAddress((void**)&prl,   g_rowloss);
    cudaGetSymbolAddress((void**)&plg,   g_logits_scratch);

    cudaFuncSetAttribute(gemm_tc_kernel, cudaFuncAttributeMaxDynamicSharedMemorySize, GEMM_SMEM);

    const long long NLOG = (long long)BT * V_;
    float* logits = (out_size >= NLOG) ? out : plg;

    dim3 cb(32, 8);
    dim3 gQKVw(E_ / 32, NQKV / 32);
    dim3 gQKV(NQKV / 256, BT / 128);
    dim3 gE(E_ / 256, BT / 128);
    dim3 gF(FF / 256, BT / 128);
    dim3 gV(V_ / 256, BT / 128);
    dim3 gAttn(T_ / 64, B_ * H_);

    // --- ordered so launch index 5 is a gemm_tc (ncu -s 5 -c 1 lands on it) ---
    embed_kernel<<<(BT * E_) / 256, 256>>>(idx, tok_emb, pos_emb, px);               // 0
    ln_kernel<<<BT, 256>>>(px, ln1g, ln1b, phhi, phlo);                              // 1
    biascat_kernel<<<(L_ * NQKV + 255) / 256, 256>>>(bq, bk, bv, pbqkv);             // 2
    wconv_qkv_kernel<<<gQKVw, cb>>>(Wq, Wk, Wv, pwthi + OFF_QKV(0), pwtlo + OFF_QKV(0), 0); // 3
    wconvt_kernel<<<dim3(E_ / 32, E_ / 32), cb>>>(Wo, pwthi + OFF_O(0), pwtlo + OFF_O(0), E_, E_); // 4
    gemm_tc_kernel<<<gQKV, 256, GEMM_SMEM>>>(phhi, phlo,                             // 5 (profiled)
        pwthi + OFF_QKV(0), pwtlo + OFF_QKV(0), pbqkv, nullptr,
        pqkv, nullptr, nullptr, NQKV, E_, 0);

    // --- remaining weight prep ---
    wconvt_kernel<<<dim3(FF / 32, E_ / 32), cb>>>(W1, pwthi + OFF_W1(0), pwtlo + OFF_W1(0), E_, FF);
    wconvt_kernel<<<dim3(E_ / 32, FF / 32), cb>>>(W2, pwthi + OFF_W2(0), pwtlo + OFF_W2(0), FF, E_);
    for (int l = 1; l < L_; l++) {
        size_t wel = (size_t)l * E_ * E_;
        wconv_qkv_kernel<<<gQKVw, cb>>>(Wq, Wk, Wv, pwthi + OFF_QKV(l), pwtlo + OFF_QKV(l), l);
        wconvt_kernel<<<dim3(E_ / 32, E_ / 32), cb>>>(Wo + wel, pwthi + OFF_O(l), pwtlo + OFF_O(l), E_, E_);
        wconvt_kernel<<<dim3(FF / 32, E_ / 32), cb>>>(W1 + (size_t)l * E_ * FF, pwthi + OFF_W1(l), pwtlo + OFF_W1(l), E_, FF);
        wconvt_kernel<<<dim3(E_ / 32, FF / 32), cb>>>(W2 + (size_t)l * FF * E_, pwthi + OFF_W2(l), pwtlo + OFF_W2(l), FF, E_);
    }
    wconvt_kernel<<<dim3(V_ / 32, E_ / 32), cb>>>(Wlm, pwthi + OFF_LM, pwtlo + OFF_LM, E_, V_);

    // --- forward ---
    for (int l = 0; l < L_; l++) {
        if (l > 0) {
            ln_kernel<<<BT, 256>>>(px, ln1g + l * E_, ln1b + l * E_, phhi, phlo);
            gemm_tc_kernel<<<gQKV, 256, GEMM_SMEM>>>(phhi, phlo,
                pwthi + OFF_QKV(l), pwtlo + OFF_QKV(l), pbqkv + l * NQKV, nullptr,
                pqkv, nullptr, nullptr, NQKV, E_, 0);
        }
        attn_kernel<<<gAttn, 256>>>(pqkv, pohi, polo);
        gemm_tc_kernel<<<gE, 256, GEMM_SMEM>>>(pohi, polo,
            pwthi + OFF_O(l), pwtlo + OFF_O(l), bo + l * E_, px,
            px, nullptr, nullptr, E_, E_, 0);
        ln_kernel<<<BT, 256>>>(px, ln2g + l * E_, ln2b + l * E_, phhi, phlo);
        gemm_tc_kernel<<<gF, 256, GEMM_SMEM>>>(phhi, phlo,
            pwthi + OFF_W1(l), pwtlo + OFF_W1(l), b1 + l * FF, nullptr,
            nullptr, pffhi, pfflo, FF, E_, 1);
        gemm_tc_kernel<<<gE, 256, GEMM_SMEM>>>(pffhi, pfflo,
            pwthi + OFF_W2(l), pwtlo + OFF_W2(l), b2 + l * E_, px,
            px, nullptr, nullptr, E_, FF, 0);
    }
    ln_kernel<<<BT, 256>>>(px, lnfg, lnfb, phhi, phlo);
    gemm_tc_kernel<<<gV, 256, GEMM_SMEM>>>(phhi, phlo,
        pwthi + OFF_LM, pwtlo + OFF_LM, blm, nullptr,
        logits, nullptr, nullptr, V_, E_, 0);

    // --- loss ---
    float* loss_dst = nullptr;
    if (out_size == 1)        loss_dst = out;
    else if (out_size > NLOG) loss_dst = out + NLOG;
    if (loss_dst) {
        row_lse_kernel<<<BT, 256>>>(logits, targets, prl);
        loss_reduce_kernel<<<1, 256>>>(prl, loss_dst);
    }
}

// round 6
// speedup vs baseline: 1.1840x; 1.1840x over previous
#include <cuda_runtime.h>
#include <cuda_bf16.h>
#include <math.h>
#include <stdint.h>

#define L_  4
#define H_  12
#define E_  768
#define HS_ 64
#define V_  32000
#define B_  2
#define T_  1024
#define BT  2048
#define FF  3072
#define NQKV 2304

// ---- weight scratch offsets (elements) ----
#define WPL 7077888ull
#define OFF_QKV(l) ((size_t)(l) * WPL)
#define OFF_O(l)   (OFF_QKV(l) + 1769472ull)
#define OFF_W1(l)  (OFF_QKV(l) + 2359296ull)
#define OFF_W2(l)  (OFF_QKV(l) + 4718592ull)
#define OFF_LM     ((size_t)4 * WPL)
#define WTOT       (OFF_LM + 24576000ull)

// ---------------- scratch (static device globals) ----------------------------
__device__ float g_x[BT * E_];
__device__ float g_qkv[BT * NQKV];
__device__ __nv_bfloat16 g_hhi[BT * E_];
__device__ __nv_bfloat16 g_hlo[BT * E_];
__device__ __nv_bfloat16 g_ohi[BT * E_];
__device__ __nv_bfloat16 g_olo[BT * E_];
__device__ __nv_bfloat16 g_ffhi[BT * FF];
__device__ __nv_bfloat16 g_fflo[BT * FF];
__device__ float g_bqkv[L_ * NQKV];
__device__ float g_part[2ull * BT * FF];     // split-K partials (max: W1 split2 N=3072)
__device__ __nv_bfloat16 g_wthi[WTOT];
__device__ __nv_bfloat16 g_wtlo[WTOT];
__device__ float g_rowloss[BT];
__device__ float g_logits_scratch[(size_t)BT * V_];

// ---------------- PTX helpers (all non-'a' features) -------------------------
__device__ __forceinline__ uint32_t smem_u32(const void* p) {
    uint32_t a;
    asm("{ .reg .u64 t; cvta.to.shared.u64 t, %1; cvt.u32.u64 %0, t; }" : "=r"(a) : "l"(p));
    return a;
}
__device__ __forceinline__ void mma16816(float* c, const uint32_t* a, uint32_t b0, uint32_t b1) {
    asm volatile(
        "mma.sync.aligned.m16n8k16.row.col.f32.bf16.bf16.f32 "
        "{%0,%1,%2,%3}, {%4,%5,%6,%7}, {%8,%9}, {%0,%1,%2,%3};"
        : "+f"(c[0]), "+f"(c[1]), "+f"(c[2]), "+f"(c[3])
        : "r"(a[0]), "r"(a[1]), "r"(a[2]), "r"(a[3]), "r"(b0), "r"(b1));
}
__device__ __forceinline__ void ldsm4(uint32_t* r, uint32_t addr) {
    asm volatile("ldmatrix.sync.aligned.m8n8.x4.shared.b16 {%0,%1,%2,%3}, [%4];"
                 : "=r"(r[0]), "=r"(r[1]), "=r"(r[2]), "=r"(r[3]) : "r"(addr));
}
__device__ __forceinline__ void cpasync16(uint32_t dst, const void* src) {
    asm volatile("cp.async.cg.shared.global [%0], [%1], 16;" :: "r"(dst), "l"(src));
}

// ---------------- fused QKV weight repack+transpose+split + bias concat ------
__global__ __launch_bounds__(256) void wconv_qkv_kernel(const float* __restrict__ Wq,
                                                        const float* __restrict__ Wk,
                                                        const float* __restrict__ Wv,
                                                        const float* __restrict__ bq,
                                                        const float* __restrict__ bk,
                                                        const float* __restrict__ bv,
                                                        __nv_bfloat16* __restrict__ Whi,
                                                        __nv_bfloat16* __restrict__ Wlo,
                                                        float* __restrict__ bqkv,
                                                        int l) {
    __shared__ float s[32][33];
    int n0 = blockIdx.y * 32, e0 = blockIdx.x * 32;
    int tx = threadIdx.x, ty = threadIdx.y;
    int sel = n0 / E_;
    int nn = n0 % E_;
    int h = nn >> 6, hs0 = nn & 63;
    const float* src = sel == 0 ? Wq : (sel == 1 ? Wk : Wv);
    const float* base = src + ((size_t)(l * H_ + h) * E_) * 64;
#pragma unroll
    for (int i = 0; i < 4; i++) {
        int e = ty + 8 * i;
        s[e][tx] = base[(size_t)(e0 + e) * 64 + hs0 + tx];
    }
    __syncthreads();
#pragma unroll
    for (int i = 0; i < 4; i++) {
        int nl = ty + 8 * i;
        float x = s[tx][nl];
        __nv_bfloat16 hh = __float2bfloat16(x);
        __nv_bfloat16 ll = __float2bfloat16(x - __bfloat162float(hh));
        size_t oi = (size_t)(n0 + nl) * E_ + e0 + tx;
        Whi[oi] = hh;
        Wlo[oi] = ll;
    }
    // fused bias concat (first NQKV global threads)
    int gid = (blockIdx.y * gridDim.x + blockIdx.x) * 256 + ty * 32 + tx;
    if (gid < NQKV) {
        float v;
        if (gid < E_)            v = bq[l * E_ + gid];
        else if (gid < 2 * E_)   v = bk[l * E_ + gid - E_];
        else                     v = bv[l * E_ + gid - 2 * E_];
        bqkv[l * NQKV + gid] = v;
    }
}

// ---------------- weight transpose + bf16 hi/lo split ------------------------
__global__ __launch_bounds__(256) void wconvt_kernel(const float* __restrict__ W,
                                                     __nv_bfloat16* __restrict__ Whi,
                                                     __nv_bfloat16* __restrict__ Wlo,
                                                     int K, int N) {
    __shared__ float s[32][33];
    int k0 = blockIdx.y * 32, n0 = blockIdx.x * 32;
    int tx = threadIdx.x, ty = threadIdx.y;
#pragma unroll
    for (int i = 0; i < 4; i++)
        s[ty + 8 * i][tx] = W[(size_t)(k0 + ty + 8 * i) * N + n0 + tx];
    __syncthreads();
#pragma unroll
    for (int i = 0; i < 4; i++) {
        int n = ty + 8 * i;
        float x = s[tx][n];
        __nv_bfloat16 h = __float2bfloat16(x);
        __nv_bfloat16 l = __float2bfloat16(x - __bfloat162float(h));
        size_t oi = (size_t)(n0 + n) * K + k0 + tx;
        Whi[oi] = h;
        Wlo[oi] = l;
    }
}

// ---------------- embedding -------------------------------------------------
__global__ __launch_bounds__(256) void embed_kernel(const int* __restrict__ idx,
                                                    const float* __restrict__ tok,
                                                    const float* __restrict__ pos,
                                                    float* __restrict__ x) {
    int i = blockIdx.x * 256 + threadIdx.x;
    int e = i % E_;
    int t = i / E_;
    int token = idx[t];
    x[i] = tok[(size_t)token * E_ + e] + pos[(t % T_) * E_ + e];
}

// ---------------- layernorm -> bf16 hi/lo ------------------------------------
__global__ __launch_bounds__(256) void ln_kernel(const float* __restrict__ x,
                                                 const float* __restrict__ g,
                                                 const float* __restrict__ b,
                                                 __nv_bfloat16* __restrict__ hi,
                                                 __nv_bfloat16* __restrict__ lo) {
    int row = blockIdx.x;
    int tid = threadIdx.x;
    const float* xr = x + (size_t)row * E_;
    float v[3], s = 0.f, sq = 0.f;
#pragma unroll
    for (int i = 0; i < 3; i++) {
        v[i] = xr[tid + i * 256];
        s += v[i];
        sq += v[i] * v[i];
    }
#pragma unroll
    for (int o = 16; o > 0; o >>= 1) {
        s  += __shfl_xor_sync(0xffffffffu, s, o);
        sq += __shfl_xor_sync(0xffffffffu, sq, o);
    }
    __shared__ float ss[8], ssq[8];
    if ((tid & 31) == 0) { ss[tid >> 5] = s; ssq[tid >> 5] = sq; }
    __syncthreads();
    s = 0.f; sq = 0.f;
#pragma unroll
    for (int i = 0; i < 8; i++) { s += ss[i]; sq += ssq[i]; }
    float mean = s * (1.f / E_);
    float var  = sq * (1.f / E_) - mean * mean;
    float rstd = rsqrtf(var + 1e-5f);
    size_t rb = (size_t)row * E_;
#pragma unroll
    for (int i = 0; i < 3; i++) {
        int e = tid + i * 256;
        float y = (v[i] - mean) * rstd * g[e] + b[e];
        __nv_bfloat16 h = __float2bfloat16(y);
        hi[rb + e] = h;
        lo[rb + e] = __float2bfloat16(y - __bfloat162float(h));
    }
}

// ---------------- tensor-core GEMM (bf16 hi/lo, all-cp.async, 3 stages) ------
// C[M,N] (or K-split partial planes) = A @ Wt^T.
// 128x128 CTA, BK=32, 256 thr (8 warps 2x4), warp tile 64x32. 3 stages.
// Stage (32KB): Ahi@0, Alo@8192, Bhi@16384, Blo@24576.
// 64B rows, 16B-chunk swizzle: phys = chunk ^ ((row>>1)&3).
#define STG3 32768
#define GEMM_SMEM (3 * STG3)
__global__ __launch_bounds__(256, 2)
void gemm_tc_kernel(const __nv_bfloat16* __restrict__ Ahi,
                    const __nv_bfloat16* __restrict__ Alo,
                    const __nv_bfloat16* __restrict__ Bhi,
                    const __nv_bfloat16* __restrict__ Blo,
                    const float* __restrict__ bias,
                    const float* __restrict__ resid,
                    float* __restrict__ C,
                    __nv_bfloat16* __restrict__ Chi,
                    __nv_bfloat16* __restrict__ Clo,
                    float* __restrict__ Cpart,
                    int N, int K, int kslen, int relu) {
    extern __shared__ __align__(16) char smem[];
    int tid = threadIdx.x, lane = tid & 31, wid = tid >> 5;
    int wm = wid >> 2, wn = wid & 3;
    int row0 = blockIdx.y << 7, col0 = blockIdx.x << 7;
    int k0base = blockIdx.z * kslen;
    uint32_t sb = smem_u32(smem);

    float acc[4][4][4] = {};

    const int nCh = kslen >> 5;
    int frow = tid >> 1;
    int fc0 = (tid & 1) << 1;
    uint32_t fsw = (uint32_t)((frow >> 1) & 3);

    auto loadStage = [&](int stg, int c) {
        if (c < nCh) {
            uint32_t st = sb + stg * STG3;
            int k0 = k0base + (c << 5);
            size_t abase = (size_t)(row0 + frow) * K + k0;
            size_t bbase = (size_t)(col0 + frow) * K + k0;
#pragma unroll
            for (int cc = 0; cc < 2; cc++) {
                int cl = fc0 + cc;
                uint32_t doff = (uint32_t)(frow << 6) + (((uint32_t)cl ^ fsw) << 4);
                cpasync16(st + doff,         Ahi + abase + (cl << 3));
                cpasync16(st + 8192 + doff,  Alo + abase + (cl << 3));
                cpasync16(st + 16384 + doff, Bhi + bbase + (cl << 3));
                cpasync16(st + 24576 + doff, Blo + bbase + (cl << 3));
            }
        }
        asm volatile("cp.async.commit_group;" ::: "memory");
    };

    int arow[4], brow[2];
    uint32_t asw[4], bsw[2];
#pragma unroll
    for (int mf = 0; mf < 4; mf++) {
        arow[mf] = (wm << 6) + (mf << 4) + (lane & 15);
        asw[mf] = (uint32_t)((arow[mf] >> 1) & 3);
    }
#pragma unroll
    for (int g = 0; g < 2; g++) {
        brow[g] = (wn << 5) + (g << 4) + (lane & 7) + (((lane >> 3) & 1) << 3);
        bsw[g] = (uint32_t)((brow[g] >> 1) & 3);
    }
    int kc = lane >> 4;

    loadStage(0, 0);
    loadStage(1, 1);

    int stg = 0;
    for (int c = 0; c < nCh; ++c) {
        asm volatile("cp.async.wait_group 1;" ::: "memory");
        __syncthreads();
        uint32_t st = sb + stg * STG3;
#pragma unroll
        for (int ks = 0; ks < 2; ks++) {
            int cl = (ks << 1) + kc;
            uint32_t ah[4][4], al[4][4];
#pragma unroll
            for (int mf = 0; mf < 4; mf++) {
                uint32_t ad = st + (uint32_t)(arow[mf] << 6) + (((uint32_t)cl ^ asw[mf]) << 4);
                ldsm4(ah[mf], ad);
                ldsm4(al[mf], ad + 8192);
            }
            uint32_t bh[2][4], bl[2][4];
#pragma unroll
            for (int g = 0; g < 2; g++) {
                uint32_t bd = st + 16384 + (uint32_t)(brow[g] << 6) + (((uint32_t)cl ^ bsw[g]) << 4);
                ldsm4(bh[g], bd);
                ldsm4(bl[g], bd + 8192);
            }
#pragma unroll
            for (int mf = 0; mf < 4; mf++)
#pragma unroll
                for (int nf = 0; nf < 4; nf++)
                    mma16816(acc[mf][nf], ah[mf], bh[nf >> 1][nf & 1], bh[nf >> 1][(nf & 1) + 2]);
#pragma unroll
            for (int mf = 0; mf < 4; mf++)
#pragma unroll
                for (int nf = 0; nf < 4; nf++)
                    mma16816(acc[mf][nf], ah[mf], bl[nf >> 1][nf & 1], bl[nf >> 1][(nf & 1) + 2]);
#pragma unroll
            for (int mf = 0; mf < 4; mf++)
#pragma unroll
                for (int nf = 0; nf < 4; nf++)
                    mma16816(acc[mf][nf], al[mf], bh[nf >> 1][nf & 1], bh[nf >> 1][(nf & 1) + 2]);
        }
        loadStage(stg == 0 ? 2 : stg - 1, c + 2);
        stg = (stg == 2) ? 0 : stg + 1;
    }

    // ---- epilogue ----
    if (Cpart) {
        size_t plane = (size_t)blockIdx.z * (((size_t)gridDim.y << 7) * (size_t)N);
#pragma unroll
        for (int mf = 0; mf < 4; mf++) {
            int rbase = row0 + (wm << 6) + (mf << 4) + (lane >> 2);
#pragma unroll
            for (int nf = 0; nf < 4; nf++) {
                int cb = col0 + (wn << 5) + (nf << 3) + ((lane & 3) << 1);
#pragma unroll
                for (int half = 0; half < 2; half++) {
                    int r = rbase + (half << 3);
                    *(float2*)(Cpart + plane + (size_t)r * N + cb) =
                        make_float2(acc[mf][nf][half * 2], acc[mf][nf][half * 2 + 1]);
                }
            }
        }
        return;
    }
#pragma unroll
    for (int mf = 0; mf < 4; mf++) {
        int rbase = row0 + (wm << 6) + (mf << 4) + (lane >> 2);
#pragma unroll
        for (int nf = 0; nf < 4; nf++) {
            int cb = col0 + (wn << 5) + (nf << 3) + ((lane & 3) << 1);
            float b0 = bias ? bias[cb] : 0.f;
            float b1 = bias ? bias[cb + 1] : 0.f;
#pragma unroll
            for (int half = 0; half < 2; half++) {
                int r = rbase + (half << 3);
                float v0 = acc[mf][nf][half * 2 + 0] + b0;
                float v1 = acc[mf][nf][half * 2 + 1] + b1;
                size_t gi = (size_t)r * N + cb;
                if (relu) { v0 = fmaxf(v0, 0.f); v1 = fmaxf(v1, 0.f); }
                if (Chi) {
                    __nv_bfloat162 h = __floats2bfloat162_rn(v0, v1);
                    float2 hf = __bfloat1622float2(h);
                    __nv_bfloat162 l = __floats2bfloat162_rn(v0 - hf.x, v1 - hf.y);
                    *(__nv_bfloat162*)(Chi + gi) = h;
                    *(__nv_bfloat162*)(Clo + gi) = l;
                } else {
                    if (resid) { v0 += resid[gi]; v1 += resid[gi + 1]; }
                    *(float2*)(C + gi) = make_float2(v0, v1);
                }
            }
        }
    }
}

// ---------------- split-K reduce (deterministic fixed order) -----------------
// out = [resid +] [relu(] sum_s part[s] + bias [)] ; optional hi/lo bf16 out
__global__ __launch_bounds__(256) void reduce_kernel(const float* __restrict__ parts,
                                                     int nsplit,
                                                     const float* __restrict__ bias,
                                                     const float* __restrict__ resid,
                                                     float* __restrict__ outF,
                                                     __nv_bfloat16* __restrict__ outHi,
                                                     __nv_bfloat16* __restrict__ outLo,
                                                     int relu, int N) {
    size_t i = ((size_t)blockIdx.x * 256 + threadIdx.x) * 4;
    size_t plane = (size_t)BT * N;
    int col = (int)(i % N);
    float4 s = *(const float4*)(parts + i);
    for (int p = 1; p < nsplit; p++) {
        float4 t = *(const float4*)(parts + plane * p + i);
        s.x += t.x; s.y += t.y; s.z += t.z; s.w += t.w;
    }
    float4 b = *(const float4*)(bias + col);
    s.x += b.x; s.y += b.y; s.z += b.z; s.w += b.w;
    if (relu) {
        s.x = fmaxf(s.x, 0.f); s.y = fmaxf(s.y, 0.f);
        s.z = fmaxf(s.z, 0.f); s.w = fmaxf(s.w, 0.f);
    }
    if (outHi) {
        __nv_bfloat162 h0 = __floats2bfloat162_rn(s.x, s.y);
        __nv_bfloat162 h1 = __floats2bfloat162_rn(s.z, s.w);
        float2 f0 = __bfloat1622float2(h0), f1 = __bfloat1622float2(h1);
        __nv_bfloat162 l0 = __floats2bfloat162_rn(s.x - f0.x, s.y - f0.y);
        __nv_bfloat162 l1 = __floats2bfloat162_rn(s.z - f1.x, s.w - f1.y);
        *(__nv_bfloat162*)(outHi + i) = h0;
        *(__nv_bfloat162*)(outHi + i + 2) = h1;
        *(__nv_bfloat162*)(outLo + i) = l0;
        *(__nv_bfloat162*)(outLo + i + 2) = l1;
    } else {
        if (resid) {
            float4 r = *(const float4*)(resid + i);
            s.x += r.x; s.y += r.y; s.z += r.z; s.w += r.w;
        }
        *(float4*)(outF + i) = s;
    }
}

// ---------------- flash-style causal attention (fp32 -> bf16 hi/lo out) ------
__global__ __launch_bounds__(256) void attn_kernel(const float* __restrict__ qkv,
                                                   __nv_bfloat16* __restrict__ ohi,
                                                   __nv_bfloat16* __restrict__ olo) {
    __shared__ float sQP[64][64];
    __shared__ float sK[64][64];
    __shared__ float sVt[64][64];
    int tid = threadIdx.x;
    int qt = blockIdx.x;
    int bh = blockIdx.y;
    int bb = bh / H_, hh = bh % H_;
    int r = tid >> 2, quarter = tid & 3;
    int cbase = quarter << 4;
    size_t rowbase = (size_t)(bb * T_ + (qt << 6));
    const float* q = qkv + hh * 64;
    const float* k = qkv + E_ + hh * 64;
    const float* v = qkv + 2 * E_ + hh * 64;

    for (int i = tid; i < 4096; i += 256) {
        int rr = i >> 6, cc = i & 63;
        sQP[rr][cc] = q[(rowbase + rr) * (size_t)NQKV + cc];
    }
    __syncthreads();
    float qreg[64];
#pragma unroll
    for (int i = 0; i < 16; i++) {
        float4 t4 = *(const float4*)&sQP[r][i << 2];
        qreg[i * 4 + 0] = t4.x * 0.125f; qreg[i * 4 + 1] = t4.y * 0.125f;
        qreg[i * 4 + 2] = t4.z * 0.125f; qreg[i * 4 + 3] = t4.w * 0.125f;
    }
    float m = -INFINITY, lsum = 0.f;
    float oacc[16];
#pragma unroll
    for (int j = 0; j < 16; j++) oacc[j] = 0.f;
    int qi = (qt << 6) + r;

    for (int kt = 0; kt <= qt; kt++) {
        __syncthreads();
        size_t kbase = (size_t)(bb * T_ + (kt << 6));
        for (int i = tid; i < 4096; i += 256) {
            int rr = i >> 6, cc = i & 63;
            sK[rr][cc]  = k[(kbase + rr) * (size_t)NQKV + cc];
            sVt[cc][rr] = v[(kbase + rr) * (size_t)NQKV + cc];
        }
        __syncthreads();

        float s[16];
#pragma unroll
        for (int j = 0; j < 16; j++) s[j] = 0.f;
#pragma unroll
        for (int kk = 0; kk < 64; kk += 4) {
#pragma unroll
            for (int j = 0; j < 16; j++) {
                float4 k4 = *(const float4*)&sK[cbase + j][kk];
                s[j] += qreg[kk] * k4.x + qreg[kk + 1] * k4.y +
                        qreg[kk + 2] * k4.z + qreg[kk + 3] * k4.w;
            }
        }
        if (kt == qt) {
#pragma unroll
            for (int j = 0; j < 16; j++)
                if ((kt << 6) + cbase + j > qi) s[j] = -INFINITY;
        }
        float mt = s[0];
#pragma unroll
        for (int j = 1; j < 16; j++) mt = fmaxf(mt, s[j]);
        mt = fmaxf(mt, __shfl_xor_sync(0xffffffffu, mt, 1));
        mt = fmaxf(mt, __shfl_xor_sync(0xffffffffu, mt, 2));
        float mnew = fmaxf(m, mt);
        float alpha = __expf(m - mnew);
        float psum = 0.f;
        float p[16];
#pragma unroll
        for (int j = 0; j < 16; j++) { p[j] = __expf(s[j] - mnew); psum += p[j]; }
        psum += __shfl_xor_sync(0xffffffffu, psum, 1);
        psum += __shfl_xor_sync(0xffffffffu, psum, 2);
        lsum = lsum * alpha + psum;
        m = mnew;
#pragma unroll
        for (int j = 0; j < 16; j++) oacc[j] *= alpha;
#pragma unroll
        for (int j = 0; j < 16; j++) sQP[r][cbase + j] = p[j];
        __syncthreads();
#pragma unroll
        for (int c0 = 0; c0 < 64; c0 += 16) {
            float pc[16];
#pragma unroll
            for (int ii = 0; ii < 4; ii++) {
                float4 p4 = *(const float4*)&sQP[r][c0 + (ii << 2)];
                pc[ii * 4 + 0] = p4.x; pc[ii * 4 + 1] = p4.y;
                pc[ii * 4 + 2] = p4.z; pc[ii * 4 + 3] = p4.w;
            }
#pragma unroll
            for (int j = 0; j < 16; j++) {
                int d = cbase + j;
#pragma unroll
                for (int cc = 0; cc < 16; cc += 4) {
                    float4 v4 = *(const float4*)&sVt[d][c0 + cc];
                    oacc[j] += pc[cc] * v4.x + pc[cc + 1] * v4.y +
                               pc[cc + 2] * v4.z + pc[cc + 3] * v4.w;
                }
            }
        }
    }
    float linv = 1.f / lsum;
    size_t obase = (rowbase + r) * (size_t)E_ + hh * 64 + cbase;
#pragma unroll
    for (int j = 0; j < 16; j += 2) {
        float v0 = oacc[j] * linv, v1 = oacc[j + 1] * linv;
        __nv_bfloat162 h = __floats2bfloat162_rn(v0, v1);
        float2 hf = __bfloat1622float2(h);
        __nv_bfloat162 l = __floats2bfloat162_rn(v0 - hf.x, v1 - hf.y);
        *(__nv_bfloat162*)(ohi + obase + j) = h;
        *(__nv_bfloat162*)(olo + obase + j) = l;
    }
}

// ---------------- loss ------------------------------------------------------
__global__ __launch_bounds__(256) void row_lse_kernel(const float* __restrict__ logits,
                                                      const int* __restrict__ targets,
                                                      float* __restrict__ rowloss) {
    int row = blockIdx.x, tid = threadIdx.x;
    const float* lr = logits + (size_t)row * V_;
    float mx = -INFINITY;
    for (int i = tid; i < V_; i += 256) mx = fmaxf(mx, lr[i]);
#pragma unroll
    for (int o = 16; o > 0; o >>= 1) mx = fmaxf(mx, __shfl_xor_sync(0xffffffffu, mx, o));
    __shared__ float sm[8];
    if ((tid & 31) == 0) sm[tid >> 5] = mx;
    __syncthreads();
    float m2 = -INFINITY;
#pragma unroll
    for (int i = 0; i < 8; i++) m2 = fmaxf(m2, sm[i]);
    float se = 0.f;
    for (int i = tid; i < V_; i += 256) se += __expf(lr[i] - m2);
#pragma unroll
    for (int o = 16; o > 0; o >>= 1) se += __shfl_xor_sync(0xffffffffu, se, o);
    __shared__ float ssum[8];
    if ((tid & 31) == 0) ssum[tid >> 5] = se;
    __syncthreads();
    if (tid == 0) {
        float tot = 0.f;
#pragma unroll
        for (int i = 0; i < 8; i++) tot += ssum[i];
        rowloss[row] = (logf(tot) + m2) - lr[targets[row]];
    }
}

__global__ __launch_bounds__(256) void loss_reduce_kernel(const float* __restrict__ rowloss,
                                                          float* __restrict__ out) {
    int tid = threadIdx.x;
    float s = 0.f;
    for (int i = tid; i < BT; i += 256) s += rowloss[i];
#pragma unroll
    for (int o = 16; o > 0; o >>= 1) s += __shfl_xor_sync(0xffffffffu, s, o);
    __shared__ float sm[8];
    if ((tid & 31) == 0) sm[tid >> 5] = s;
    __syncthreads();
    if (tid == 0) {
        float t = 0.f;
#pragma unroll
        for (int i = 0; i < 8; i++) t += sm[i];
        out[0] = t * (1.f / BT);
    }
}

// ---------------- launch ----------------------------------------------------
extern "C" void kernel_launch(void* const* d_in, const int* in_sizes, int n_in,
                              void* d_out, int out_size) {
    const int*   idx     = (const int*)d_in[0];
    const int*   targets = (const int*)d_in[1];
    const float* tok_emb = (const float*)d_in[2];
    const float* pos_emb = (const float*)d_in[3];
    const float* Wq  = (const float*)d_in[4];
    const float* bq  = (const float*)d_in[5];
    const float* Wk  = (const float*)d_in[6];
    const float* bk  = (const float*)d_in[7];
    const float* Wv  = (const float*)d_in[8];
    const float* bv  = (const float*)d_in[9];
    const float* Wo  = (const float*)d_in[10];
    const float* bo  = (const float*)d_in[11];
    const float* ln1g = (const float*)d_in[12];
    const float* ln1b = (const float*)d_in[13];
    const float* W1  = (const float*)d_in[14];
    const float* b1  = (const float*)d_in[15];
    const float* W2  = (const float*)d_in[16];
    const float* b2  = (const float*)d_in[17];
    const float* ln2g = (const float*)d_in[18];
    const float* ln2b = (const float*)d_in[19];
    const float* lnfg = (const float*)d_in[20];
    const float* lnfb = (const float*)d_in[21];
    const float* Wlm = (const float*)d_in[22];
    const float* blm = (const float*)d_in[23];
    float* out = (float*)d_out;

    float *px, *pqkv, *pbqkv, *ppart, *prl, *plg;
    __nv_bfloat16 *phhi, *phlo, *pohi, *polo, *pffhi, *pfflo, *pwthi, *pwtlo;
    cudaGetSymbolAddress((void**)&px,    g_x);
    cudaGetSymbolAddress((void**)&pqkv,  g_qkv);
    cudaGetSymbolAddress((void**)&phhi,  g_hhi);
    cudaGetSymbolAddress((void**)&phlo,  g_hlo);
    cudaGetSymbolAddress((void**)&pohi,  g_ohi);
    cudaGetSymbolAddress((void**)&polo,  g_olo);
    cudaGetSymbolAddress((void**)&pffhi, g_ffhi);
    cudaGetSymbolAddress((void**)&pfflo, g_fflo);
    cudaGetSymbolAddress((void**)&pbqkv, g_bqkv);
    cudaGetSymbolAddress((void**)&ppart, g_part);
    cudaGetSymbolAddress((void**)&pwthi, g_wthi);
    cudaGetSymbolAddress((void**)&pwtlo, g_wtlo);
    cudaGetSymbolAddress((void**)&prl,   g_rowloss);
    cudaGetSymbolAddress((void**)&plg,   g_logits_scratch);

    cudaFuncSetAttribute(gemm_tc_kernel, cudaFuncAttributeMaxDynamicSharedMemorySize, GEMM_SMEM);

    const long long NLOG = (long long)BT * V_;
    float* logits = (out_size >= NLOG) ? out : plg;

    dim3 cb(32, 8);
    dim3 gQKVw(E_ / 32, NQKV / 32);
    dim3 gQKV(NQKV / 128, BT / 128);
    dim3 gWo(E_ / 128, BT / 128, 3);     // split-3, kslen 256
    dim3 gW1(FF / 128, BT / 128, 2);     // split-2, kslen 384
    dim3 gW2(E_ / 128, BT / 128, 3);     // split-3, kslen 1024
    dim3 gV(V_ / 128, BT / 128);
    dim3 gAttn(T_ / 64, B_ * H_);
    int rE = BT * E_ / 1024, rF = BT * FF / 1024;

    for (int l = 0; l < L_; l++) {
        size_t wel = (size_t)l * E_ * E_;
        // (l==0 ordering puts gemm at my-index 3 => global launch 5 for ncu)
        if (l == 0) embed_kernel<<<(BT * E_) / 256, 256>>>(idx, tok_emb, pos_emb, px);
        ln_kernel<<<BT, 256>>>(px, ln1g + l * E_, ln1b + l * E_, phhi, phlo);
        wconv_qkv_kernel<<<gQKVw, cb>>>(Wq, Wk, Wv, bq, bk, bv,
                                        pwthi + OFF_QKV(l), pwtlo + OFF_QKV(l), pbqkv, l);
        gemm_tc_kernel<<<gQKV, 256, GEMM_SMEM>>>(phhi, phlo,
            pwthi + OFF_QKV(l), pwtlo + OFF_QKV(l), pbqkv + l * NQKV, nullptr,
            pqkv, nullptr, nullptr, nullptr, NQKV, E_, E_, 0);
        attn_kernel<<<gAttn, 256>>>(pqkv, pohi, polo);
        wconvt_kernel<<<dim3(E_ / 32, E_ / 32), cb>>>(Wo + wel, pwthi + OFF_O(l), pwtlo + OFF_O(l), E_, E_);
        gemm_tc_kernel<<<gWo, 256, GEMM_SMEM>>>(pohi, polo,
            pwthi + OFF_O(l), pwtlo + OFF_O(l), nullptr, nullptr,
            nullptr, nullptr, nullptr, ppart, E_, E_, 256, 0);
        reduce_kernel<<<rE, 256>>>(ppart, 3, bo + l * E_, px, px, nullptr, nullptr, 0, E_);
        ln_kernel<<<BT, 256>>>(px, ln2g + l * E_, ln2b + l * E_, phhi, phlo);
        wconvt_kernel<<<dim3(FF / 32, E_ / 32), cb>>>(W1 + (size_t)l * E_ * FF,
            pwthi + OFF_W1(l), pwtlo + OFF_W1(l), E_, FF);
        gemm_tc_kernel<<<gW1, 256, GEMM_SMEM>>>(phhi, phlo,
            pwthi + OFF_W1(l), pwtlo + OFF_W1(l), nullptr, nullptr,
            nullptr, nullptr, nullptr, ppart, FF, E_, 384, 0);
        reduce_kernel<<<rF, 256>>>(ppart, 2, b1 + l * FF, nullptr, nullptr, pffhi, pfflo, 1, FF);
        wconvt_kernel<<<dim3(E_ / 32, FF / 32), cb>>>(W2 + (size_t)l * FF * E_,
            pwthi + OFF_W2(l), pwtlo + OFF_W2(l), FF, E_);
        gemm_tc_kernel<<<gW2, 256, GEMM_SMEM>>>(pffhi, pfflo,
            pwthi + OFF_W2(l), pwtlo + OFF_W2(l), nullptr, nullptr,
            nullptr, nullptr, nullptr, ppart, E_, FF, 1024, 0);
        reduce_kernel<<<rE, 256>>>(ppart, 3, b2 + l * E_, px, px, nullptr, nullptr, 0, E_);
    }
    ln_kernel<<<BT, 256>>>(px, lnfg, lnfb, phhi, phlo);
    wconvt_kernel<<<dim3(V_ / 32, E_ / 32), cb>>>(Wlm, pwthi + OFF_LM, pwtlo + OFF_LM, E_, V_);
    gemm_tc_kernel<<<gV, 256, GEMM_SMEM>>>(phhi, phlo,
        pwthi + OFF_LM, pwtlo + OFF_LM, blm, nullptr,
        logits, nullptr, nullptr, nullptr, V_, E_, E_, 0);

    // --- loss ---
    float* loss_dst = nullptr;
    if (out_size == 1)        loss_dst = out;
    else if (out_size > NLOG) loss_dst = out + NLOG;
    if (loss_dst) {
        row_lse_kernel<<<BT, 256>>>(logits, targets, prl);
        loss_reduce_kernel<<<1, 256>>>(prl, loss_dst);
    }
}

// round 7
// speedup vs baseline: 1.2721x; 1.0744x over previous
#include <cuda_runtime.h>
#include <cuda_bf16.h>
#include <cuda_fp16.h>
#include <math.h>
#include <stdint.h>

#define L_  4
#define H_  12
#define E_  768
#define HS_ 64
#define V_  32000
#define B_  2
#define T_  1024
#define BT  2048
#define FF  3072
#define NQKV 2304

// ---- weight scratch offsets (elements) ----
#define WPL 7077888ull
#define OFF_QKV(l) ((size_t)(l) * WPL)
#define OFF_O(l)   (OFF_QKV(l) + 1769472ull)
#define OFF_W1(l)  (OFF_QKV(l) + 2359296ull)
#define OFF_W2(l)  (OFF_QKV(l) + 4718592ull)
#define OFF_LM     ((size_t)4 * WPL)
#define WTOT       (OFF_LM + 24576000ull)

// ---------------- scratch (static device globals) ----------------------------
__device__ float g_x[BT * E_];
__device__ float g_qkv[BT * NQKV];
__device__ __nv_bfloat16 g_hhi[BT * E_];
__device__ __nv_bfloat16 g_hlo[BT * E_];
__device__ __nv_bfloat16 g_ohi[BT * E_];
__device__ __nv_bfloat16 g_olo[BT * E_];
__device__ __nv_bfloat16 g_ffhi[BT * FF];
__device__ __nv_bfloat16 g_fflo[BT * FF];
__device__ float g_bqkv[L_ * NQKV];
__device__ float g_part[2ull * BT * FF];
__device__ __nv_bfloat16 g_wthi[WTOT];
__device__ __nv_bfloat16 g_wtlo[WTOT];
__device__ __half g_wlmh[(size_t)V_ * E_];
__device__ float g_rowloss[BT];
__device__ float g_logits_scratch[(size_t)BT * V_];

// ---------------- PTX helpers ------------------------------------------------
__device__ __forceinline__ uint32_t smem_u32(const void* p) {
    uint32_t a;
    asm("{ .reg .u64 t; cvta.to.shared.u64 t, %1; cvt.u32.u64 %0, t; }" : "=r"(a) : "l"(p));
    return a;
}
__device__ __forceinline__ void mma16816(float* c, const uint32_t* a, uint32_t b0, uint32_t b1) {
    asm volatile(
        "mma.sync.aligned.m16n8k16.row.col.f32.bf16.bf16.f32 "
        "{%0,%1,%2,%3}, {%4,%5,%6,%7}, {%8,%9}, {%0,%1,%2,%3};"
        : "+f"(c[0]), "+f"(c[1]), "+f"(c[2]), "+f"(c[3])
        : "r"(a[0]), "r"(a[1]), "r"(a[2]), "r"(a[3]), "r"(b0), "r"(b1));
}
__device__ __forceinline__ void mma16816h(float* c, const uint32_t* a, uint32_t b0, uint32_t b1) {
    asm volatile(
        "mma.sync.aligned.m16n8k16.row.col.f32.f16.f16.f32 "
        "{%0,%1,%2,%3}, {%4,%5,%6,%7}, {%8,%9}, {%0,%1,%2,%3};"
        : "+f"(c[0]), "+f"(c[1]), "+f"(c[2]), "+f"(c[3])
        : "r"(a[0]), "r"(a[1]), "r"(a[2]), "r"(a[3]), "r"(b0), "r"(b1));
}
__device__ __forceinline__ void ldsm4(uint32_t* r, uint32_t addr) {
    asm volatile("ldmatrix.sync.aligned.m8n8.x4.shared.b16 {%0,%1,%2,%3}, [%4];"
                 : "=r"(r[0]), "=r"(r[1]), "=r"(r[2]), "=r"(r[3]) : "r"(addr));
}
__device__ __forceinline__ void cpasync16(uint32_t dst, const void* src) {
    asm volatile("cp.async.cg.shared.global [%0], [%1], 16;" :: "r"(dst), "l"(src));
}

// ---------------- fused QKV weight repack+transpose+split + bias concat ------
__global__ __launch_bounds__(256) void wconv_qkv_kernel(const float* __restrict__ Wq,
                                                        const float* __restrict__ Wk,
                                                        const float* __restrict__ Wv,
                                                        const float* __restrict__ bq,
                                                        const float* __restrict__ bk,
                                                        const float* __restrict__ bv,
                                                        __nv_bfloat16* __restrict__ Whi,
                                                        __nv_bfloat16* __restrict__ Wlo,
                                                        float* __restrict__ bqkv,
                                                        int l) {
    __shared__ float s[32][33];
    int n0 = blockIdx.y * 32, e0 = blockIdx.x * 32;
    int tx = threadIdx.x, ty = threadIdx.y;
    int sel = n0 / E_;
    int nn = n0 % E_;
    int h = nn >> 6, hs0 = nn & 63;
    const float* src = sel == 0 ? Wq : (sel == 1 ? Wk : Wv);
    const float* base = src + ((size_t)(l * H_ + h) * E_) * 64;
#pragma unroll
    for (int i = 0; i < 4; i++) {
        int e = ty + 8 * i;
        s[e][tx] = base[(size_t)(e0 + e) * 64 + hs0 + tx];
    }
    __syncthreads();
#pragma unroll
    for (int i = 0; i < 4; i++) {
        int nl = ty + 8 * i;
        float x = s[tx][nl];
        __nv_bfloat16 hh = __float2bfloat16(x);
        __nv_bfloat16 ll = __float2bfloat16(x - __bfloat162float(hh));
        size_t oi = (size_t)(n0 + nl) * E_ + e0 + tx;
        Whi[oi] = hh;
        Wlo[oi] = ll;
    }
    int gid = (blockIdx.y * gridDim.x + blockIdx.x) * 256 + ty * 32 + tx;
    if (gid < NQKV) {
        float v;
        if (gid < E_)            v = bq[l * E_ + gid];
        else if (gid < 2 * E_)   v = bk[l * E_ + gid - E_];
        else                     v = bv[l * E_ + gid - 2 * E_];
        bqkv[l * NQKV + gid] = v;
    }
}

// ---------------- weight transpose + bf16 hi/lo split ------------------------
__global__ __launch_bounds__(256) void wconvt_kernel(const float* __restrict__ W,
                                                     __nv_bfloat16* __restrict__ Whi,
                                                     __nv_bfloat16* __restrict__ Wlo,
                                                     int K, int N) {
    __shared__ float s[32][33];
    int k0 = blockIdx.y * 32, n0 = blockIdx.x * 32;
    int tx = threadIdx.x, ty = threadIdx.y;
#pragma unroll
    for (int i = 0; i < 4; i++)
        s[ty + 8 * i][tx] = W[(size_t)(k0 + ty + 8 * i) * N + n0 + tx];
    __syncthreads();
#pragma unroll
    for (int i = 0; i < 4; i++) {
        int n = ty + 8 * i;
        float x = s[tx][n];
        __nv_bfloat16 h = __float2bfloat16(x);
        __nv_bfloat16 l = __float2bfloat16(x - __bfloat162float(h));
        size_t oi = (size_t)(n0 + n) * K + k0 + tx;
        Whi[oi] = h;
        Wlo[oi] = l;
    }
}

// ---------------- LM weight transpose -> single fp16 -------------------------
__global__ __launch_bounds__(256) void wconvt_lm_kernel(const float* __restrict__ W,
                                                        __half* __restrict__ Wt) {
    __shared__ float s[32][33];
    int k0 = blockIdx.y * 32, n0 = blockIdx.x * 32;
    int tx = threadIdx.x, ty = threadIdx.y;
#pragma unroll
    for (int i = 0; i < 4; i++)
        s[ty + 8 * i][tx] = W[(size_t)(k0 + ty + 8 * i) * V_ + n0 + tx];
    __syncthreads();
#pragma unroll
    for (int i = 0; i < 4; i++) {
        int n = ty + 8 * i;
        Wt[(size_t)(n0 + n) * E_ + k0 + tx] = __float2half_rn(s[tx][n]);
    }
}

// ---------------- embedding -------------------------------------------------
__global__ __launch_bounds__(256) void embed_kernel(const int* __restrict__ idx,
                                                    const float* __restrict__ tok,
                                                    const float* __restrict__ pos,
                                                    float* __restrict__ x) {
    int i = blockIdx.x * 256 + threadIdx.x;
    int e = i % E_;
    int t = i / E_;
    int token = idx[t];
    x[i] = tok[(size_t)token * E_ + e] + pos[(t % T_) * E_ + e];
}

// ---------------- layernorm -> bf16 hi/lo (standalone, l=0 only) -------------
__global__ __launch_bounds__(256) void ln_kernel(const float* __restrict__ x,
                                                 const float* __restrict__ g,
                                                 const float* __restrict__ b,
                                                 __nv_bfloat16* __restrict__ hi,
                                                 __nv_bfloat16* __restrict__ lo) {
    int row = blockIdx.x;
    int tid = threadIdx.x;
    const float* xr = x + (size_t)row * E_;
    float v[3], s = 0.f, sq = 0.f;
#pragma unroll
    for (int i = 0; i < 3; i++) {
        v[i] = xr[tid + i * 256];
        s += v[i];
        sq += v[i] * v[i];
    }
#pragma unroll
    for (int o = 16; o > 0; o >>= 1) {
        s  += __shfl_xor_sync(0xffffffffu, s, o);
        sq += __shfl_xor_sync(0xffffffffu, sq, o);
    }
    __shared__ float ss[8], ssq[8];
    if ((tid & 31) == 0) { ss[tid >> 5] = s; ssq[tid >> 5] = sq; }
    __syncthreads();
    s = 0.f; sq = 0.f;
#pragma unroll
    for (int i = 0; i < 8; i++) { s += ss[i]; sq += ssq[i]; }
    float mean = s * (1.f / E_);
    float var  = sq * (1.f / E_) - mean * mean;
    float rstd = rsqrtf(var + 1e-5f);
    size_t rb = (size_t)row * E_;
#pragma unroll
    for (int i = 0; i < 3; i++) {
        int e = tid + i * 256;
        float y = (v[i] - mean) * rstd * g[e] + b[e];
        __nv_bfloat16 h = __float2bfloat16(y);
        hi[rb + e] = h;
        lo[rb + e] = __float2bfloat16(y - __bfloat162float(h));
    }
}

// ---------------- fused split-K reduce + residual + layernorm ----------------
// x += sum(parts)+bias ; then LN(x) -> hi/lo (bf16 or fp16-bits when FP16=1)
template<int FP16>
__global__ __launch_bounds__(256) void reduce_ln_kernel(const float* __restrict__ parts,
                                                        int nsplit,
                                                        const float* __restrict__ bias,
                                                        float* __restrict__ x,
                                                        const float* __restrict__ g,
                                                        const float* __restrict__ b,
                                                        __nv_bfloat16* __restrict__ hi,
                                                        __nv_bfloat16* __restrict__ lo) {
    int row = blockIdx.x, tid = threadIdx.x;
    size_t rb = (size_t)row * E_;
    const size_t plane = (size_t)BT * E_;
    float v[3], s = 0.f, sq = 0.f;
#pragma unroll
    for (int i = 0; i < 3; i++) {
        int e = tid + (i << 8);
        size_t ix = rb + e;
        float t = parts[ix];
        for (int p = 1; p < nsplit; p++) t += parts[plane * p + ix];
        t += bias[e] + x[ix];
        x[ix] = t;
        v[i] = t; s += t; sq += t * t;
    }
#pragma unroll
    for (int o = 16; o > 0; o >>= 1) {
        s  += __shfl_xor_sync(0xffffffffu, s, o);
        sq += __shfl_xor_sync(0xffffffffu, sq, o);
    }
    __shared__ float ss[8], ssq[8];
    if ((tid & 31) == 0) { ss[tid >> 5] = s; ssq[tid >> 5] = sq; }
    __syncthreads();
    s = 0.f; sq = 0.f;
#pragma unroll
    for (int i = 0; i < 8; i++) { s += ss[i]; sq += ssq[i]; }
    float mean = s * (1.f / E_);
    float var  = sq * (1.f / E_) - mean * mean;
    float rstd = rsqrtf(var + 1e-5f);
#pragma unroll
    for (int i = 0; i < 3; i++) {
        int e = tid + (i << 8);
        float y = (v[i] - mean) * rstd * g[e] + b[e];
        if (FP16) {
            __half h = __float2half_rn(y);
            __half l2 = __float2half_rn(y - __half2float(h));
            *(unsigned short*)&hi[rb + e] = *(unsigned short*)&h;
            *(unsigned short*)&lo[rb + e] = *(unsigned short*)&l2;
        } else {
            __nv_bfloat16 h = __float2bfloat16(y);
            hi[rb + e] = h;
            lo[rb + e] = __float2bfloat16(y - __bfloat162float(h));
        }
    }
}

// ---------------- tensor-core GEMM (bf16 hi/lo, 3-sweep, 3 stages) -----------
#define STG3 32768
#define GEMM_SMEM (3 * STG3)
__global__ __launch_bounds__(256, 2)
void gemm_tc_kernel(const __nv_bfloat16* __restrict__ Ahi,
                    const __nv_bfloat16* __restrict__ Alo,
                    const __nv_bfloat16* __restrict__ Bhi,
                    const __nv_bfloat16* __restrict__ Blo,
                    const float* __restrict__ bias,
                    const float* __restrict__ resid,
                    float* __restrict__ C,
                    __nv_bfloat16* __restrict__ Chi,
                    __nv_bfloat16* __restrict__ Clo,
                    float* __restrict__ Cpart,
                    int N, int K, int kslen, int relu) {
    extern __shared__ __align__(16) char smem[];
    int tid = threadIdx.x, lane = tid & 31, wid = tid >> 5;
    int wm = wid >> 2, wn = wid & 3;
    int row0 = blockIdx.y << 7, col0 = blockIdx.x << 7;
    int k0base = blockIdx.z * kslen;
    uint32_t sb = smem_u32(smem);

    float acc[4][4][4] = {};

    const int nCh = kslen >> 5;
    int frow = tid >> 1;
    int fc0 = (tid & 1) << 1;
    uint32_t fsw = (uint32_t)((frow >> 1) & 3);

    auto loadStage = [&](int stg, int c) {
        if (c < nCh) {
            uint32_t st = sb + stg * STG3;
            int k0 = k0base + (c << 5);
            size_t abase = (size_t)(row0 + frow) * K + k0;
            size_t bbase = (size_t)(col0 + frow) * K + k0;
#pragma unroll
            for (int cc = 0; cc < 2; cc++) {
                int cl = fc0 + cc;
                uint32_t doff = (uint32_t)(frow << 6) + (((uint32_t)cl ^ fsw) << 4);
                cpasync16(st + doff,         Ahi + abase + (cl << 3));
                cpasync16(st + 8192 + doff,  Alo + abase + (cl << 3));
                cpasync16(st + 16384 + doff, Bhi + bbase + (cl << 3));
                cpasync16(st + 24576 + doff, Blo + bbase + (cl << 3));
            }
        }
        asm volatile("cp.async.commit_group;" ::: "memory");
    };

    int arow[4], brow[2];
    uint32_t asw[4], bsw[2];
#pragma unroll
    for (int mf = 0; mf < 4; mf++) {
        arow[mf] = (wm << 6) + (mf << 4) + (lane & 15);
        asw[mf] = (uint32_t)((arow[mf] >> 1) & 3);
    }
#pragma unroll
    for (int g = 0; g < 2; g++) {
        brow[g] = (wn << 5) + (g << 4) + (lane & 7) + (((lane >> 3) & 1) << 3);
        bsw[g] = (uint32_t)((brow[g] >> 1) & 3);
    }
    int kc = lane >> 4;

    loadStage(0, 0);
    loadStage(1, 1);

    int stg = 0;
    for (int c = 0; c < nCh; ++c) {
        asm volatile("cp.async.wait_group 1;" ::: "memory");
        __syncthreads();
        loadStage(stg == 0 ? 2 : stg - 1, c + 2);   // overlap loads with MMAs below
        uint32_t st = sb + stg * STG3;
#pragma unroll
        for (int ks = 0; ks < 2; ks++) {
            int cl = (ks << 1) + kc;
            uint32_t ah[4][4], bh[2][4];
#pragma unroll
            for (int mf = 0; mf < 4; mf++)
                ldsm4(ah[mf], st + (uint32_t)(arow[mf] << 6) + (((uint32_t)cl ^ asw[mf]) << 4));
#pragma unroll
            for (int g = 0; g < 2; g++)
                ldsm4(bh[g], st + 16384 + (uint32_t)(brow[g] << 6) + (((uint32_t)cl ^ bsw[g]) << 4));
            // sweep 1: ahi * bhi
#pragma unroll
            for (int mf = 0; mf < 4; mf++)
#pragma unroll
                for (int nf = 0; nf < 4; nf++)
                    mma16816(acc[mf][nf], ah[mf], bh[nf >> 1][nf & 1], bh[nf >> 1][(nf & 1) + 2]);
            // sweep 2: alo * bhi (load al late)
            {
                uint32_t al[4][4];
#pragma unroll
                for (int mf = 0; mf < 4; mf++)
                    ldsm4(al[mf], st + 8192 + (uint32_t)(arow[mf] << 6) + (((uint32_t)cl ^ asw[mf]) << 4));
#pragma unroll
                for (int mf = 0; mf < 4; mf++)
#pragma unroll
                    for (int nf = 0; nf < 4; nf++)
                        mma16816(acc[mf][nf], al[mf], bh[nf >> 1][nf & 1], bh[nf >> 1][(nf & 1) + 2]);
            }
            // sweep 3: ahi * blo (bh dead, load bl late)
            {
                uint32_t bl[2][4];
#pragma unroll
                for (int g = 0; g < 2; g++)
                    ldsm4(bl[g], st + 24576 + (uint32_t)(brow[g] << 6) + (((uint32_t)cl ^ bsw[g]) << 4));
#pragma unroll
                for (int mf = 0; mf < 4; mf++)
#pragma unroll
                    for (int nf = 0; nf < 4; nf++)
                        mma16816(acc[mf][nf], ah[mf], bl[nf >> 1][nf & 1], bl[nf >> 1][(nf & 1) + 2]);
            }
        }
        stg = (stg == 2) ? 0 : stg + 1;
    }

    if (Cpart) {
        size_t plane = (size_t)blockIdx.z * (((size_t)gridDim.y << 7) * (size_t)N);
#pragma unroll
        for (int mf = 0; mf < 4; mf++) {
            int rbase = row0 + (wm << 6) + (mf << 4) + (lane >> 2);
#pragma unroll
            for (int nf = 0; nf < 4; nf++) {
                int cb = col0 + (wn << 5) + (nf << 3) + ((lane & 3) << 1);
#pragma unroll
                for (int half = 0; half < 2; half++) {
                    int r = rbase + (half << 3);
                    *(float2*)(Cpart + plane + (size_t)r * N + cb) =
                        make_float2(acc[mf][nf][half * 2], acc[mf][nf][half * 2 + 1]);
                }
            }
        }
        return;
    }
#pragma unroll
    for (int mf = 0; mf < 4; mf++) {
        int rbase = row0 + (wm << 6) + (mf << 4) + (lane >> 2);
#pragma unroll
        for (int nf = 0; nf < 4; nf++) {
            int cb = col0 + (wn << 5) + (nf << 3) + ((lane & 3) << 1);
            float b0 = bias ? bias[cb] : 0.f;
            float b1 = bias ? bias[cb + 1] : 0.f;
#pragma unroll
            for (int half = 0; half < 2; half++) {
                int r = rbase + (half << 3);
                float v0 = acc[mf][nf][half * 2 + 0] + b0;
                float v1 = acc[mf][nf][half * 2 + 1] + b1;
                size_t gi = (size_t)r * N + cb;
                if (relu) { v0 = fmaxf(v0, 0.f); v1 = fmaxf(v1, 0.f); }
                if (Chi) {
                    __nv_bfloat162 h = __floats2bfloat162_rn(v0, v1);
                    float2 hf = __bfloat1622float2(h);
                    __nv_bfloat162 l = __floats2bfloat162_rn(v0 - hf.x, v1 - hf.y);
                    *(__nv_bfloat162*)(Chi + gi) = h;
                    *(__nv_bfloat162*)(Clo + gi) = l;
                } else {
                    if (resid) { v0 += resid[gi]; v1 += resid[gi + 1]; }
                    *(float2*)(C + gi) = make_float2(v0, v1);
                }
            }
        }
    }
}

// ---------------- LM-head GEMM: fp16 2-sweep (A hi/lo fp16, B single fp16) ---
#define LSTG 24576
#define GEMM_LM_SMEM (3 * LSTG)
__global__ __launch_bounds__(256, 2)
void gemm_lm_kernel(const __nv_bfloat16* __restrict__ AhiB,   // fp16 bits
                    const __nv_bfloat16* __restrict__ AloB,   // fp16 bits
                    const __half* __restrict__ Bt,
                    const float* __restrict__ bias,
                    float* __restrict__ C) {
    extern __shared__ __align__(16) char smem[];
    const int N = V_, K = E_;
    int tid = threadIdx.x, lane = tid & 31, wid = tid >> 5;
    int wm = wid >> 2, wn = wid & 3;
    int row0 = blockIdx.y << 7, col0 = blockIdx.x << 7;
    uint32_t sb = smem_u32(smem);
    const __half* Ahi = (const __half*)AhiB;
    const __half* Alo = (const __half*)AloB;

    float acc[4][4][4] = {};
    const int nCh = K >> 5;
    int frow = tid >> 1;
    int fc0 = (tid & 1) << 1;
    uint32_t fsw = (uint32_t)((frow >> 1) & 3);

    auto loadStage = [&](int stg, int c) {
        if (c < nCh) {
            uint32_t st = sb + stg * LSTG;
            int k0 = c << 5;
            size_t abase = (size_t)(row0 + frow) * K + k0;
            size_t bbase = (size_t)(col0 + frow) * K + k0;
#pragma unroll
            for (int cc = 0; cc < 2; cc++) {
                int cl = fc0 + cc;
                uint32_t doff = (uint32_t)(frow << 6) + (((uint32_t)cl ^ fsw) << 4);
                cpasync16(st + doff,         Ahi + abase + (cl << 3));
                cpasync16(st + 8192 + doff,  Alo + abase + (cl << 3));
                cpasync16(st + 16384 + doff, Bt  + bbase + (cl << 3));
            }
        }
        asm volatile("cp.async.commit_group;" ::: "memory");
    };

    int arow[4], brow[2];
    uint32_t asw[4], bsw[2];
#pragma unroll
    for (int mf = 0; mf < 4; mf++) {
        arow[mf] = (wm << 6) + (mf << 4) + (lane & 15);
        asw[mf] = (uint32_t)((arow[mf] >> 1) & 3);
    }
#pragma unroll
    for (int g = 0; g < 2; g++) {
        brow[g] = (wn << 5) + (g << 4) + (lane & 7) + (((lane >> 3) & 1) << 3);
        bsw[g] = (uint32_t)((brow[g] >> 1) & 3);
    }
    int kc = lane >> 4;

    loadStage(0, 0);
    loadStage(1, 1);

    int stg = 0;
    for (int c = 0; c < nCh; ++c) {
        asm volatile("cp.async.wait_group 1;" ::: "memory");
        __syncthreads();
        loadStage(stg == 0 ? 2 : stg - 1, c + 2);
        uint32_t st = sb + stg * LSTG;
#pragma unroll
        for (int ks = 0; ks < 2; ks++) {
            int cl = (ks << 1) + kc;
            uint32_t ah[4][4], bb[2][4];
#pragma unroll
            for (int mf = 0; mf < 4; mf++)
                ldsm4(ah[mf], st + (uint32_t)(arow[mf] << 6) + (((uint32_t)cl ^ asw[mf]) << 4));
#pragma unroll
            for (int g = 0; g < 2; g++)
                ldsm4(bb[g], st + 16384 + (uint32_t)(brow[g] << 6) + (((uint32_t)cl ^ bsw[g]) << 4));
#pragma unroll
            for (int mf = 0; mf < 4; mf++)
#pragma unroll
                for (int nf = 0; nf < 4; nf++)
                    mma16816h(acc[mf][nf], ah[mf], bb[nf >> 1][nf & 1], bb[nf >> 1][(nf & 1) + 2]);
            {
                uint32_t al[4][4];
#pragma unroll
                for (int mf = 0; mf < 4; mf++)
                    ldsm4(al[mf], st + 8192 + (uint32_t)(arow[mf] << 6) + (((uint32_t)cl ^ asw[mf]) << 4));
#pragma unroll
                for (int mf = 0; mf < 4; mf++)
#pragma unroll
                    for (int nf = 0; nf < 4; nf++)
                        mma16816h(acc[mf][nf], al[mf], bb[nf >> 1][nf & 1], bb[nf >> 1][(nf & 1) + 2]);
            }
        }
        stg = (stg == 2) ? 0 : stg + 1;
    }
#pragma unroll
    for (int mf = 0; mf < 4; mf++) {
        int rbase = row0 + (wm << 6) + (mf << 4) + (lane >> 2);
#pragma unroll
        for (int nf = 0; nf < 4; nf++) {
            int cb = col0 + (wn << 5) + (nf << 3) + ((lane & 3) << 1);
            float b0 = bias[cb], b1 = bias[cb + 1];
#pragma unroll
            for (int half = 0; half < 2; half++) {
                int r = rbase + (half << 3);
                size_t gi = (size_t)r * N + cb;
                *(float2*)(C + gi) = make_float2(acc[mf][nf][half * 2] + b0,
                                                 acc[mf][nf][half * 2 + 1] + b1);
            }
        }
    }
}

// ---------------- split-K reduce (W1 path: relu + bf16 hi/lo out) ------------
__global__ __launch_bounds__(256) void reduce_kernel(const float* __restrict__ parts,
                                                     int nsplit,
                                                     const float* __restrict__ bias,
                                                     __nv_bfloat16* __restrict__ outHi,
                                                     __nv_bfloat16* __restrict__ outLo,
                                                     int N) {
    size_t i = ((size_t)blockIdx.x * 256 + threadIdx.x) * 4;
    size_t plane = (size_t)BT * N;
    int col = (int)(i % N);
    float4 s = *(const float4*)(parts + i);
    for (int p = 1; p < nsplit; p++) {
        float4 t = *(const float4*)(parts + plane * p + i);
        s.x += t.x; s.y += t.y; s.z += t.z; s.w += t.w;
    }
    float4 b = *(const float4*)(bias + col);
    s.x = fmaxf(s.x + b.x, 0.f); s.y = fmaxf(s.y + b.y, 0.f);
    s.z = fmaxf(s.z + b.z, 0.f); s.w = fmaxf(s.w + b.w, 0.f);
    __nv_bfloat162 h0 = __floats2bfloat162_rn(s.x, s.y);
    __nv_bfloat162 h1 = __floats2bfloat162_rn(s.z, s.w);
    float2 f0 = __bfloat1622float2(h0), f1 = __bfloat1622float2(h1);
    __nv_bfloat162 l0 = __floats2bfloat162_rn(s.x - f0.x, s.y - f0.y);
    __nv_bfloat162 l1 = __floats2bfloat162_rn(s.z - f1.x, s.w - f1.y);
    *(__nv_bfloat162*)(outHi + i) = h0;
    *(__nv_bfloat162*)(outHi + i + 2) = h1;
    *(__nv_bfloat162*)(outLo + i) = l0;
    *(__nv_bfloat162*)(outLo + i + 2) = l1;
}

// ---------------- flash-style causal attention (fp32, full reg budget) -------
__global__ __launch_bounds__(256, 1) void attn_kernel(const float* __restrict__ qkv,
                                                      __nv_bfloat16* __restrict__ ohi,
                                                      __nv_bfloat16* __restrict__ olo) {
    __shared__ float sQP[64][64];
    __shared__ float sK[64][64];
    __shared__ float sVt[64][64];
    int tid = threadIdx.x;
    int qt = blockIdx.x;
    int bh = blockIdx.y;
    int bb = bh / H_, hh = bh % H_;
    int r = tid >> 2, quarter = tid & 3;
    int cbase = quarter << 4;
    size_t rowbase = (size_t)(bb * T_ + (qt << 6));
    const float* q = qkv + hh * 64;
    const float* k = qkv + E_ + hh * 64;
    const float* v = qkv + 2 * E_ + hh * 64;

    for (int i = tid; i < 4096; i += 256) {
        int rr = i >> 6, cc = i & 63;
        sQP[rr][cc] = q[(rowbase + rr) * (size_t)NQKV + cc];
    }
    __syncthreads();
    float qreg[64];
#pragma unroll
    for (int i = 0; i < 16; i++) {
        float4 t4 = *(const float4*)&sQP[r][i << 2];
        qreg[i * 4 + 0] = t4.x * 0.125f; qreg[i * 4 + 1] = t4.y * 0.125f;
        qreg[i * 4 + 2] = t4.z * 0.125f; qreg[i * 4 + 3] = t4.w * 0.125f;
    }
    float m = -INFINITY, lsum = 0.f;
    float oacc[16];
#pragma unroll
    for (int j = 0; j < 16; j++) oacc[j] = 0.f;
    int qi = (qt << 6) + r;

    for (int kt = 0; kt <= qt; kt++) {
        __syncthreads();
        size_t kbase = (size_t)(bb * T_ + (kt << 6));
        for (int i = tid; i < 4096; i += 256) {
            int rr = i >> 6, cc = i & 63;
            sK[rr][cc]  = k[(kbase + rr) * (size_t)NQKV + cc];
            sVt[cc][rr] = v[(kbase + rr) * (size_t)NQKV + cc];
        }
        __syncthreads();

        float s[16];
#pragma unroll
        for (int j = 0; j < 16; j++) s[j] = 0.f;
#pragma unroll
        for (int kk = 0; kk < 64; kk += 4) {
#pragma unroll
            for (int j = 0; j < 16; j++) {
                float4 k4 = *(const float4*)&sK[cbase + j][kk];
                s[j] += qreg[kk] * k4.x + qreg[kk + 1] * k4.y +
                        qreg[kk + 2] * k4.z + qreg[kk + 3] * k4.w;
            }
        }
        if (kt == qt) {
#pragma unroll
            for (int j = 0; j < 16; j++)
                if ((kt << 6) + cbase + j > qi) s[j] = -INFINITY;
        }
        float mt = s[0];
#pragma unroll
        for (int j = 1; j < 16; j++) mt = fmaxf(mt, s[j]);
        mt = fmaxf(mt, __shfl_xor_sync(0xffffffffu, mt, 1));
        mt = fmaxf(mt, __shfl_xor_sync(0xffffffffu, mt, 2));
        float mnew = fmaxf(m, mt);
        float alpha = __expf(m - mnew);
        float psum = 0.f;
        float p[16];
#pragma unroll
        for (int j = 0; j < 16; j++) { p[j] = __expf(s[j] - mnew); psum += p[j]; }
        psum += __shfl_xor_sync(0xffffffffu, psum, 1);
        psum += __shfl_xor_sync(0xffffffffu, psum, 2);
        lsum = lsum * alpha + psum;
        m = mnew;
#pragma unroll
        for (int j = 0; j < 16; j++) oacc[j] *= alpha;
#pragma unroll
        for (int j = 0; j < 16; j++) sQP[r][cbase + j] = p[j];
        __syncthreads();
#pragma unroll
        for (int c0 = 0; c0 < 64; c0 += 16) {
            float pc[16];
#pragma unroll
            for (int ii = 0; ii < 4; ii++) {
                float4 p4 = *(const float4*)&sQP[r][c0 + (ii << 2)];
                pc[ii * 4 + 0] = p4.x; pc[ii * 4 + 1] = p4.y;
                pc[ii * 4 + 2] = p4.z; pc[ii * 4 + 3] = p4.w;
            }
#pragma unroll
            for (int j = 0; j < 16; j++) {
                int d = cbase + j;
#pragma unroll
                for (int cc = 0; cc < 16; cc += 4) {
                    float4 v4 = *(const float4*)&sVt[d][c0 + cc];
                    oacc[j] += pc[cc] * v4.x + pc[cc + 1] * v4.y +
                               pc[cc + 2] * v4.z + pc[cc + 3] * v4.w;
                }
            }
        }
    }
    float linv = 1.f / lsum;
    size_t obase = (rowbase + r) * (size_t)E_ + hh * 64 + cbase;
#pragma unroll
    for (int j = 0; j < 16; j += 2) {
        float v0 = oacc[j] * linv, v1 = oacc[j + 1] * linv;
        __nv_bfloat162 h = __floats2bfloat162_rn(v0, v1);
        float2 hf = __bfloat1622float2(h);
        __nv_bfloat162 l = __floats2bfloat162_rn(v0 - hf.x, v1 - hf.y);
        *(__nv_bfloat162*)(ohi + obase + j) = h;
        *(__nv_bfloat162*)(olo + obase + j) = l;
    }
}

// ---------------- loss ------------------------------------------------------
__global__ __launch_bounds__(256) void row_lse_kernel(const float* __restrict__ logits,
                                                      const int* __restrict__ targets,
                                                      float* __restrict__ rowloss) {
    int row = blockIdx.x, tid = threadIdx.x;
    const float* lr = logits + (size_t)row * V_;
    float mx = -INFINITY;
    for (int i = tid; i < V_; i += 256) mx = fmaxf(mx, lr[i]);
#pragma unroll
    for (int o = 16; o > 0; o >>= 1) mx = fmaxf(mx, __shfl_xor_sync(0xffffffffu, mx, o));
    __shared__ float sm[8];
    if ((tid & 31) == 0) sm[tid >> 5] = mx;
    __syncthreads();
    float m2 = -INFINITY;
#pragma unroll
    for (int i = 0; i < 8; i++) m2 = fmaxf(m2, sm[i]);
    float se = 0.f;
    for (int i = tid; i < V_; i += 256) se += __expf(lr[i] - m2);
#pragma unroll
    for (int o = 16; o > 0; o >>= 1) se += __shfl_xor_sync(0xffffffffu, se, o);
    __shared__ float ssum[8];
    if ((tid & 31) == 0) ssum[tid >> 5] = se;
    __syncthreads();
    if (tid == 0) {
        float tot = 0.f;
#pragma unroll
        for (int i = 0; i < 8; i++) tot += ssum[i];
        rowloss[row] = (logf(tot) + m2) - lr[targets[row]];
    }
}

__global__ __launch_bounds__(256) void loss_reduce_kernel(const float* __restrict__ rowloss,
                                                          float* __restrict__ out) {
    int tid = threadIdx.x;
    float s = 0.f;
    for (int i = tid; i < BT; i += 256) s += rowloss[i];
#pragma unroll
    for (int o = 16; o > 0; o >>= 1) s += __shfl_xor_sync(0xffffffffu, s, o);
    __shared__ float sm[8];
    if ((tid & 31) == 0) sm[tid >> 5] = s;
    __syncthreads();
    if (tid == 0) {
        float t = 0.f;
#pragma unroll
        for (int i = 0; i < 8; i++) t += sm[i];
        out[0] = t * (1.f / BT);
    }
}

// ---------------- launch ----------------------------------------------------
extern "C" void kernel_launch(void* const* d_in, const int* in_sizes, int n_in,
                              void* d_out, int out_size) {
    const int*   idx     = (const int*)d_in[0];
    const int*   targets = (const int*)d_in[1];
    const float* tok_emb = (const float*)d_in[2];
    const float* pos_emb = (const float*)d_in[3];
    const float* Wq  = (const float*)d_in[4];
    const float* bq  = (const float*)d_in[5];
    const float* Wk  = (const float*)d_in[6];
    const float* bk  = (const float*)d_in[7];
    const float* Wv  = (const float*)d_in[8];
    const float* bv  = (const float*)d_in[9];
    const float* Wo  = (const float*)d_in[10];
    const float* bo  = (const float*)d_in[11];
    const float* ln1g = (const float*)d_in[12];
    const float* ln1b = (const float*)d_in[13];
    const float* W1  = (const float*)d_in[14];
    const float* b1  = (const float*)d_in[15];
    const float* W2  = (const float*)d_in[16];
    const float* b2  = (const float*)d_in[17];
    const float* ln2g = (const float*)d_in[18];
    const float* ln2b = (const float*)d_in[19];
    const float* lnfg = (const float*)d_in[20];
    const float* lnfb = (const float*)d_in[21];
    const float* Wlm = (const float*)d_in[22];
    const float* blm = (const float*)d_in[23];
    float* out = (float*)d_out;

    float *px, *pqkv, *pbqkv, *ppart, *prl, *plg;
    __nv_bfloat16 *phhi, *phlo, *pohi, *polo, *pffhi, *pfflo, *pwthi, *pwtlo;
    __half *pwlmh;
    cudaGetSymbolAddress((void**)&px,    g_x);
    cudaGetSymbolAddress((void**)&pqkv,  g_qkv);
    cudaGetSymbolAddress((void**)&phhi,  g_hhi);
    cudaGetSymbolAddress((void**)&phlo,  g_hlo);
    cudaGetSymbolAddress((void**)&pohi,  g_ohi);
    cudaGetSymbolAddress((void**)&polo,  g_olo);
    cudaGetSymbolAddress((void**)&pffhi, g_ffhi);
    cudaGetSymbolAddress((void**)&pfflo, g_fflo);
    cudaGetSymbolAddress((void**)&pbqkv, g_bqkv);
    cudaGetSymbolAddress((void**)&ppart, g_part);
    cudaGetSymbolAddress((void**)&pwthi, g_wthi);
    cudaGetSymbolAddress((void**)&pwtlo, g_wtlo);
    cudaGetSymbolAddress((void**)&pwlmh, g_wlmh);
    cudaGetSymbolAddress((void**)&prl,   g_rowloss);
    cudaGetSymbolAddress((void**)&plg,   g_logits_scratch);

    cudaFuncSetAttribute(gemm_tc_kernel, cudaFuncAttributeMaxDynamicSharedMemorySize, GEMM_SMEM);
    cudaFuncSetAttribute(gemm_lm_kernel, cudaFuncAttributeMaxDynamicSharedMemorySize, GEMM_LM_SMEM);

    const long long NLOG = (long long)BT * V_;
    float* logits = (out_size >= NLOG) ? out : plg;

    dim3 cb(32, 8);
    dim3 gQKVw(E_ / 32, NQKV / 32);
    dim3 gQKV(NQKV / 128, BT / 128);
    dim3 gWo(E_ / 128, BT / 128, 3);
    dim3 gW1(FF / 128, BT / 128, 2);
    dim3 gW2(E_ / 128, BT / 128, 3);
    dim3 gVd(V_ / 128, BT / 128);
    dim3 gAttn(T_ / 64, B_ * H_);
    int rF = BT * FF / 1024;

    for (int l = 0; l < L_; l++) {
        size_t wel = (size_t)l * E_ * E_;
        if (l == 0) {
            embed_kernel<<<(BT * E_) / 256, 256>>>(idx, tok_emb, pos_emb, px);       // 0
            ln_kernel<<<BT, 256>>>(px, ln1g, ln1b, phhi, phlo);                      // 1
        }
        wconv_qkv_kernel<<<gQKVw, cb>>>(Wq, Wk, Wv, bq, bk, bv,
                                        pwthi + OFF_QKV(l), pwtlo + OFF_QKV(l), pbqkv, l);  // 2
        gemm_tc_kernel<<<gQKV, 256, GEMM_SMEM>>>(phhi, phlo,                          // 3 (= global 5)
            pwthi + OFF_QKV(l), pwtlo + OFF_QKV(l), pbqkv + l * NQKV, nullptr,
            pqkv, nullptr, nullptr, nullptr, NQKV, E_, E_, 0);
        attn_kernel<<<gAttn, 256>>>(pqkv, pohi, polo);
        wconvt_kernel<<<dim3(E_ / 32, E_ / 32), cb>>>(Wo + wel, pwthi + OFF_O(l), pwtlo + OFF_O(l), E_, E_);
        gemm_tc_kernel<<<gWo, 256, GEMM_SMEM>>>(pohi, polo,
            pwthi + OFF_O(l), pwtlo + OFF_O(l), nullptr, nullptr,
            nullptr, nullptr, nullptr, ppart, E_, E_, 256, 0);
        reduce_ln_kernel<0><<<BT, 256>>>(ppart, 3, bo + l * E_, px,
                                         ln2g + l * E_, ln2b + l * E_, phhi, phlo);
        wconvt_kernel<<<dim3(FF / 32, E_ / 32), cb>>>(W1 + (size_t)l * E_ * FF,
            pwthi + OFF_W1(l), pwtlo + OFF_W1(l), E_, FF);
        gemm_tc_kernel<<<gW1, 256, GEMM_SMEM>>>(phhi, phlo,
            pwthi + OFF_W1(l), pwtlo + OFF_W1(l), nullptr, nullptr,
            nullptr, nullptr, nullptr, ppart, FF, E_, 384, 0);
        reduce_kernel<<<rF, 256>>>(ppart, 2, b1 + l * FF, pffhi, pfflo, FF);
        wconvt_kernel<<<dim3(E_ / 32, FF / 32), cb>>>(W2 + (size_t)l * FF * E_,
            pwthi + OFF_W2(l), pwtlo + OFF_W2(l), FF, E_);
        gemm_tc_kernel<<<gW2, 256, GEMM_SMEM>>>(pffhi, pfflo,
            pwthi + OFF_W2(l), pwtlo + OFF_W2(l), nullptr, nullptr,
            nullptr, nullptr, nullptr, ppart, E_, FF, 1024, 0);
        if (l < L_ - 1)
            reduce_ln_kernel<0><<<BT, 256>>>(ppart, 3, b2 + l * E_, px,
                                             ln1g + (l + 1) * E_, ln1b + (l + 1) * E_, phhi, phlo);
        else
            reduce_ln_kernel<1><<<BT, 256>>>(ppart, 3, b2 + l * E_, px,
                                             lnfg, lnfb, phhi, phlo);   // fp16 for LM head
    }
    wconvt_lm_kernel<<<dim3(V_ / 32, E_ / 32), cb>>>(Wlm, pwlmh);
    gemm_lm_kernel<<<gVd, 256, GEMM_LM_SMEM>>>(phhi, phlo, pwlmh, blm, logits);

    // --- loss ---
    float* loss_dst = nullptr;
    if (out_size == 1)        loss_dst = out;
    else if (out_size > NLOG) loss_dst = out + NLOG;
    if (loss_dst) {
        row_lse_kernel<<<BT, 256>>>(logits, targets, prl);
        loss_reduce_kernel<<<1, 256>>>(prl, loss_dst);
    }
}

// round 8
// speedup vs baseline: 2.4340x; 1.9134x over previous
#include <cuda_runtime.h>
#include <cuda_bf16.h>
#include <cuda_fp16.h>
#include <math.h>
#include <stdint.h>

#define L_  4
#define H_  12
#define E_  768
#define HS_ 64
#define V_  32000
#define B_  2
#define T_  1024
#define BT  2048
#define FF  3072
#define NQKV 2304

// ---- weight scratch offsets (elements) ----
#define WPL 7077888ull
#define OFF_QKV(l) ((size_t)(l) * WPL)
#define OFF_O(l)   (OFF_QKV(l) + 1769472ull)
#define OFF_W1(l)  (OFF_QKV(l) + 2359296ull)
#define OFF_W2(l)  (OFF_QKV(l) + 4718592ull)
#define OFF_LM     ((size_t)4 * WPL)
#define WTOT       (OFF_LM + 24576000ull)

// ---------------- scratch (static device globals) ----------------------------
__device__ float g_x[BT * E_];
__device__ float g_qkv[BT * NQKV];
__device__ __nv_bfloat16 g_hhi[BT * E_];
__device__ __nv_bfloat16 g_hlo[BT * E_];
__device__ __nv_bfloat16 g_ohi[BT * E_];
__device__ __nv_bfloat16 g_olo[BT * E_];
__device__ __nv_bfloat16 g_ffhi[BT * FF];
__device__ __nv_bfloat16 g_fflo[BT * FF];
__device__ float g_bqkv[L_ * NQKV];
__device__ float g_part[2ull * BT * FF];
__device__ __nv_bfloat16 g_wthi[WTOT];
__device__ __nv_bfloat16 g_wtlo[WTOT];
__device__ __half g_wlmh[(size_t)V_ * E_];
__device__ float g_rowloss[BT];
__device__ float g_logits_scratch[(size_t)BT * V_];

// ---------------- PTX helpers ------------------------------------------------
__device__ __forceinline__ uint32_t smem_u32(const void* p) {
    uint32_t a;
    asm("{ .reg .u64 t; cvta.to.shared.u64 t, %1; cvt.u32.u64 %0, t; }" : "=r"(a) : "l"(p));
    return a;
}
__device__ __forceinline__ void mma16816(float* c, const uint32_t* a, uint32_t b0, uint32_t b1) {
    asm volatile(
        "mma.sync.aligned.m16n8k16.row.col.f32.bf16.bf16.f32 "
        "{%0,%1,%2,%3}, {%4,%5,%6,%7}, {%8,%9}, {%0,%1,%2,%3};"
        : "+f"(c[0]), "+f"(c[1]), "+f"(c[2]), "+f"(c[3])
        : "r"(a[0]), "r"(a[1]), "r"(a[2]), "r"(a[3]), "r"(b0), "r"(b1));
}
__device__ __forceinline__ void mma16816h(float* c, const uint32_t* a, uint32_t b0, uint32_t b1) {
    asm volatile(
        "mma.sync.aligned.m16n8k16.row.col.f32.f16.f16.f32 "
        "{%0,%1,%2,%3}, {%4,%5,%6,%7}, {%8,%9}, {%0,%1,%2,%3};"
        : "+f"(c[0]), "+f"(c[1]), "+f"(c[2]), "+f"(c[3])
        : "r"(a[0]), "r"(a[1]), "r"(a[2]), "r"(a[3]), "r"(b0), "r"(b1));
}
__device__ __forceinline__ void ldsm4(uint32_t* r, uint32_t addr) {
    asm volatile("ldmatrix.sync.aligned.m8n8.x4.shared.b16 {%0,%1,%2,%3}, [%4];"
                 : "=r"(r[0]), "=r"(r[1]), "=r"(r[2]), "=r"(r[3]) : "r"(addr));
}
__device__ __forceinline__ void cpasync16(uint32_t dst, const void* src) {
    asm volatile("cp.async.cg.shared.global [%0], [%1], 16;" :: "r"(dst), "l"(src));
}

// ---------------- fused QKV weight repack+transpose+split + bias concat ------
__global__ __launch_bounds__(256) void wconv_qkv_kernel(const float* __restrict__ Wq,
                                                        const float* __restrict__ Wk,
                                                        const float* __restrict__ Wv,
                                                        const float* __restrict__ bq,
                                                        const float* __restrict__ bk,
                                                        const float* __restrict__ bv,
                                                        __nv_bfloat16* __restrict__ Whi,
                                                        __nv_bfloat16* __restrict__ Wlo,
                                                        float* __restrict__ bqkv,
                                                        int l) {
    __shared__ float s[32][33];
    int n0 = blockIdx.y * 32, e0 = blockIdx.x * 32;
    int tx = threadIdx.x, ty = threadIdx.y;
    int sel = n0 / E_;
    int nn = n0 % E_;
    int h = nn >> 6, hs0 = nn & 63;
    const float* src = sel == 0 ? Wq : (sel == 1 ? Wk : Wv);
    const float* base = src + ((size_t)(l * H_ + h) * E_) * 64;
#pragma unroll
    for (int i = 0; i < 4; i++) {
        int e = ty + 8 * i;
        s[e][tx] = base[(size_t)(e0 + e) * 64 + hs0 + tx];
    }
    __syncthreads();
#pragma unroll
    for (int i = 0; i < 4; i++) {
        int nl = ty + 8 * i;
        float x = s[tx][nl];
        __nv_bfloat16 hh = __float2bfloat16(x);
        __nv_bfloat16 ll = __float2bfloat16(x - __bfloat162float(hh));
        size_t oi = (size_t)(n0 + nl) * E_ + e0 + tx;
        Whi[oi] = hh;
        Wlo[oi] = ll;
    }
    int gid = (blockIdx.y * gridDim.x + blockIdx.x) * 256 + ty * 32 + tx;
    if (gid < NQKV) {
        float v;
        if (gid < E_)            v = bq[l * E_ + gid];
        else if (gid < 2 * E_)   v = bk[l * E_ + gid - E_];
        else                     v = bv[l * E_ + gid - 2 * E_];
        bqkv[l * NQKV + gid] = v;
    }
}

// ---------------- weight transpose + bf16 hi/lo split ------------------------
__global__ __launch_bounds__(256) void wconvt_kernel(const float* __restrict__ W,
                                                     __nv_bfloat16* __restrict__ Whi,
                                                     __nv_bfloat16* __restrict__ Wlo,
                                                     int K, int N) {
    __shared__ float s[32][33];
    int k0 = blockIdx.y * 32, n0 = blockIdx.x * 32;
    int tx = threadIdx.x, ty = threadIdx.y;
#pragma unroll
    for (int i = 0; i < 4; i++)
        s[ty + 8 * i][tx] = W[(size_t)(k0 + ty + 8 * i) * N + n0 + tx];
    __syncthreads();
#pragma unroll
    for (int i = 0; i < 4; i++) {
        int n = ty + 8 * i;
        float x = s[tx][n];
        __nv_bfloat16 h = __float2bfloat16(x);
        __nv_bfloat16 l = __float2bfloat16(x - __bfloat162float(h));
        size_t oi = (size_t)(n0 + n) * K + k0 + tx;
        Whi[oi] = h;
        Wlo[oi] = l;
    }
}

// ---------------- LM weight transpose -> single fp16 -------------------------
__global__ __launch_bounds__(256) void wconvt_lm_kernel(const float* __restrict__ W,
                                                        __half* __restrict__ Wt) {
    __shared__ float s[32][33];
    int k0 = blockIdx.y * 32, n0 = blockIdx.x * 32;
    int tx = threadIdx.x, ty = threadIdx.y;
#pragma unroll
    for (int i = 0; i < 4; i++)
        s[ty + 8 * i][tx] = W[(size_t)(k0 + ty + 8 * i) * V_ + n0 + tx];
    __syncthreads();
#pragma unroll
    for (int i = 0; i < 4; i++) {
        int n = ty + 8 * i;
        Wt[(size_t)(n0 + n) * E_ + k0 + tx] = __float2half_rn(s[tx][n]);
    }
}

// ---------------- fused embedding + layernorm -> bf16 hi/lo -------------------
__global__ __launch_bounds__(256) void embed_ln_kernel(const int* __restrict__ idx,
                                                       const float* __restrict__ tok,
                                                       const float* __restrict__ pos,
                                                       const float* __restrict__ g,
                                                       const float* __restrict__ b,
                                                       float* __restrict__ x,
                                                       __nv_bfloat16* __restrict__ hi,
                                                       __nv_bfloat16* __restrict__ lo) {
    int row = blockIdx.x;
    int tid = threadIdx.x;
    int token = idx[row];
    int tp = row % T_;
    size_t rb = (size_t)row * E_;
    float v[3], s = 0.f, sq = 0.f;
#pragma unroll
    for (int i = 0; i < 3; i++) {
        int e = tid + (i << 8);
        float t = tok[(size_t)token * E_ + e] + pos[(size_t)tp * E_ + e];
        x[rb + e] = t;
        v[i] = t; s += t; sq += t * t;
    }
#pragma unroll
    for (int o = 16; o > 0; o >>= 1) {
        s  += __shfl_xor_sync(0xffffffffu, s, o);
        sq += __shfl_xor_sync(0xffffffffu, sq, o);
    }
    __shared__ float ss[8], ssq[8];
    if ((tid & 31) == 0) { ss[tid >> 5] = s; ssq[tid >> 5] = sq; }
    __syncthreads();
    s = 0.f; sq = 0.f;
#pragma unroll
    for (int i = 0; i < 8; i++) { s += ss[i]; sq += ssq[i]; }
    float mean = s * (1.f / E_);
    float var  = sq * (1.f / E_) - mean * mean;
    float rstd = rsqrtf(var + 1e-5f);
#pragma unroll
    for (int i = 0; i < 3; i++) {
        int e = tid + (i << 8);
        float y = (v[i] - mean) * rstd * g[e] + b[e];
        __nv_bfloat16 h = __float2bfloat16(y);
        hi[rb + e] = h;
        lo[rb + e] = __float2bfloat16(y - __bfloat162float(h));
    }
}

// ---------------- fused split-K reduce + residual + layernorm ----------------
template<int FP16>
__global__ __launch_bounds__(256) void reduce_ln_kernel(const float* __restrict__ parts,
                                                        int nsplit,
                                                        const float* __restrict__ bias,
                                                        float* __restrict__ x,
                                                        const float* __restrict__ g,
                                                        const float* __restrict__ b,
                                                        __nv_bfloat16* __restrict__ hi,
                                                        __nv_bfloat16* __restrict__ lo) {
    int row = blockIdx.x, tid = threadIdx.x;
    size_t rb = (size_t)row * E_;
    const size_t plane = (size_t)BT * E_;
    float v[3], s = 0.f, sq = 0.f;
#pragma unroll
    for (int i = 0; i < 3; i++) {
        int e = tid + (i << 8);
        size_t ix = rb + e;
        float t = parts[ix];
        for (int p = 1; p < nsplit; p++) t += parts[plane * p + ix];
        t += bias[e] + x[ix];
        x[ix] = t;
        v[i] = t; s += t; sq += t * t;
    }
#pragma unroll
    for (int o = 16; o > 0; o >>= 1) {
        s  += __shfl_xor_sync(0xffffffffu, s, o);
        sq += __shfl_xor_sync(0xffffffffu, sq, o);
    }
    __shared__ float ss[8], ssq[8];
    if ((tid & 31) == 0) { ss[tid >> 5] = s; ssq[tid >> 5] = sq; }
    __syncthreads();
    s = 0.f; sq = 0.f;
#pragma unroll
    for (int i = 0; i < 8; i++) { s += ss[i]; sq += ssq[i]; }
    float mean = s * (1.f / E_);
    float var  = sq * (1.f / E_) - mean * mean;
    float rstd = rsqrtf(var + 1e-5f);
#pragma unroll
    for (int i = 0; i < 3; i++) {
        int e = tid + (i << 8);
        float y = (v[i] - mean) * rstd * g[e] + b[e];
        if (FP16) {
            __half h = __float2half_rn(y);
            __half l2 = __float2half_rn(y - __half2float(h));
            *(unsigned short*)&hi[rb + e] = *(unsigned short*)&h;
            *(unsigned short*)&lo[rb + e] = *(unsigned short*)&l2;
        } else {
            __nv_bfloat16 h = __float2bfloat16(y);
            hi[rb + e] = h;
            lo[rb + e] = __float2bfloat16(y - __bfloat162float(h));
        }
    }
}

// ---------------- tensor-core GEMM (bf16 hi/lo, 3-sweep, 3 stages) -----------
#define STG3 32768
#define GEMM_SMEM (3 * STG3)
__global__ __launch_bounds__(256, 2)
void gemm_tc_kernel(const __nv_bfloat16* __restrict__ Ahi,
                    const __nv_bfloat16* __restrict__ Alo,
                    const __nv_bfloat16* __restrict__ Bhi,
                    const __nv_bfloat16* __restrict__ Blo,
                    const float* __restrict__ bias,
                    const float* __restrict__ resid,
                    float* __restrict__ C,
                    __nv_bfloat16* __restrict__ Chi,
                    __nv_bfloat16* __restrict__ Clo,
                    float* __restrict__ Cpart,
                    int N, int K, int kslen, int relu) {
    extern __shared__ __align__(16) char smem[];
    int tid = threadIdx.x, lane = tid & 31, wid = tid >> 5;
    int wm = wid >> 2, wn = wid & 3;
    int row0 = blockIdx.y << 7, col0 = blockIdx.x << 7;
    int k0base = blockIdx.z * kslen;
    uint32_t sb = smem_u32(smem);

    float acc[4][4][4] = {};

    const int nCh = kslen >> 5;
    int frow = tid >> 1;
    int fc0 = (tid & 1) << 1;
    uint32_t fsw = (uint32_t)((frow >> 1) & 3);

    auto loadStage = [&](int stg, int c) {
        if (c < nCh) {
            uint32_t st = sb + stg * STG3;
            int k0 = k0base + (c << 5);
            size_t abase = (size_t)(row0 + frow) * K + k0;
            size_t bbase = (size_t)(col0 + frow) * K + k0;
#pragma unroll
            for (int cc = 0; cc < 2; cc++) {
                int cl = fc0 + cc;
                uint32_t doff = (uint32_t)(frow << 6) + (((uint32_t)cl ^ fsw) << 4);
                cpasync16(st + doff,         Ahi + abase + (cl << 3));
                cpasync16(st + 8192 + doff,  Alo + abase + (cl << 3));
                cpasync16(st + 16384 + doff, Bhi + bbase + (cl << 3));
                cpasync16(st + 24576 + doff, Blo + bbase + (cl << 3));
            }
        }
        asm volatile("cp.async.commit_group;" ::: "memory");
    };

    int arow[4], brow[2];
    uint32_t asw[4], bsw[2];
#pragma unroll
    for (int mf = 0; mf < 4; mf++) {
        arow[mf] = (wm << 6) + (mf << 4) + (lane & 15);
        asw[mf] = (uint32_t)((arow[mf] >> 1) & 3);
    }
#pragma unroll
    for (int g = 0; g < 2; g++) {
        brow[g] = (wn << 5) + (g << 4) + (lane & 7) + (((lane >> 3) & 1) << 3);
        bsw[g] = (uint32_t)((brow[g] >> 1) & 3);
    }
    int kc = lane >> 4;

    loadStage(0, 0);
    loadStage(1, 1);

    int stg = 0;
    for (int c = 0; c < nCh; ++c) {
        asm volatile("cp.async.wait_group 1;" ::: "memory");
        __syncthreads();
        loadStage(stg == 0 ? 2 : stg - 1, c + 2);
        uint32_t st = sb + stg * STG3;
#pragma unroll
        for (int ks = 0; ks < 2; ks++) {
            int cl = (ks << 1) + kc;
            uint32_t ah[4][4], bh[2][4];
#pragma unroll
            for (int mf = 0; mf < 4; mf++)
                ldsm4(ah[mf], st + (uint32_t)(arow[mf] << 6) + (((uint32_t)cl ^ asw[mf]) << 4));
#pragma unroll
            for (int g = 0; g < 2; g++)
                ldsm4(bh[g], st + 16384 + (uint32_t)(brow[g] << 6) + (((uint32_t)cl ^ bsw[g]) << 4));
#pragma unroll
            for (int mf = 0; mf < 4; mf++)
#pragma unroll
                for (int nf = 0; nf < 4; nf++)
                    mma16816(acc[mf][nf], ah[mf], bh[nf >> 1][nf & 1], bh[nf >> 1][(nf & 1) + 2]);
            {
                uint32_t al[4][4];
#pragma unroll
                for (int mf = 0; mf < 4; mf++)
                    ldsm4(al[mf], st + 8192 + (uint32_t)(arow[mf] << 6) + (((uint32_t)cl ^ asw[mf]) << 4));
#pragma unroll
                for (int mf = 0; mf < 4; mf++)
#pragma unroll
                    for (int nf = 0; nf < 4; nf++)
                        mma16816(acc[mf][nf], al[mf], bh[nf >> 1][nf & 1], bh[nf >> 1][(nf & 1) + 2]);
            }
            {
                uint32_t bl[2][4];
#pragma unroll
                for (int g = 0; g < 2; g++)
                    ldsm4(bl[g], st + 24576 + (uint32_t)(brow[g] << 6) + (((uint32_t)cl ^ bsw[g]) << 4));
#pragma unroll
                for (int mf = 0; mf < 4; mf++)
#pragma unroll
                    for (int nf = 0; nf < 4; nf++)
                        mma16816(acc[mf][nf], ah[mf], bl[nf >> 1][nf & 1], bl[nf >> 1][(nf & 1) + 2]);
            }
        }
        stg = (stg == 2) ? 0 : stg + 1;
    }

    if (Cpart) {
        size_t plane = (size_t)blockIdx.z * (((size_t)gridDim.y << 7) * (size_t)N);
#pragma unroll
        for (int mf = 0; mf < 4; mf++) {
            int rbase = row0 + (wm << 6) + (mf << 4) + (lane >> 2);
#pragma unroll
            for (int nf = 0; nf < 4; nf++) {
                int cb = col0 + (wn << 5) + (nf << 3) + ((lane & 3) << 1);
#pragma unroll
                for (int half = 0; half < 2; half++) {
                    int r = rbase + (half << 3);
                    *(float2*)(Cpart + plane + (size_t)r * N + cb) =
                        make_float2(acc[mf][nf][half * 2], acc[mf][nf][half * 2 + 1]);
                }
            }
        }
        return;
    }
#pragma unroll
    for (int mf = 0; mf < 4; mf++) {
        int rbase = row0 + (wm << 6) + (mf << 4) + (lane >> 2);
#pragma unroll
        for (int nf = 0; nf < 4; nf++) {
            int cb = col0 + (wn << 5) + (nf << 3) + ((lane & 3) << 1);
            float b0 = bias ? bias[cb] : 0.f;
            float b1 = bias ? bias[cb + 1] : 0.f;
#pragma unroll
            for (int half = 0; half < 2; half++) {
                int r = rbase + (half << 3);
                float v0 = acc[mf][nf][half * 2 + 0] + b0;
                float v1 = acc[mf][nf][half * 2 + 1] + b1;
                size_t gi = (size_t)r * N + cb;
                if (relu) { v0 = fmaxf(v0, 0.f); v1 = fmaxf(v1, 0.f); }
                if (Chi) {
                    __nv_bfloat162 h = __floats2bfloat162_rn(v0, v1);
                    float2 hf = __bfloat1622float2(h);
                    __nv_bfloat162 l = __floats2bfloat162_rn(v0 - hf.x, v1 - hf.y);
                    *(__nv_bfloat162*)(Chi + gi) = h;
                    *(__nv_bfloat162*)(Clo + gi) = l;
                } else {
                    if (resid) { v0 += resid[gi]; v1 += resid[gi + 1]; }
                    *(float2*)(C + gi) = make_float2(v0, v1);
                }
            }
        }
    }
}

// ---------------- LM-head GEMM: fp16 2-sweep ---------------------------------
#define LSTG 24576
#define GEMM_LM_SMEM (3 * LSTG)
__global__ __launch_bounds__(256, 2)
void gemm_lm_kernel(const __nv_bfloat16* __restrict__ AhiB,
                    const __nv_bfloat16* __restrict__ AloB,
                    const __half* __restrict__ Bt,
                    const float* __restrict__ bias,
                    float* __restrict__ C) {
    extern __shared__ __align__(16) char smem[];
    const int N = V_, K = E_;
    int tid = threadIdx.x, lane = tid & 31, wid = tid >> 5;
    int wm = wid >> 2, wn = wid & 3;
    int row0 = blockIdx.y << 7, col0 = blockIdx.x << 7;
    uint32_t sb = smem_u32(smem);
    const __half* Ahi = (const __half*)AhiB;
    const __half* Alo = (const __half*)AloB;

    float acc[4][4][4] = {};
    const int nCh = K >> 5;
    int frow = tid >> 1;
    int fc0 = (tid & 1) << 1;
    uint32_t fsw = (uint32_t)((frow >> 1) & 3);

    auto loadStage = [&](int stg, int c) {
        if (c < nCh) {
            uint32_t st = sb + stg * LSTG;
            int k0 = c << 5;
            size_t abase = (size_t)(row0 + frow) * K + k0;
            size_t bbase = (size_t)(col0 + frow) * K + k0;
#pragma unroll
            for (int cc = 0; cc < 2; cc++) {
                int cl = fc0 + cc;
                uint32_t doff = (uint32_t)(frow << 6) + (((uint32_t)cl ^ fsw) << 4);
                cpasync16(st + doff,         Ahi + abase + (cl << 3));
                cpasync16(st + 8192 + doff,  Alo + abase + (cl << 3));
                cpasync16(st + 16384 + doff, Bt  + bbase + (cl << 3));
            }
        }
        asm volatile("cp.async.commit_group;" ::: "memory");
    };

    int arow[4], brow[2];
    uint32_t asw[4], bsw[2];
#pragma unroll
    for (int mf = 0; mf < 4; mf++) {
        arow[mf] = (wm << 6) + (mf << 4) + (lane & 15);
        asw[mf] = (uint32_t)((arow[mf] >> 1) & 3);
    }
#pragma unroll
    for (int g = 0; g < 2; g++) {
        brow[g] = (wn << 5) + (g << 4) + (lane & 7) + (((lane >> 3) & 1) << 3);
        bsw[g] = (uint32_t)((brow[g] >> 1) & 3);
    }
    int kc = lane >> 4;

    loadStage(0, 0);
    loadStage(1, 1);

    int stg = 0;
    for (int c = 0; c < nCh; ++c) {
        asm volatile("cp.async.wait_group 1;" ::: "memory");
        __syncthreads();
        loadStage(stg == 0 ? 2 : stg - 1, c + 2);
        uint32_t st = sb + stg * LSTG;
#pragma unroll
        for (int ks = 0; ks < 2; ks++) {
            int cl = (ks << 1) + kc;
            uint32_t ah[4][4], bb[2][4];
#pragma unroll
            for (int mf = 0; mf < 4; mf++)
                ldsm4(ah[mf], st + (uint32_t)(arow[mf] << 6) + (((uint32_t)cl ^ asw[mf]) << 4));
#pragma unroll
            for (int g = 0; g < 2; g++)
                ldsm4(bb[g], st + 16384 + (uint32_t)(brow[g] << 6) + (((uint32_t)cl ^ bsw[g]) << 4));
#pragma unroll
            for (int mf = 0; mf < 4; mf++)
#pragma unroll
                for (int nf = 0; nf < 4; nf++)
                    mma16816h(acc[mf][nf], ah[mf], bb[nf >> 1][nf & 1], bb[nf >> 1][(nf & 1) + 2]);
            {
                uint32_t al[4][4];
#pragma unroll
                for (int mf = 0; mf < 4; mf++)
                    ldsm4(al[mf], st + 8192 + (uint32_t)(arow[mf] << 6) + (((uint32_t)cl ^ asw[mf]) << 4));
#pragma unroll
                for (int mf = 0; mf < 4; mf++)
#pragma unroll
                    for (int nf = 0; nf < 4; nf++)
                        mma16816h(acc[mf][nf], al[mf], bb[nf >> 1][nf & 1], bb[nf >> 1][(nf & 1) + 2]);
            }
        }
        stg = (stg == 2) ? 0 : stg + 1;
    }
#pragma unroll
    for (int mf = 0; mf < 4; mf++) {
        int rbase = row0 + (wm << 6) + (mf << 4) + (lane >> 2);
#pragma unroll
        for (int nf = 0; nf < 4; nf++) {
            int cb = col0 + (wn << 5) + (nf << 3) + ((lane & 3) << 1);
            float b0 = bias[cb], b1 = bias[cb + 1];
#pragma unroll
            for (int half = 0; half < 2; half++) {
                int r = rbase + (half << 3);
                size_t gi = (size_t)r * N + cb;
                *(float2*)(C + gi) = make_float2(acc[mf][nf][half * 2] + b0,
                                                 acc[mf][nf][half * 2 + 1] + b1);
            }
        }
    }
}

// ---------------- split-K reduce (W1 path) -----------------------------------
__global__ __launch_bounds__(256) void reduce_kernel(const float* __restrict__ parts,
                                                     int nsplit,
                                                     const float* __restrict__ bias,
                                                     __nv_bfloat16* __restrict__ outHi,
                                                     __nv_bfloat16* __restrict__ outLo,
                                                     int N) {
    size_t i = ((size_t)blockIdx.x * 256 + threadIdx.x) * 4;
    size_t plane = (size_t)BT * N;
    int col = (int)(i % N);
    float4 s = *(const float4*)(parts + i);
    for (int p = 1; p < nsplit; p++) {
        float4 t = *(const float4*)(parts + plane * p + i);
        s.x += t.x; s.y += t.y; s.z += t.z; s.w += t.w;
    }
    float4 b = *(const float4*)(bias + col);
    s.x = fmaxf(s.x + b.x, 0.f); s.y = fmaxf(s.y + b.y, 0.f);
    s.z = fmaxf(s.z + b.z, 0.f); s.w = fmaxf(s.w + b.w, 0.f);
    __nv_bfloat162 h0 = __floats2bfloat162_rn(s.x, s.y);
    __nv_bfloat162 h1 = __floats2bfloat162_rn(s.z, s.w);
    float2 f0 = __bfloat1622float2(h0), f1 = __bfloat1622float2(h1);
    __nv_bfloat162 l0 = __floats2bfloat162_rn(s.x - f0.x, s.y - f0.y);
    __nv_bfloat162 l1 = __floats2bfloat162_rn(s.z - f1.x, s.w - f1.y);
    *(__nv_bfloat162*)(outHi + i) = h0;
    *(__nv_bfloat162*)(outHi + i + 2) = h1;
    *(__nv_bfloat162*)(outLo + i) = l0;
    *(__nv_bfloat162*)(outLo + i + 2) = l1;
}

// ---------------- flash-style causal attention -------------------------------
// Conflict-free smem geometry: 68-float rows + interleaved column mapping
// (thread handles cols/dims quarter + 4*j).
__global__ __launch_bounds__(256, 1) void attn_kernel(const float* __restrict__ qkv,
                                                      __nv_bfloat16* __restrict__ ohi,
                                                      __nv_bfloat16* __restrict__ olo) {
    __shared__ float sQP[64][68];
    __shared__ float sK[64][68];
    __shared__ float sVt[64][68];
    int tid = threadIdx.x;
    int qt = blockIdx.x;
    int bh = blockIdx.y;
    int bb = bh / H_, hh = bh % H_;
    int r = tid >> 2, quarter = tid & 3;
    size_t rowbase = (size_t)(bb * T_ + (qt << 6));
    const float* q = qkv + hh * 64;
    const float* k = qkv + E_ + hh * 64;
    const float* v = qkv + 2 * E_ + hh * 64;

    for (int i = tid; i < 4096; i += 256) {
        int rr = i >> 6, cc = i & 63;
        sQP[rr][cc] = q[(rowbase + rr) * (size_t)NQKV + cc];
    }
    __syncthreads();
    float qreg[64];
#pragma unroll
    for (int i = 0; i < 16; i++) {
        float4 t4 = *(const float4*)&sQP[r][i << 2];
        qreg[i * 4 + 0] = t4.x * 0.125f; qreg[i * 4 + 1] = t4.y * 0.125f;
        qreg[i * 4 + 2] = t4.z * 0.125f; qreg[i * 4 + 3] = t4.w * 0.125f;
    }
    float m = -INFINITY, lsum = 0.f;
    float oacc[16];
#pragma unroll
    for (int j = 0; j < 16; j++) oacc[j] = 0.f;
    int qi = (qt << 6) + r;

    for (int kt = 0; kt <= qt; kt++) {
        __syncthreads();
        size_t kbase = (size_t)(bb * T_ + (kt << 6));
        for (int i = tid; i < 4096; i += 256) {
            int rr = i >> 6, cc = i & 63;
            sK[rr][cc]  = k[(kbase + rr) * (size_t)NQKV + cc];
            sVt[cc][rr] = v[(kbase + rr) * (size_t)NQKV + cc];
        }
        __syncthreads();

        float s[16];
#pragma unroll
        for (int j = 0; j < 16; j++) s[j] = 0.f;
#pragma unroll
        for (int kk = 0; kk < 64; kk += 4) {
#pragma unroll
            for (int j = 0; j < 16; j++) {
                float4 k4 = *(const float4*)&sK[quarter + (j << 2)][kk];
                s[j] += qreg[kk] * k4.x + qreg[kk + 1] * k4.y +
                        qreg[kk + 2] * k4.z + qreg[kk + 3] * k4.w;
            }
        }
        if (kt == qt) {
#pragma unroll
            for (int j = 0; j < 16; j++)
                if ((kt << 6) + quarter + (j << 2) > qi) s[j] = -INFINITY;
        }
        float mt = s[0];
#pragma unroll
        for (int j = 1; j < 16; j++) mt = fmaxf(mt, s[j]);
        mt = fmaxf(mt, __shfl_xor_sync(0xffffffffu, mt, 1));
        mt = fmaxf(mt, __shfl_xor_sync(0xffffffffu, mt, 2));
        float mnew = fmaxf(m, mt);
        float alpha = __expf(m - mnew);
        float psum = 0.f;
        float p[16];
#pragma unroll
        for (int j = 0; j < 16; j++) { p[j] = __expf(s[j] - mnew); psum += p[j]; }
        psum += __shfl_xor_sync(0xffffffffu, psum, 1);
        psum += __shfl_xor_sync(0xffffffffu, psum, 2);
        lsum = lsum * alpha + psum;
        m = mnew;
#pragma unroll
        for (int j = 0; j < 16; j++) oacc[j] *= alpha;
#pragma unroll
        for (int j = 0; j < 16; j++) sQP[r][quarter + (j << 2)] = p[j];
        __syncthreads();
#pragma unroll
        for (int c0 = 0; c0 < 64; c0 += 16) {
            float pc[16];
#pragma unroll
            for (int ii = 0; ii < 4; ii++) {
                float4 p4 = *(const float4*)&sQP[r][c0 + (ii << 2)];
                pc[ii * 4 + 0] = p4.x; pc[ii * 4 + 1] = p4.y;
                pc[ii * 4 + 2] = p4.z; pc[ii * 4 + 3] = p4.w;
            }
#pragma unroll
            for (int j = 0; j < 16; j++) {
                int d = quarter + (j << 2);
#pragma unroll
                for (int cc = 0; cc < 16; cc += 4) {
                    float4 v4 = *(const float4*)&sVt[d][c0 + cc];
                    oacc[j] += pc[cc] * v4.x + pc[cc + 1] * v4.y +
                               pc[cc + 2] * v4.z + pc[cc + 3] * v4.w;
                }
            }
        }
    }
    float linv = 1.f / lsum;
    size_t obase = (rowbase + r) * (size_t)E_ + hh * 64;
#pragma unroll
    for (int j = 0; j < 16; j++) {
        float v0 = oacc[j] * linv;
        __nv_bfloat16 h = __float2bfloat16(v0);
        int col = quarter + (j << 2);
        ohi[obase + col] = h;
        olo[obase + col] = __float2bfloat16(v0 - __bfloat162float(h));
    }
}

// ---------------- loss ------------------------------------------------------
__global__ __launch_bounds__(256) void row_lse_kernel(const float* __restrict__ logits,
                                                      const int* __restrict__ targets,
                                                      float* __restrict__ rowloss) {
    int row = blockIdx.x, tid = threadIdx.x;
    const float* lr = logits + (size_t)row * V_;
    float mx = -INFINITY;
    for (int i = tid; i < V_; i += 256) mx = fmaxf(mx, lr[i]);
#pragma unroll
    for (int o = 16; o > 0; o >>= 1) mx = fmaxf(mx, __shfl_xor_sync(0xffffffffu, mx, o));
    __shared__ float sm[8];
    if ((tid & 31) == 0) sm[tid >> 5] = mx;
    __syncthreads();
    float m2 = -INFINITY;
#pragma unroll
    for (int i = 0; i < 8; i++) m2 = fmaxf(m2, sm[i]);
    float se = 0.f;
    for (int i = tid; i < V_; i += 256) se += __expf(lr[i] - m2);
#pragma unroll
    for (int o = 16; o > 0; o >>= 1) se += __shfl_xor_sync(0xffffffffu, se, o);
    __shared__ float ssum[8];
    if ((tid & 31) == 0) ssum[tid >> 5] = se;
    __syncthreads();
    if (tid == 0) {
        float tot = 0.f;
#pragma unroll
        for (int i = 0; i < 8; i++) tot += ssum[i];
        rowloss[row] = (logf(tot) + m2) - lr[targets[row]];
    }
}

__global__ __launch_bounds__(256) void loss_reduce_kernel(const float* __restrict__ rowloss,
                                                          float* __restrict__ out) {
    int tid = threadIdx.x;
    float s = 0.f;
    for (int i = tid; i < BT; i += 256) s += rowloss[i];
#pragma unroll
    for (int o = 16; o > 0; o >>= 1) s += __shfl_xor_sync(0xffffffffu, s, o);
    __shared__ float sm[8];
    if ((tid & 31) == 0) sm[tid >> 5] = s;
    __syncthreads();
    if (tid == 0) {
        float t = 0.f;
#pragma unroll
        for (int i = 0; i < 8; i++) t += sm[i];
        out[0] = t * (1.f / BT);
    }
}

// ---------------- launch ----------------------------------------------------
extern "C" void kernel_launch(void* const* d_in, const int* in_sizes, int n_in,
                              void* d_out, int out_size) {
    const int*   idx     = (const int*)d_in[0];
    const int*   targets = (const int*)d_in[1];
    const float* tok_emb = (const float*)d_in[2];
    const float* pos_emb = (const float*)d_in[3];
    const float* Wq  = (const float*)d_in[4];
    const float* bq  = (const float*)d_in[5];
    const float* Wk  = (const float*)d_in[6];
    const float* bk  = (const float*)d_in[7];
    const float* Wv  = (const float*)d_in[8];
    const float* bv  = (const float*)d_in[9];
    const float* Wo  = (const float*)d_in[10];
    const float* bo  = (const float*)d_in[11];
    const float* ln1g = (const float*)d_in[12];
    const float* ln1b = (const float*)d_in[13];
    const float* W1  = (const float*)d_in[14];
    const float* b1  = (const float*)d_in[15];
    const float* W2  = (const float*)d_in[16];
    const float* b2  = (const float*)d_in[17];
    const float* ln2g = (const float*)d_in[18];
    const float* ln2b = (const float*)d_in[19];
    const float* lnfg = (const float*)d_in[20];
    const float* lnfb = (const float*)d_in[21];
    const float* Wlm = (const float*)d_in[22];
    const float* blm = (const float*)d_in[23];
    float* out = (float*)d_out;

    float *px, *pqkv, *pbqkv, *ppart, *prl, *plg;
    __nv_bfloat16 *phhi, *phlo, *pohi, *polo, *pffhi, *pfflo, *pwthi, *pwtlo;
    __half *pwlmh;
    cudaGetSymbolAddress((void**)&px,    g_x);
    cudaGetSymbolAddress((void**)&pqkv,  g_qkv);
    cudaGetSymbolAddress((void**)&phhi,  g_hhi);
    cudaGetSymbolAddress((void**)&phlo,  g_hlo);
    cudaGetSymbolAddress((void**)&pohi,  g_ohi);
    cudaGetSymbolAddress((void**)&polo,  g_olo);
    cudaGetSymbolAddress((void**)&pffhi, g_ffhi);
    cudaGetSymbolAddress((void**)&pfflo, g_fflo);
    cudaGetSymbolAddress((void**)&pbqkv, g_bqkv);
    cudaGetSymbolAddress((void**)&ppart, g_part);
    cudaGetSymbolAddress((void**)&pwthi, g_wthi);
    cudaGetSymbolAddress((void**)&pwtlo, g_wtlo);
    cudaGetSymbolAddress((void**)&pwlmh, g_wlmh);
    cudaGetSymbolAddress((void**)&prl,   g_rowloss);
    cudaGetSymbolAddress((void**)&plg,   g_logits_scratch);

    cudaFuncSetAttribute(gemm_tc_kernel, cudaFuncAttributeMaxDynamicSharedMemorySize, GEMM_SMEM);
    cudaFuncSetAttribute(gemm_lm_kernel, cudaFuncAttributeMaxDynamicSharedMemorySize, GEMM_LM_SMEM);

    const long long NLOG = (long long)BT * V_;
    float* logits = (out_size >= NLOG) ? out : plg;

    dim3 cb(32, 8);
    dim3 gQKVw(E_ / 32, NQKV / 32);
    dim3 gQKV(NQKV / 128, BT / 128);
    dim3 gWo(E_ / 128, BT / 128, 3);
    dim3 gW1(FF / 128, BT / 128, 2);
    dim3 gW2(E_ / 128, BT / 128, 3);
    dim3 gVd(V_ / 128, BT / 128);
    dim3 gAttn(T_ / 64, B_ * H_);
    int rF = BT * FF / 1024;

    for (int l = 0; l < L_; l++) {
        size_t wel = (size_t)l * E_ * E_;
        if (l == 0)
            embed_ln_kernel<<<BT, 256>>>(idx, tok_emb, pos_emb, ln1g, ln1b, px, phhi, phlo); // 0
        wconv_qkv_kernel<<<gQKVw, cb>>>(Wq, Wk, Wv, bq, bk, bv,
                                        pwthi + OFF_QKV(l), pwtlo + OFF_QKV(l), pbqkv, l);  // 1
        gemm_tc_kernel<<<gQKV, 256, GEMM_SMEM>>>(phhi, phlo,                                // 2
            pwthi + OFF_QKV(l), pwtlo + OFF_QKV(l), pbqkv + l * NQKV, nullptr,
            pqkv, nullptr, nullptr, nullptr, NQKV, E_, E_, 0);
        attn_kernel<<<gAttn, 256>>>(pqkv, pohi, polo);                                      // 3 (= global 5)
        wconvt_kernel<<<dim3(E_ / 32, E_ / 32), cb>>>(Wo + wel, pwthi + OFF_O(l), pwtlo + OFF_O(l), E_, E_);
        gemm_tc_kernel<<<gWo, 256, GEMM_SMEM>>>(pohi, polo,
            pwthi + OFF_O(l), pwtlo + OFF_O(l), nullptr, nullptr,
            nullptr, nullptr, nullptr, ppart, E_, E_, 256, 0);
        reduce_ln_kernel<0><<<BT, 256>>>(ppart, 3, bo + l * E_, px,
                                         ln2g + l * E_, ln2b + l * E_, phhi, phlo);
        wconvt_kernel<<<dim3(FF / 32, E_ / 32), cb>>>(W1 + (size_t)l * E_ * FF,
            pwthi + OFF_W1(l), pwtlo + OFF_W1(l), E_, FF);
        gemm_tc_kernel<<<gW1, 256, GEMM_SMEM>>>(phhi, phlo,
            pwthi + OFF_W1(l), pwtlo + OFF_W1(l), nullptr, nullptr,
            nullptr, nullptr, nullptr, ppart, FF, E_, 384, 0);
        reduce_kernel<<<rF, 256>>>(ppart, 2, b1 + l * FF, pffhi, pfflo, FF);
        wconvt_kernel<<<dim3(E_ / 32, FF / 32), cb>>>(W2 + (size_t)l * FF * E_,
            pwthi + OFF_W2(l), pwtlo + OFF_W2(l), FF, E_);
        gemm_tc_kernel<<<gW2, 256, GEMM_SMEM>>>(pffhi, pfflo,
            pwthi + OFF_W2(l), pwtlo + OFF_W2(l), nullptr, nullptr,
            nullptr, nullptr, nullptr, ppart, E_, FF, 1024, 0);
        if (l < L_ - 1)
            reduce_ln_kernel<0><<<BT, 256>>>(ppart, 3, b2 + l * E_, px,
                                             ln1g + (l + 1) * E_, ln1b + (l + 1) * E_, phhi, phlo);
        else
            reduce_ln_kernel<1><<<BT, 256>>>(ppart, 3, b2 + l * E_, px,
                                             lnfg, lnfb, phhi, phlo);
    }
    wconvt_lm_kernel<<<dim3(V_ / 32, E_ / 32), cb>>>(Wlm, pwlmh);
    gemm_lm_kernel<<<gVd, 256, GEMM_LM_SMEM>>>(phhi, phlo, pwlmh, blm, logits);

    // --- loss ---
    float* loss_dst = nullptr;
    if (out_size == 1)        loss_dst = out;
    else if (out_size > NLOG) loss_dst = out + NLOG;
    if (loss_dst) {
        row_lse_kernel<<<BT, 256>>>(logits, targets, prl);
        loss_reduce_kernel<<<1, 256>>>(prl, loss_dst);
    }
}

// round 9
// speedup vs baseline: 3.3800x; 1.3887x over previous
#include <cuda_runtime.h>
#include <cuda_bf16.h>
#include <cuda_fp16.h>
#include <math.h>
#include <stdint.h>

#define L_  4
#define H_  12
#define E_  768
#define HS_ 64
#define V_  32000
#define B_  2
#define T_  1024
#define BT  2048
#define FF  3072
#define NQKV 2304

// ---- weight scratch offsets (elements) ----
#define WPL 7077888ull
#define OFF_QKV(l) ((size_t)(l) * WPL)
#define OFF_O(l)   (OFF_QKV(l) + 1769472ull)
#define OFF_W1(l)  (OFF_QKV(l) + 2359296ull)
#define OFF_W2(l)  (OFF_QKV(l) + 4718592ull)
#define OFF_LM     ((size_t)4 * WPL)
#define WTOT       (OFF_LM + 24576000ull)

// ---------------- scratch (static device globals) ----------------------------
__device__ float g_x[BT * E_];
__device__ __nv_bfloat16 g_qkvhi[BT * NQKV];
__device__ __nv_bfloat16 g_qkvlo[BT * NQKV];
__device__ __nv_bfloat16 g_hhi[BT * E_];
__device__ __nv_bfloat16 g_hlo[BT * E_];
__device__ __nv_bfloat16 g_ohi[BT * E_];
__device__ __nv_bfloat16 g_olo[BT * E_];
__device__ __nv_bfloat16 g_ffhi[BT * FF];
__device__ __nv_bfloat16 g_fflo[BT * FF];
__device__ float g_bqkv[L_ * NQKV];
__device__ float g_part[2ull * BT * FF];
__device__ __nv_bfloat16 g_wthi[WTOT];
__device__ __nv_bfloat16 g_wtlo[WTOT];
__device__ __half g_wlmh[(size_t)V_ * E_];
__device__ float g_rowloss[BT];
__device__ float g_logits_scratch[(size_t)BT * V_];

// ---------------- PTX helpers ------------------------------------------------
__device__ __forceinline__ uint32_t smem_u32(const void* p) {
    uint32_t a;
    asm("{ .reg .u64 t; cvta.to.shared.u64 t, %1; cvt.u32.u64 %0, t; }" : "=r"(a) : "l"(p));
    return a;
}
__device__ __forceinline__ void mma16816(float* c, const uint32_t* a, uint32_t b0, uint32_t b1) {
    asm volatile(
        "mma.sync.aligned.m16n8k16.row.col.f32.bf16.bf16.f32 "
        "{%0,%1,%2,%3}, {%4,%5,%6,%7}, {%8,%9}, {%0,%1,%2,%3};"
        : "+f"(c[0]), "+f"(c[1]), "+f"(c[2]), "+f"(c[3])
        : "r"(a[0]), "r"(a[1]), "r"(a[2]), "r"(a[3]), "r"(b0), "r"(b1));
}
__device__ __forceinline__ void mma16816h(float* c, const uint32_t* a, uint32_t b0, uint32_t b1) {
    asm volatile(
        "mma.sync.aligned.m16n8k16.row.col.f32.f16.f16.f32 "
        "{%0,%1,%2,%3}, {%4,%5,%6,%7}, {%8,%9}, {%0,%1,%2,%3};"
        : "+f"(c[0]), "+f"(c[1]), "+f"(c[2]), "+f"(c[3])
        : "r"(a[0]), "r"(a[1]), "r"(a[2]), "r"(a[3]), "r"(b0), "r"(b1));
}
__device__ __forceinline__ void ldsm4(uint32_t* r, uint32_t addr) {
    asm volatile("ldmatrix.sync.aligned.m8n8.x4.shared.b16 {%0,%1,%2,%3}, [%4];"
                 : "=r"(r[0]), "=r"(r[1]), "=r"(r[2]), "=r"(r[3]) : "r"(addr));
}
__device__ __forceinline__ void cpasync16(uint32_t dst, const void* src) {
    asm volatile("cp.async.cg.shared.global [%0], [%1], 16;" :: "r"(dst), "l"(src));
}

// ---------------- fused QKV weight repack+transpose+split + bias concat ------
__global__ __launch_bounds__(256) void wconv_qkv_kernel(const float* __restrict__ Wq,
                                                        const float* __restrict__ Wk,
                                                        const float* __restrict__ Wv,
                                                        const float* __restrict__ bq,
                                                        const float* __restrict__ bk,
                                                        const float* __restrict__ bv,
                                                        __nv_bfloat16* __restrict__ Whi,
                                                        __nv_bfloat16* __restrict__ Wlo,
                                                        float* __restrict__ bqkv,
                                                        int l) {
    __shared__ float s[32][33];
    int n0 = blockIdx.y * 32, e0 = blockIdx.x * 32;
    int tx = threadIdx.x, ty = threadIdx.y;
    int sel = n0 / E_;
    int nn = n0 % E_;
    int h = nn >> 6, hs0 = nn & 63;
    const float* src = sel == 0 ? Wq : (sel == 1 ? Wk : Wv);
    const float* base = src + ((size_t)(l * H_ + h) * E_) * 64;
#pragma unroll
    for (int i = 0; i < 4; i++) {
        int e = ty + 8 * i;
        s[e][tx] = base[(size_t)(e0 + e) * 64 + hs0 + tx];
    }
    __syncthreads();
#pragma unroll
    for (int i = 0; i < 4; i++) {
        int nl = ty + 8 * i;
        float x = s[tx][nl];
        __nv_bfloat16 hh = __float2bfloat16(x);
        __nv_bfloat16 ll = __float2bfloat16(x - __bfloat162float(hh));
        size_t oi = (size_t)(n0 + nl) * E_ + e0 + tx;
        Whi[oi] = hh;
        Wlo[oi] = ll;
    }
    int gid = (blockIdx.y * gridDim.x + blockIdx.x) * 256 + ty * 32 + tx;
    if (gid < NQKV) {
        float v;
        if (gid < E_)            v = bq[l * E_ + gid];
        else if (gid < 2 * E_)   v = bk[l * E_ + gid - E_];
        else                     v = bv[l * E_ + gid - 2 * E_];
        bqkv[l * NQKV + gid] = v;
    }
}

// ---------------- weight transpose + bf16 hi/lo split ------------------------
__global__ __launch_bounds__(256) void wconvt_kernel(const float* __restrict__ W,
                                                     __nv_bfloat16* __restrict__ Whi,
                                                     __nv_bfloat16* __restrict__ Wlo,
                                                     int K, int N) {
    __shared__ float s[32][33];
    int k0 = blockIdx.y * 32, n0 = blockIdx.x * 32;
    int tx = threadIdx.x, ty = threadIdx.y;
#pragma unroll
    for (int i = 0; i < 4; i++)
        s[ty + 8 * i][tx] = W[(size_t)(k0 + ty + 8 * i) * N + n0 + tx];
    __syncthreads();
#pragma unroll
    for (int i = 0; i < 4; i++) {
        int n = ty + 8 * i;
        float x = s[tx][n];
        __nv_bfloat16 h = __float2bfloat16(x);
        __nv_bfloat16 l = __float2bfloat16(x - __bfloat162float(h));
        size_t oi = (size_t)(n0 + n) * K + k0 + tx;
        Whi[oi] = h;
        Wlo[oi] = l;
    }
}

// ---------------- LM weight transpose -> single fp16 -------------------------
__global__ __launch_bounds__(256) void wconvt_lm_kernel(const float* __restrict__ W,
                                                        __half* __restrict__ Wt) {
    __shared__ float s[32][33];
    int k0 = blockIdx.y * 32, n0 = blockIdx.x * 32;
    int tx = threadIdx.x, ty = threadIdx.y;
#pragma unroll
    for (int i = 0; i < 4; i++)
        s[ty + 8 * i][tx] = W[(size_t)(k0 + ty + 8 * i) * V_ + n0 + tx];
    __syncthreads();
#pragma unroll
    for (int i = 0; i < 4; i++) {
        int n = ty + 8 * i;
        Wt[(size_t)(n0 + n) * E_ + k0 + tx] = __float2half_rn(s[tx][n]);
    }
}

// ---------------- fused embedding + layernorm -> bf16 hi/lo -------------------
__global__ __launch_bounds__(256) void embed_ln_kernel(const int* __restrict__ idx,
                                                       const float* __restrict__ tok,
                                                       const float* __restrict__ pos,
                                                       const float* __restrict__ g,
                                                       const float* __restrict__ b,
                                                       float* __restrict__ x,
                                                       __nv_bfloat16* __restrict__ hi,
                                                       __nv_bfloat16* __restrict__ lo) {
    int row = blockIdx.x;
    int tid = threadIdx.x;
    int token = idx[row];
    int tp = row % T_;
    size_t rb = (size_t)row * E_;
    float v[3], s = 0.f, sq = 0.f;
#pragma unroll
    for (int i = 0; i < 3; i++) {
        int e = tid + (i << 8);
        float t = tok[(size_t)token * E_ + e] + pos[(size_t)tp * E_ + e];
        x[rb + e] = t;
        v[i] = t; s += t; sq += t * t;
    }
#pragma unroll
    for (int o = 16; o > 0; o >>= 1) {
        s  += __shfl_xor_sync(0xffffffffu, s, o);
        sq += __shfl_xor_sync(0xffffffffu, sq, o);
    }
    __shared__ float ss[8], ssq[8];
    if ((tid & 31) == 0) { ss[tid >> 5] = s; ssq[tid >> 5] = sq; }
    __syncthreads();
    s = 0.f; sq = 0.f;
#pragma unroll
    for (int i = 0; i < 8; i++) { s += ss[i]; sq += ssq[i]; }
    float mean = s * (1.f / E_);
    float var  = sq * (1.f / E_) - mean * mean;
    float rstd = rsqrtf(var + 1e-5f);
#pragma unroll
    for (int i = 0; i < 3; i++) {
        int e = tid + (i << 8);
        float y = (v[i] - mean) * rstd * g[e] + b[e];
        __nv_bfloat16 h = __float2bfloat16(y);
        hi[rb + e] = h;
        lo[rb + e] = __float2bfloat16(y - __bfloat162float(h));
    }
}

// ---------------- fused split-K reduce + residual + layernorm ----------------
template<int FP16>
__global__ __launch_bounds__(256) void reduce_ln_kernel(const float* __restrict__ parts,
                                                        int nsplit,
                                                        const float* __restrict__ bias,
                                                        float* __restrict__ x,
                                                        const float* __restrict__ g,
                                                        const float* __restrict__ b,
                                                        __nv_bfloat16* __restrict__ hi,
                                                        __nv_bfloat16* __restrict__ lo) {
    int row = blockIdx.x, tid = threadIdx.x;
    size_t rb = (size_t)row * E_;
    const size_t plane = (size_t)BT * E_;
    float v[3], s = 0.f, sq = 0.f;
#pragma unroll
    for (int i = 0; i < 3; i++) {
        int e = tid + (i << 8);
        size_t ix = rb + e;
        float t = parts[ix];
        for (int p = 1; p < nsplit; p++) t += parts[plane * p + ix];
        t += bias[e] + x[ix];
        x[ix] = t;
        v[i] = t; s += t; sq += t * t;
    }
#pragma unroll
    for (int o = 16; o > 0; o >>= 1) {
        s  += __shfl_xor_sync(0xffffffffu, s, o);
        sq += __shfl_xor_sync(0xffffffffu, sq, o);
    }
    __shared__ float ss[8], ssq[8];
    if ((tid & 31) == 0) { ss[tid >> 5] = s; ssq[tid >> 5] = sq; }
    __syncthreads();
    s = 0.f; sq = 0.f;
#pragma unroll
    for (int i = 0; i < 8; i++) { s += ss[i]; sq += ssq[i]; }
    float mean = s * (1.f / E_);
    float var  = sq * (1.f / E_) - mean * mean;
    float rstd = rsqrtf(var + 1e-5f);
#pragma unroll
    for (int i = 0; i < 3; i++) {
        int e = tid + (i << 8);
        float y = (v[i] - mean) * rstd * g[e] + b[e];
        if (FP16) {
            __half h = __float2half_rn(y);
            __half l2 = __float2half_rn(y - __half2float(h));
            *(unsigned short*)&hi[rb + e] = *(unsigned short*)&h;
            *(unsigned short*)&lo[rb + e] = *(unsigned short*)&l2;
        } else {
            __nv_bfloat16 h = __float2bfloat16(y);
            hi[rb + e] = h;
            lo[rb + e] = __float2bfloat16(y - __bfloat162float(h));
        }
    }
}

// ---------------- tensor-core GEMM (bf16 hi/lo, 3-sweep, 3 stages) -----------
#define STG3 32768
#define GEMM_SMEM (3 * STG3)
__global__ __launch_bounds__(256, 2)
void gemm_tc_kernel(const __nv_bfloat16* __restrict__ Ahi,
                    const __nv_bfloat16* __restrict__ Alo,
                    const __nv_bfloat16* __restrict__ Bhi,
                    const __nv_bfloat16* __restrict__ Blo,
                    const float* __restrict__ bias,
                    const float* __restrict__ resid,
                    float* __restrict__ C,
                    __nv_bfloat16* __restrict__ Chi,
                    __nv_bfloat16* __restrict__ Clo,
                    float* __restrict__ Cpart,
                    int N, int K, int kslen, int relu) {
    extern __shared__ __align__(16) char smem[];
    int tid = threadIdx.x, lane = tid & 31, wid = tid >> 5;
    int wm = wid >> 2, wn = wid & 3;
    int row0 = blockIdx.y << 7, col0 = blockIdx.x << 7;
    int k0base = blockIdx.z * kslen;
    uint32_t sb = smem_u32(smem);

    float acc[4][4][4] = {};

    const int nCh = kslen >> 5;
    int frow = tid >> 1;
    int fc0 = (tid & 1) << 1;
    uint32_t fsw = (uint32_t)((frow >> 1) & 3);

    auto loadStage = [&](int stg, int c) {
        if (c < nCh) {
            uint32_t st = sb + stg * STG3;
            int k0 = k0base + (c << 5);
            size_t abase = (size_t)(row0 + frow) * K + k0;
            size_t bbase = (size_t)(col0 + frow) * K + k0;
#pragma unroll
            for (int cc = 0; cc < 2; cc++) {
                int cl = fc0 + cc;
                uint32_t doff = (uint32_t)(frow << 6) + (((uint32_t)cl ^ fsw) << 4);
                cpasync16(st + doff,         Ahi + abase + (cl << 3));
                cpasync16(st + 8192 + doff,  Alo + abase + (cl << 3));
                cpasync16(st + 16384 + doff, Bhi + bbase + (cl << 3));
                cpasync16(st + 24576 + doff, Blo + bbase + (cl << 3));
            }
        }
        asm volatile("cp.async.commit_group;" ::: "memory");
    };

    int arow[4], brow[2];
    uint32_t asw[4], bsw[2];
#pragma unroll
    for (int mf = 0; mf < 4; mf++) {
        arow[mf] = (wm << 6) + (mf << 4) + (lane & 15);
        asw[mf] = (uint32_t)((arow[mf] >> 1) & 3);
    }
#pragma unroll
    for (int g = 0; g < 2; g++) {
        brow[g] = (wn << 5) + (g << 4) + (lane & 7) + (((lane >> 3) & 1) << 3);
        bsw[g] = (uint32_t)((brow[g] >> 1) & 3);
    }
    int kc = lane >> 4;

    loadStage(0, 0);
    loadStage(1, 1);

    int stg = 0;
    for (int c = 0; c < nCh; ++c) {
        asm volatile("cp.async.wait_group 1;" ::: "memory");
        __syncthreads();
        loadStage(stg == 0 ? 2 : stg - 1, c + 2);
        uint32_t st = sb + stg * STG3;
#pragma unroll
        for (int ks = 0; ks < 2; ks++) {
            int cl = (ks << 1) + kc;
            uint32_t ah[4][4], bh[2][4];
#pragma unroll
            for (int mf = 0; mf < 4; mf++)
                ldsm4(ah[mf], st + (uint32_t)(arow[mf] << 6) + (((uint32_t)cl ^ asw[mf]) << 4));
#pragma unroll
            for (int g = 0; g < 2; g++)
                ldsm4(bh[g], st + 16384 + (uint32_t)(brow[g] << 6) + (((uint32_t)cl ^ bsw[g]) << 4));
#pragma unroll
            for (int mf = 0; mf < 4; mf++)
#pragma unroll
                for (int nf = 0; nf < 4; nf++)
                    mma16816(acc[mf][nf], ah[mf], bh[nf >> 1][nf & 1], bh[nf >> 1][(nf & 1) + 2]);
            {
                uint32_t al[4][4];
#pragma unroll
                for (int mf = 0; mf < 4; mf++)
                    ldsm4(al[mf], st + 8192 + (uint32_t)(arow[mf] << 6) + (((uint32_t)cl ^ asw[mf]) << 4));
#pragma unroll
                for (int mf = 0; mf < 4; mf++)
#pragma unroll
                    for (int nf = 0; nf < 4; nf++)
                        mma16816(acc[mf][nf], al[mf], bh[nf >> 1][nf & 1], bh[nf >> 1][(nf & 1) + 2]);
            }
            {
                uint32_t bl[2][4];
#pragma unroll
                for (int g = 0; g < 2; g++)
                    ldsm4(bl[g], st + 24576 + (uint32_t)(brow[g] << 6) + (((uint32_t)cl ^ bsw[g]) << 4));
#pragma unroll
                for (int mf = 0; mf < 4; mf++)
#pragma unroll
                    for (int nf = 0; nf < 4; nf++)
                        mma16816(acc[mf][nf], ah[mf], bl[nf >> 1][nf & 1], bl[nf >> 1][(nf & 1) + 2]);
            }
        }
        stg = (stg == 2) ? 0 : stg + 1;
    }

    if (Cpart) {
        size_t plane = (size_t)blockIdx.z * (((size_t)gridDim.y << 7) * (size_t)N);
#pragma unroll
        for (int mf = 0; mf < 4; mf++) {
            int rbase = row0 + (wm << 6) + (mf << 4) + (lane >> 2);
#pragma unroll
            for (int nf = 0; nf < 4; nf++) {
                int cb = col0 + (wn << 5) + (nf << 3) + ((lane & 3) << 1);
#pragma unroll
                for (int half = 0; half < 2; half++) {
                    int r = rbase + (half << 3);
                    *(float2*)(Cpart + plane + (size_t)r * N + cb) =
                        make_float2(acc[mf][nf][half * 2], acc[mf][nf][half * 2 + 1]);
                }
            }
        }
        return;
    }
#pragma unroll
    for (int mf = 0; mf < 4; mf++) {
        int rbase = row0 + (wm << 6) + (mf << 4) + (lane >> 2);
#pragma unroll
        for (int nf = 0; nf < 4; nf++) {
            int cb = col0 + (wn << 5) + (nf << 3) + ((lane & 3) << 1);
            float b0 = bias ? bias[cb] : 0.f;
            float b1 = bias ? bias[cb + 1] : 0.f;
#pragma unroll
            for (int half = 0; half < 2; half++) {
                int r = rbase + (half << 3);
                float v0 = acc[mf][nf][half * 2 + 0] + b0;
                float v1 = acc[mf][nf][half * 2 + 1] + b1;
                size_t gi = (size_t)r * N + cb;
                if (relu) { v0 = fmaxf(v0, 0.f); v1 = fmaxf(v1, 0.f); }
                if (Chi) {
                    __nv_bfloat162 h = __floats2bfloat162_rn(v0, v1);
                    float2 hf = __bfloat1622float2(h);
                    __nv_bfloat162 l = __floats2bfloat162_rn(v0 - hf.x, v1 - hf.y);
                    *(__nv_bfloat162*)(Chi + gi) = h;
                    *(__nv_bfloat162*)(Clo + gi) = l;
                } else {
                    if (resid) { v0 += resid[gi]; v1 += resid[gi + 1]; }
                    *(float2*)(C + gi) = make_float2(v0, v1);
                }
            }
        }
    }
}

// ---------------- LM-head GEMM: fp16 2-sweep ---------------------------------
#define LSTG 24576
#define GEMM_LM_SMEM (3 * LSTG)
__global__ __launch_bounds__(256, 2)
void gemm_lm_kernel(const __nv_bfloat16* __restrict__ AhiB,
                    const __nv_bfloat16* __restrict__ AloB,
                    const __half* __restrict__ Bt,
                    const float* __restrict__ bias,
                    float* __restrict__ C) {
    extern __shared__ __align__(16) char smem[];
    const int N = V_, K = E_;
    int tid = threadIdx.x, lane = tid & 31, wid = tid >> 5;
    int wm = wid >> 2, wn = wid & 3;
    int row0 = blockIdx.y << 7, col0 = blockIdx.x << 7;
    uint32_t sb = smem_u32(smem);
    const __half* Ahi = (const __half*)AhiB;
    const __half* Alo = (const __half*)AloB;

    float acc[4][4][4] = {};
    const int nCh = K >> 5;
    int frow = tid >> 1;
    int fc0 = (tid & 1) << 1;
    uint32_t fsw = (uint32_t)((frow >> 1) & 3);

    auto loadStage = [&](int stg, int c) {
        if (c < nCh) {
            uint32_t st = sb + stg * LSTG;
            int k0 = c << 5;
            size_t abase = (size_t)(row0 + frow) * K + k0;
            size_t bbase = (size_t)(col0 + frow) * K + k0;
#pragma unroll
            for (int cc = 0; cc < 2; cc++) {
                int cl = fc0 + cc;
                uint32_t doff = (uint32_t)(frow << 6) + (((uint32_t)cl ^ fsw) << 4);
                cpasync16(st + doff,         Ahi + abase + (cl << 3));
                cpasync16(st + 8192 + doff,  Alo + abase + (cl << 3));
                cpasync16(st + 16384 + doff, Bt  + bbase + (cl << 3));
            }
        }
        asm volatile("cp.async.commit_group;" ::: "memory");
    };

    int arow[4], brow[2];
    uint32_t asw[4], bsw[2];
#pragma unroll
    for (int mf = 0; mf < 4; mf++) {
        arow[mf] = (wm << 6) + (mf << 4) + (lane & 15);
        asw[mf] = (uint32_t)((arow[mf] >> 1) & 3);
    }
#pragma unroll
    for (int g = 0; g < 2; g++) {
        brow[g] = (wn << 5) + (g << 4) + (lane & 7) + (((lane >> 3) & 1) << 3);
        bsw[g] = (uint32_t)((brow[g] >> 1) & 3);
    }
    int kc = lane >> 4;

    loadStage(0, 0);
    loadStage(1, 1);

    int stg = 0;
    for (int c = 0; c < nCh; ++c) {
        asm volatile("cp.async.wait_group 1;" ::: "memory");
        __syncthreads();
        loadStage(stg == 0 ? 2 : stg - 1, c + 2);
        uint32_t st = sb + stg * LSTG;
#pragma unroll
        for (int ks = 0; ks < 2; ks++) {
            int cl = (ks << 1) + kc;
            uint32_t ah[4][4], bb[2][4];
#pragma unroll
            for (int mf = 0; mf < 4; mf++)
                ldsm4(ah[mf], st + (uint32_t)(arow[mf] << 6) + (((uint32_t)cl ^ asw[mf]) << 4));
#pragma unroll
            for (int g = 0; g < 2; g++)
                ldsm4(bb[g], st + 16384 + (uint32_t)(brow[g] << 6) + (((uint32_t)cl ^ bsw[g]) << 4));
#pragma unroll
            for (int mf = 0; mf < 4; mf++)
#pragma unroll
                for (int nf = 0; nf < 4; nf++)
                    mma16816h(acc[mf][nf], ah[mf], bb[nf >> 1][nf & 1], bb[nf >> 1][(nf & 1) + 2]);
            {
                uint32_t al[4][4];
#pragma unroll
                for (int mf = 0; mf < 4; mf++)
                    ldsm4(al[mf], st + 8192 + (uint32_t)(arow[mf] << 6) + (((uint32_t)cl ^ asw[mf]) << 4));
#pragma unroll
                for (int mf = 0; mf < 4; mf++)
#pragma unroll
                    for (int nf = 0; nf < 4; nf++)
                        mma16816h(acc[mf][nf], al[mf], bb[nf >> 1][nf & 1], bb[nf >> 1][(nf & 1) + 2]);
            }
        }
        stg = (stg == 2) ? 0 : stg + 1;
    }
#pragma unroll
    for (int mf = 0; mf < 4; mf++) {
        int rbase = row0 + (wm << 6) + (mf << 4) + (lane >> 2);
#pragma unroll
        for (int nf = 0; nf < 4; nf++) {
            int cb = col0 + (wn << 5) + (nf << 3) + ((lane & 3) << 1);
            float b0 = bias[cb], b1 = bias[cb + 1];
#pragma unroll
            for (int half = 0; half < 2; half++) {
                int r = rbase + (half << 3);
                size_t gi = (size_t)r * N + cb;
                *(float2*)(C + gi) = make_float2(acc[mf][nf][half * 2] + b0,
                                                 acc[mf][nf][half * 2 + 1] + b1);
            }
        }
    }
}

// ---------------- split-K reduce (W1 path) -----------------------------------
__global__ __launch_bounds__(256) void reduce_kernel(const float* __restrict__ parts,
                                                     int nsplit,
                                                     const float* __restrict__ bias,
                                                     __nv_bfloat16* __restrict__ outHi,
                                                     __nv_bfloat16* __restrict__ outLo,
                                                     int N) {
    size_t i = ((size_t)blockIdx.x * 256 + threadIdx.x) * 4;
    size_t plane = (size_t)BT * N;
    int col = (int)(i % N);
    float4 s = *(const float4*)(parts + i);
    for (int p = 1; p < nsplit; p++) {
        float4 t = *(const float4*)(parts + plane * p + i);
        s.x += t.x; s.y += t.y; s.z += t.z; s.w += t.w;
    }
    float4 b = *(const float4*)(bias + col);
    s.x = fmaxf(s.x + b.x, 0.f); s.y = fmaxf(s.y + b.y, 0.f);
    s.z = fmaxf(s.z + b.z, 0.f); s.w = fmaxf(s.w + b.w, 0.f);
    __nv_bfloat162 h0 = __floats2bfloat162_rn(s.x, s.y);
    __nv_bfloat162 h1 = __floats2bfloat162_rn(s.z, s.w);
    float2 f0 = __bfloat1622float2(h0), f1 = __bfloat1622float2(h1);
    __nv_bfloat162 l0 = __floats2bfloat162_rn(s.x - f0.x, s.y - f0.y);
    __nv_bfloat162 l1 = __floats2bfloat162_rn(s.z - f1.x, s.w - f1.y);
    *(__nv_bfloat162*)(outHi + i) = h0;
    *(__nv_bfloat162*)(outHi + i + 2) = h1;
    *(__nv_bfloat162*)(outLo + i) = l0;
    *(__nv_bfloat162*)(outLo + i + 2) = l1;
}

// ---------------- tensor-core flash attention --------------------------------
// 128 threads / 4 warps; warp w owns q-rows [16w,16w+16). bf16 hi/lo 3-sweep
// for both QK^T and PV. smem tiles 64x64 bf16: row=128B, 8 chunks, swizzle
// phys_chunk = c ^ (row&7) (proven conflict-free ldsm4 pattern).
#define ATT_SMEM 49152
__global__ __launch_bounds__(128)
void attn_kernel(const __nv_bfloat16* __restrict__ qkvhi,
                 const __nv_bfloat16* __restrict__ qkvlo,
                 __nv_bfloat16* __restrict__ ohi,
                 __nv_bfloat16* __restrict__ olo) {
    extern __shared__ __align__(16) char smem[];
    uint32_t sb = smem_u32(smem);
    const uint32_t Q_HI = 0, Q_LO = 8192, K_HI = 16384, K_LO = 24576,
                   VT_HI = 32768, VT_LO = 40960;
    int tid = threadIdx.x, lane = tid & 31, w = tid >> 5;
    int qt = (int)gridDim.x - 1 - (int)blockIdx.x;   // heavy tiles first
    int bh = blockIdx.y;
    int bb = bh / H_, hh = bh % H_;
    size_t qrowbase = (size_t)(bb * T_ + (qt << 6));
    const int coff = hh * 64;
    int kc = lane >> 4;

    // ---- load Q tile hi/lo ----
    {
        int r0 = tid >> 1;
        int c0 = (tid & 1) << 2;
        size_t g = (qrowbase + r0) * (size_t)NQKV + coff;
#pragma unroll
        for (int i = 0; i < 4; i++) {
            int c = c0 + i;
            uint32_t d = (uint32_t)(r0 << 7) + (((uint32_t)(c ^ (r0 & 7))) << 4);
            cpasync16(sb + Q_HI + d, qkvhi + g + (c << 3));
            cpasync16(sb + Q_LO + d, qkvlo + g + (c << 3));
        }
        asm volatile("cp.async.commit_group;\n\tcp.async.wait_group 0;" ::: "memory");
    }
    __syncthreads();
    // preload Q a-frags (held across all kv tiles)
    uint32_t qh[4][4], ql[4][4];
    {
        int aRow = (w << 4) + (lane & 15);
#pragma unroll
        for (int ks = 0; ks < 4; ks++) {
            int cl = (ks << 1) + kc;
            uint32_t ad = (uint32_t)(aRow << 7) + (((uint32_t)(cl ^ (aRow & 7))) << 4);
            ldsm4(qh[ks], sb + Q_HI + ad);
            ldsm4(ql[ks], sb + Q_LO + ad);
        }
    }

    float oacc[8][4] = {};
    float m1 = -INFINITY, m2 = -INFINITY, l1 = 0.f, l2 = 0.f;
    int r1 = lane >> 2;
    int rowg1 = (qt << 6) + (w << 4) + r1;
    int rowg2 = rowg1 + 8;

    for (int kt = 0; kt <= qt; kt++) {
        __syncthreads();   // prior tile consumers done
        size_t kbase = (size_t)(bb * T_ + (kt << 6));
        // K fill (cp.async)
        {
            int r0 = tid >> 1;
            int c0 = (tid & 1) << 2;
            size_t g = (kbase + r0) * (size_t)NQKV + E_ + coff;
#pragma unroll
            for (int i = 0; i < 4; i++) {
                int c = c0 + i;
                uint32_t d = (uint32_t)(r0 << 7) + (((uint32_t)(c ^ (r0 & 7))) << 4);
                cpasync16(sb + K_HI + d, qkvhi + g + (c << 3));
                cpasync16(sb + K_LO + d, qkvlo + g + (c << 3));
            }
            asm volatile("cp.async.commit_group;" ::: "memory");
        }
        // Vt fill (transpose through registers; conflict-free word stores)
        {
            int kvp = tid & 31;
            int dg0 = tid >> 5;
            int kv = kvp << 1;
#pragma unroll
            for (int t = 0; t < 2; t++) {
                int d0 = (dg0 + (t << 2)) << 3;
                size_t g0 = (kbase + kv) * (size_t)NQKV + 2 * E_ + coff + d0;
                uint4 h0 = *(const uint4*)(qkvhi + g0);
                uint4 h1 = *(const uint4*)(qkvhi + g0 + NQKV);
                uint4 l0 = *(const uint4*)(qkvlo + g0);
                uint4 l1 = *(const uint4*)(qkvlo + g0 + NQKV);
                const __nv_bfloat16* ph0 = (const __nv_bfloat16*)&h0;
                const __nv_bfloat16* ph1 = (const __nv_bfloat16*)&h1;
                const __nv_bfloat16* pl0 = (const __nv_bfloat16*)&l0;
                const __nv_bfloat16* pl1 = (const __nv_bfloat16*)&l1;
#pragma unroll
                for (int j = 0; j < 8; j++) {
                    int d = d0 + j;
                    uint32_t ad = (uint32_t)(d << 7) +
                                  ((((uint32_t)(kvp >> 2) ^ (uint32_t)(d & 7)) << 4)) +
                                  ((uint32_t)(kvp & 3) << 2);
                    __nv_bfloat162 hw; hw.x = ph0[j]; hw.y = ph1[j];
                    __nv_bfloat162 lw; lw.x = pl0[j]; lw.y = pl1[j];
                    *(__nv_bfloat162*)(smem + VT_HI + ad) = hw;
                    *(__nv_bfloat162*)(smem + VT_LO + ad) = lw;
                }
            }
        }
        asm volatile("cp.async.wait_group 0;" ::: "memory");
        __syncthreads();

        // ---- S = Q K^T (3-sweep) ----
        float sacc[8][4] = {};
#pragma unroll
        for (int ks = 0; ks < 4; ks++) {
            int cl = (ks << 1) + kc;
            uint32_t kh[4][4], kl2[4][4];
#pragma unroll
            for (int g = 0; g < 4; g++) {
                int bRow = (g << 4) + (lane & 7) + (((lane >> 3) & 1) << 3);
                uint32_t bd = (uint32_t)(bRow << 7) + (((uint32_t)(cl ^ (bRow & 7))) << 4);
                ldsm4(kh[g], sb + K_HI + bd);
                ldsm4(kl2[g], sb + K_LO + bd);
            }
#pragma unroll
            for (int g = 0; g < 4; g++)
#pragma unroll
                for (int nfp = 0; nfp < 2; nfp++)
                    mma16816(sacc[2 * g + nfp], qh[ks], kh[g][nfp], kh[g][nfp + 2]);
#pragma unroll
            for (int g = 0; g < 4; g++)
#pragma unroll
                for (int nfp = 0; nfp < 2; nfp++)
                    mma16816(sacc[2 * g + nfp], ql[ks], kh[g][nfp], kh[g][nfp + 2]);
#pragma unroll
            for (int g = 0; g < 4; g++)
#pragma unroll
                for (int nfp = 0; nfp < 2; nfp++)
                    mma16816(sacc[2 * g + nfp], qh[ks], kl2[g][nfp], kl2[g][nfp + 2]);
        }
        // ---- scale + causal mask ----
#pragma unroll
        for (int nf = 0; nf < 8; nf++) {
            sacc[nf][0] *= 0.125f; sacc[nf][1] *= 0.125f;
            sacc[nf][2] *= 0.125f; sacc[nf][3] *= 0.125f;
        }
        if (kt == qt) {
#pragma unroll
            for (int nf = 0; nf < 8; nf++) {
                int colb = (kt << 6) + (nf << 3) + ((lane & 3) << 1);
                if (colb > rowg1)     sacc[nf][0] = -INFINITY;
                if (colb + 1 > rowg1) sacc[nf][1] = -INFINITY;
                if (colb > rowg2)     sacc[nf][2] = -INFINITY;
                if (colb + 1 > rowg2) sacc[nf][3] = -INFINITY;
            }
        }
        // ---- online softmax (rows r1, r2) ----
        float t1 = -INFINITY, t2 = -INFINITY;
#pragma unroll
        for (int nf = 0; nf < 8; nf++) {
            t1 = fmaxf(t1, fmaxf(sacc[nf][0], sacc[nf][1]));
            t2 = fmaxf(t2, fmaxf(sacc[nf][2], sacc[nf][3]));
        }
        t1 = fmaxf(t1, __shfl_xor_sync(0xffffffffu, t1, 1));
        t1 = fmaxf(t1, __shfl_xor_sync(0xffffffffu, t1, 2));
        t2 = fmaxf(t2, __shfl_xor_sync(0xffffffffu, t2, 1));
        t2 = fmaxf(t2, __shfl_xor_sync(0xffffffffu, t2, 2));
        float mn1 = fmaxf(m1, t1), mn2 = fmaxf(m2, t2);
        float a1 = __expf(m1 - mn1), a2 = __expf(m2 - mn2);
        float ps1 = 0.f, ps2 = 0.f;
#pragma unroll
        for (int nf = 0; nf < 8; nf++) {
            sacc[nf][0] = __expf(sacc[nf][0] - mn1);
            sacc[nf][1] = __expf(sacc[nf][1] - mn1);
            sacc[nf][2] = __expf(sacc[nf][2] - mn2);
            sacc[nf][3] = __expf(sacc[nf][3] - mn2);
            ps1 += sacc[nf][0] + sacc[nf][1];
            ps2 += sacc[nf][2] + sacc[nf][3];
        }
        ps1 += __shfl_xor_sync(0xffffffffu, ps1, 1);
        ps1 += __shfl_xor_sync(0xffffffffu, ps1, 2);
        ps2 += __shfl_xor_sync(0xffffffffu, ps2, 1);
        ps2 += __shfl_xor_sync(0xffffffffu, ps2, 2);
        l1 = l1 * a1 + ps1;
        l2 = l2 * a2 + ps2;
        m1 = mn1; m2 = mn2;
#pragma unroll
        for (int nf = 0; nf < 8; nf++) {
            oacc[nf][0] *= a1; oacc[nf][1] *= a1;
            oacc[nf][2] *= a2; oacc[nf][3] *= a2;
        }
        // ---- O += P V (3-sweep); P c-frags -> a-frags in regs ----
#pragma unroll
        for (int j = 0; j < 4; j++) {
            uint32_t pah[4], pal[4];
#pragma unroll
            for (int half = 0; half < 2; half++) {      // half 0: sacc[2j], half 1: sacc[2j+1]
                float x0 = sacc[2 * j + half][0], x1 = sacc[2 * j + half][1];
                float x2 = sacc[2 * j + half][2], x3 = sacc[2 * j + half][3];
                __nv_bfloat162 h01 = __floats2bfloat162_rn(x0, x1);
                __nv_bfloat162 h23 = __floats2bfloat162_rn(x2, x3);
                float2 f01 = __bfloat1622float2(h01), f23 = __bfloat1622float2(h23);
                __nv_bfloat162 lo01 = __floats2bfloat162_rn(x0 - f01.x, x1 - f01.y);
                __nv_bfloat162 lo23 = __floats2bfloat162_rn(x2 - f23.x, x3 - f23.y);
                pah[2 * half + 0] = *(uint32_t*)&h01;
                pah[2 * half + 1] = *(uint32_t*)&h23;
                pal[2 * half + 0] = *(uint32_t*)&lo01;
                pal[2 * half + 1] = *(uint32_t*)&lo23;
            }
            int cl = (j << 1) + kc;
            uint32_t vh[4][4], vl[4][4];
#pragma unroll
            for (int g = 0; g < 4; g++) {
                int bRow = (g << 4) + (lane & 7) + (((lane >> 3) & 1) << 3);
                uint32_t bd = (uint32_t)(bRow << 7) + (((uint32_t)(cl ^ (bRow & 7))) << 4);
                ldsm4(vh[g], sb + VT_HI + bd);
                ldsm4(vl[g], sb + VT_LO + bd);
            }
#pragma unroll
            for (int g = 0; g < 4; g++)
#pragma unroll
                for (int nfp = 0; nfp < 2; nfp++)
                    mma16816(oacc[2 * g + nfp], pah, vh[g][nfp], vh[g][nfp + 2]);
#pragma unroll
            for (int g = 0; g < 4; g++)
#pragma unroll
                for (int nfp = 0; nfp < 2; nfp++)
                    mma16816(oacc[2 * g + nfp], pal, vh[g][nfp], vh[g][nfp + 2]);
#pragma unroll
            for (int g = 0; g < 4; g++)
#pragma unroll
                for (int nfp = 0; nfp < 2; nfp++)
                    mma16816(oacc[2 * g + nfp], pah, vl[g][nfp], vl[g][nfp + 2]);
        }
    }

    // ---- output (bf16 hi/lo) ----
    float li1 = 1.f / l1, li2 = 1.f / l2;
    size_t ob1 = (qrowbase + (w << 4) + r1) * (size_t)E_ + coff;
    size_t ob2 = ob1 + (size_t)8 * E_;
#pragma unroll
    for (int nf = 0; nf < 8; nf++) {
        int d = (nf << 3) + ((lane & 3) << 1);
        float v0 = oacc[nf][0] * li1, v1 = oacc[nf][1] * li1;
        __nv_bfloat162 h = __floats2bfloat162_rn(v0, v1);
        float2 hf = __bfloat1622float2(h);
        __nv_bfloat162 lo = __floats2bfloat162_rn(v0 - hf.x, v1 - hf.y);
        *(__nv_bfloat162*)(ohi + ob1 + d) = h;
        *(__nv_bfloat162*)(olo + ob1 + d) = lo;
        float v2 = oacc[nf][2] * li2, v3 = oacc[nf][3] * li2;
        __nv_bfloat162 h2 = __floats2bfloat162_rn(v2, v3);
        float2 hf2 = __bfloat1622float2(h2);
        __nv_bfloat162 lo2 = __floats2bfloat162_rn(v2 - hf2.x, v3 - hf2.y);
        *(__nv_bfloat162*)(ohi + ob2 + d) = h2;
        *(__nv_bfloat162*)(olo + ob2 + d) = lo2;
    }
}

// ---------------- loss ------------------------------------------------------
__global__ __launch_bounds__(256) void row_lse_kernel(const float* __restrict__ logits,
                                                      const int* __restrict__ targets,
                                                      float* __restrict__ rowloss) {
    int row = blockIdx.x, tid = threadIdx.x;
    const float* lr = logits + (size_t)row * V_;
    float mx = -INFINITY;
    for (int i = tid; i < V_; i += 256) mx = fmaxf(mx, lr[i]);
#pragma unroll
    for (int o = 16; o > 0; o >>= 1) mx = fmaxf(mx, __shfl_xor_sync(0xffffffffu, mx, o));
    __shared__ float sm[8];
    if ((tid & 31) == 0) sm[tid >> 5] = mx;
    __syncthreads();
    float m2 = -INFINITY;
#pragma unroll
    for (int i = 0; i < 8; i++) m2 = fmaxf(m2, sm[i]);
    float se = 0.f;
    for (int i = tid; i < V_; i += 256) se += __expf(lr[i] - m2);
#pragma unroll
    for (int o = 16; o > 0; o >>= 1) se += __shfl_xor_sync(0xffffffffu, se, o);
    __shared__ float ssum[8];
    if ((tid & 31) == 0) ssum[tid >> 5] = se;
    __syncthreads();
    if (tid == 0) {
        float tot = 0.f;
#pragma unroll
        for (int i = 0; i < 8; i++) tot += ssum[i];
        rowloss[row] = (logf(tot) + m2) - lr[targets[row]];
    }
}

__global__ __launch_bounds__(256) void loss_reduce_kernel(const float* __restrict__ rowloss,
                                                          float* __restrict__ out) {
    int tid = threadIdx.x;
    float s = 0.f;
    for (int i = tid; i < BT; i += 256) s += rowloss[i];
#pragma unroll
    for (int o = 16; o > 0; o >>= 1) s += __shfl_xor_sync(0xffffffffu, s, o);
    __shared__ float sm[8];
    if ((tid & 31) == 0) sm[tid >> 5] = s;
    __syncthreads();
    if (tid == 0) {
        float t = 0.f;
#pragma unroll
        for (int i = 0; i < 8; i++) t += sm[i];
        out[0] = t * (1.f / BT);
    }
}

// ---------------- launch ----------------------------------------------------
extern "C" void kernel_launch(void* const* d_in, const int* in_sizes, int n_in,
                              void* d_out, int out_size) {
    const int*   idx     = (const int*)d_in[0];
    const int*   targets = (const int*)d_in[1];
    const float* tok_emb = (const float*)d_in[2];
    const float* pos_emb = (const float*)d_in[3];
    const float* Wq  = (const float*)d_in[4];
    const float* bq  = (const float*)d_in[5];
    const float* Wk  = (const float*)d_in[6];
    const float* bk  = (const float*)d_in[7];
    const float* Wv  = (const float*)d_in[8];
    const float* bv  = (const float*)d_in[9];
    const float* Wo  = (const float*)d_in[10];
    const float* bo  = (const float*)d_in[11];
    const float* ln1g = (const float*)d_in[12];
    const float* ln1b = (const float*)d_in[13];
    const float* W1  = (const float*)d_in[14];
    const float* b1  = (const float*)d_in[15];
    const float* W2  = (const float*)d_in[16];
    const float* b2  = (const float*)d_in[17];
    const float* ln2g = (const float*)d_in[18];
    const float* ln2b = (const float*)d_in[19];
    const float* lnfg = (const float*)d_in[20];
    const float* lnfb = (const float*)d_in[21];
    const float* Wlm = (const float*)d_in[22];
    const float* blm = (const float*)d_in[23];
    float* out = (float*)d_out;

    float *px, *pbqkv, *ppart, *prl, *plg;
    __nv_bfloat16 *pqkvhi, *pqkvlo, *phhi, *phlo, *pohi, *polo, *pffhi, *pfflo, *pwthi, *pwtlo;
    __half *pwlmh;
    cudaGetSymbolAddress((void**)&px,     g_x);
    cudaGetSymbolAddress((void**)&pqkvhi, g_qkvhi);
    cudaGetSymbolAddress((void**)&pqkvlo, g_qkvlo);
    cudaGetSymbolAddress((void**)&phhi,   g_hhi);
    cudaGetSymbolAddress((void**)&phlo,   g_hlo);
    cudaGetSymbolAddress((void**)&pohi,   g_ohi);
    cudaGetSymbolAddress((void**)&polo,   g_olo);
    cudaGetSymbolAddress((void**)&pffhi,  g_ffhi);
    cudaGetSymbolAddress((void**)&pfflo,  g_fflo);
    cudaGetSymbolAddress((void**)&pbqkv,  g_bqkv);
    cudaGetSymbolAddress((void**)&ppart,  g_part);
    cudaGetSymbolAddress((void**)&pwthi,  g_wthi);
    cudaGetSymbolAddress((void**)&pwtlo,  g_wtlo);
    cudaGetSymbolAddress((void**)&pwlmh,  g_wlmh);
    cudaGetSymbolAddress((void**)&prl,    g_rowloss);
    cudaGetSymbolAddress((void**)&plg,    g_logits_scratch);

    cudaFuncSetAttribute(gemm_tc_kernel, cudaFuncAttributeMaxDynamicSharedMemorySize, GEMM_SMEM);
    cudaFuncSetAttribute(gemm_lm_kernel, cudaFuncAttributeMaxDynamicSharedMemorySize, GEMM_LM_SMEM);
    cudaFuncSetAttribute(attn_kernel,    cudaFuncAttributeMaxDynamicSharedMemorySize, ATT_SMEM);

    const long long NLOG = (long long)BT * V_;
    float* logits = (out_size >= NLOG) ? out : plg;

    dim3 cb(32, 8);
    dim3 gQKVw(E_ / 32, NQKV / 32);
    dim3 gQKV(NQKV / 128, BT / 128);
    dim3 gWo(E_ / 128, BT / 128, 3);
    dim3 gW1(FF / 128, BT / 128, 2);
    dim3 gW2(E_ / 128, BT / 128, 3);
    dim3 gVd(V_ / 128, BT / 128);
    dim3 gAttn(T_ / 64, B_ * H_);
    int rF = BT * FF / 1024;

    for (int l = 0; l < L_; l++) {
        size_t wel = (size_t)l * E_ * E_;
        if (l == 0)
            embed_ln_kernel<<<BT, 256>>>(idx, tok_emb, pos_emb, ln1g, ln1b, px, phhi, phlo); // 0
        wconv_qkv_kernel<<<gQKVw, cb>>>(Wq, Wk, Wv, bq, bk, bv,
                                        pwthi + OFF_QKV(l), pwtlo + OFF_QKV(l), pbqkv, l);  // 1
        gemm_tc_kernel<<<gQKV, 256, GEMM_SMEM>>>(phhi, phlo,                                // 2
            pwthi + OFF_QKV(l), pwtlo + OFF_QKV(l), pbqkv + l * NQKV, nullptr,
            nullptr, pqkvhi, pqkvlo, nullptr, NQKV, E_, E_, 0);
        attn_kernel<<<gAttn, 128, ATT_SMEM>>>(pqkvhi, pqkvlo, pohi, polo);                  // 3 (= global 5)
        wconvt_kernel<<<dim3(E_ / 32, E_ / 32), cb>>>(Wo + wel, pwthi + OFF_O(l), pwtlo + OFF_O(l), E_, E_);
        gemm_tc_kernel<<<gWo, 256, GEMM_SMEM>>>(pohi, polo,
            pwthi + OFF_O(l), pwtlo + OFF_O(l), nullptr, nullptr,
            nullptr, nullptr, nullptr, ppart, E_, E_, 256, 0);
        reduce_ln_kernel<0><<<BT, 256>>>(ppart, 3, bo + l * E_, px,
                                         ln2g + l * E_, ln2b + l * E_, phhi, phlo);
        wconvt_kernel<<<dim3(FF / 32, E_ / 32), cb>>>(W1 + (size_t)l * E_ * FF,
            pwthi + OFF_W1(l), pwtlo + OFF_W1(l), E_, FF);
        gemm_tc_kernel<<<gW1, 256, GEMM_SMEM>>>(phhi, phlo,
            pwthi + OFF_W1(l), pwtlo + OFF_W1(l), nullptr, nullptr,
            nullptr, nullptr, nullptr, ppart, FF, E_, 384, 0);
        reduce_kernel<<<rF, 256>>>(ppart, 2, b1 + l * FF, pffhi, pfflo, FF);
        wconvt_kernel<<<dim3(E_ / 32, FF / 32), cb>>>(W2 + (size_t)l * FF * E_,
            pwthi + OFF_W2(l), pwtlo + OFF_W2(l), FF, E_);
        gemm_tc_kernel<<<gW2, 256, GEMM_SMEM>>>(pffhi, pfflo,
            pwthi + OFF_W2(l), pwtlo + OFF_W2(l), nullptr, nullptr,
            nullptr, nullptr, nullptr, ppart, E_, FF, 1024, 0);
        if (l < L_ - 1)
            reduce_ln_kernel<0><<<BT, 256>>>(ppart, 3, b2 + l * E_, px,
                                             ln1g + (l + 1) * E_, ln1b + (l + 1) * E_, phhi, phlo);
        else
            reduce_ln_kernel<1><<<BT, 256>>>(ppart, 3, b2 + l * E_, px,
                                             lnfg, lnfb, phhi, phlo);
    }
    wconvt_lm_kernel<<<dim3(V_ / 32, E_ / 32), cb>>>(Wlm, pwlmh);
    gemm_lm_kernel<<<gVd, 256, GEMM_LM_SMEM>>>(phhi, phlo, pwlmh, blm, logits);

    // --- loss ---
    float* loss_dst = nullptr;
    if (out_size == 1)        loss_dst = out;
    else if (out_size > NLOG) loss_dst = out + NLOG;
    if (loss_dst) {
        row_lse_kernel<<<BT, 256>>>(logits, targets, prl);
        loss_reduce_kernel<<<1, 256>>>(prl, loss_dst);
    }
}

// round 10
// speedup vs baseline: 4.2070x; 1.2447x over previous
#include <cuda_runtime.h>
#include <cuda_bf16.h>
#include <cuda_fp16.h>
#include <math.h>
#include <stdint.h>

#define L_  4
#define H_  12
#define E_  768
#define HS_ 64
#define V_  32000
#define B_  2
#define T_  1024
#define BT  2048
#define FF  3072
#define NQKV 2304

// ---- weight scratch offsets (elements) ----
#define WPL 7077888ull
#define OFF_QKV(l) ((size_t)(l) * WPL)
#define OFF_O(l)   (OFF_QKV(l) + 1769472ull)
#define OFF_W1(l)  (OFF_QKV(l) + 2359296ull)
#define OFF_W2(l)  (OFF_QKV(l) + 4718592ull)
#define WTOT       ((size_t)4 * WPL)

// ---------------- scratch (static device globals) ----------------------------
__device__ float g_x[BT * E_];
__device__ __nv_bfloat16 g_qkvhi[BT * NQKV];
__device__ __nv_bfloat16 g_qkvlo[BT * NQKV];
__device__ __nv_bfloat16 g_hhi[BT * E_];
__device__ __nv_bfloat16 g_hlo[BT * E_];
__device__ __nv_bfloat16 g_ohi[BT * E_];
__device__ __nv_bfloat16 g_olo[BT * E_];
__device__ __nv_bfloat16 g_ffhi[BT * FF];
__device__ __nv_bfloat16 g_fflo[BT * FF];
__device__ float g_bqkv[L_ * NQKV];
__device__ float g_part[2ull * BT * FF];
__device__ __nv_bfloat16 g_wthi[WTOT];
__device__ __nv_bfloat16 g_wtlo[WTOT];
__device__ __half g_wlmh[(size_t)V_ * E_];
__device__ float g_rowloss[BT];
__device__ float g_logits_scratch[(size_t)BT * V_];

// ---------------- PTX helpers ------------------------------------------------
__device__ __forceinline__ uint32_t smem_u32(const void* p) {
    uint32_t a;
    asm("{ .reg .u64 t; cvta.to.shared.u64 t, %1; cvt.u32.u64 %0, t; }" : "=r"(a) : "l"(p));
    return a;
}
__device__ __forceinline__ void mma16816(float* c, const uint32_t* a, uint32_t b0, uint32_t b1) {
    asm volatile(
        "mma.sync.aligned.m16n8k16.row.col.f32.bf16.bf16.f32 "
        "{%0,%1,%2,%3}, {%4,%5,%6,%7}, {%8,%9}, {%0,%1,%2,%3};"
        : "+f"(c[0]), "+f"(c[1]), "+f"(c[2]), "+f"(c[3])
        : "r"(a[0]), "r"(a[1]), "r"(a[2]), "r"(a[3]), "r"(b0), "r"(b1));
}
__device__ __forceinline__ void mma16816h(float* c, const uint32_t* a, uint32_t b0, uint32_t b1) {
    asm volatile(
        "mma.sync.aligned.m16n8k16.row.col.f32.f16.f16.f32 "
        "{%0,%1,%2,%3}, {%4,%5,%6,%7}, {%8,%9}, {%0,%1,%2,%3};"
        : "+f"(c[0]), "+f"(c[1]), "+f"(c[2]), "+f"(c[3])
        : "r"(a[0]), "r"(a[1]), "r"(a[2]), "r"(a[3]), "r"(b0), "r"(b1));
}
__device__ __forceinline__ void ldsm4(uint32_t* r, uint32_t addr) {
    asm volatile("ldmatrix.sync.aligned.m8n8.x4.shared.b16 {%0,%1,%2,%3}, [%4];"
                 : "=r"(r[0]), "=r"(r[1]), "=r"(r[2]), "=r"(r[3]) : "r"(addr));
}
__device__ __forceinline__ void cpasync16(uint32_t dst, const void* src) {
    asm volatile("cp.async.cg.shared.global [%0], [%1], 16;" :: "r"(dst), "l"(src));
}

// ---------------- fused QKV weight repack+transpose+split + bias concat ------
__global__ __launch_bounds__(256) void wconv_qkv_kernel(const float* __restrict__ Wq,
                                                        const float* __restrict__ Wk,
                                                        const float* __restrict__ Wv,
                                                        const float* __restrict__ bq,
                                                        const float* __restrict__ bk,
                                                        const float* __restrict__ bv,
                                                        __nv_bfloat16* __restrict__ Whi,
                                                        __nv_bfloat16* __restrict__ Wlo,
                                                        float* __restrict__ bqkv,
                                                        int l) {
    __shared__ float s[32][33];
    int n0 = blockIdx.y * 32, e0 = blockIdx.x * 32;
    int tx = threadIdx.x, ty = threadIdx.y;
    int sel = n0 / E_;
    int nn = n0 % E_;
    int h = nn >> 6, hs0 = nn & 63;
    const float* src = sel == 0 ? Wq : (sel == 1 ? Wk : Wv);
    const float* base = src + ((size_t)(l * H_ + h) * E_) * 64;
#pragma unroll
    for (int i = 0; i < 4; i++) {
        int e = ty + 8 * i;
        s[e][tx] = base[(size_t)(e0 + e) * 64 + hs0 + tx];
    }
    __syncthreads();
#pragma unroll
    for (int i = 0; i < 4; i++) {
        int nl = ty + 8 * i;
        float x = s[tx][nl];
        __nv_bfloat16 hh = __float2bfloat16(x);
        __nv_bfloat16 ll = __float2bfloat16(x - __bfloat162float(hh));
        size_t oi = (size_t)(n0 + nl) * E_ + e0 + tx;
        Whi[oi] = hh;
        Wlo[oi] = ll;
    }
    int gid = (blockIdx.y * gridDim.x + blockIdx.x) * 256 + ty * 32 + tx;
    if (gid < NQKV) {
        float v;
        if (gid < E_)            v = bq[l * E_ + gid];
        else if (gid < 2 * E_)   v = bk[l * E_ + gid - E_];
        else                     v = bv[l * E_ + gid - 2 * E_];
        bqkv[l * NQKV + gid] = v;
    }
}

// ---------------- weight transpose + bf16 hi/lo split ------------------------
__global__ __launch_bounds__(256) void wconvt_kernel(const float* __restrict__ W,
                                                     __nv_bfloat16* __restrict__ Whi,
                                                     __nv_bfloat16* __restrict__ Wlo,
                                                     int K, int N) {
    __shared__ float s[32][33];
    int k0 = blockIdx.y * 32, n0 = blockIdx.x * 32;
    int tx = threadIdx.x, ty = threadIdx.y;
#pragma unroll
    for (int i = 0; i < 4; i++)
        s[ty + 8 * i][tx] = W[(size_t)(k0 + ty + 8 * i) * N + n0 + tx];
    __syncthreads();
#pragma unroll
    for (int i = 0; i < 4; i++) {
        int n = ty + 8 * i;
        float x = s[tx][n];
        __nv_bfloat16 h = __float2bfloat16(x);
        __nv_bfloat16 l = __float2bfloat16(x - __bfloat162float(h));
        size_t oi = (size_t)(n0 + n) * K + k0 + tx;
        Whi[oi] = h;
        Wlo[oi] = l;
    }
}

// ---------------- generic weight transpose -> single fp16 --------------------
__global__ __launch_bounds__(256) void wconvt_h_kernel(const float* __restrict__ W,
                                                       __half* __restrict__ Wt,
                                                       int K, int N) {
    __shared__ float s[32][33];
    int k0 = blockIdx.y * 32, n0 = blockIdx.x * 32;
    int tx = threadIdx.x, ty = threadIdx.y;
#pragma unroll
    for (int i = 0; i < 4; i++)
        s[ty + 8 * i][tx] = W[(size_t)(k0 + ty + 8 * i) * N + n0 + tx];
    __syncthreads();
#pragma unroll
    for (int i = 0; i < 4; i++) {
        int n = ty + 8 * i;
        Wt[(size_t)(n0 + n) * K + k0 + tx] = __float2half_rn(s[tx][n]);
    }
}

// ---------------- fused embedding + layernorm -> bf16 hi/lo -------------------
__global__ __launch_bounds__(256) void embed_ln_kernel(const int* __restrict__ idx,
                                                       const float* __restrict__ tok,
                                                       const float* __restrict__ pos,
                                                       const float* __restrict__ g,
                                                       const float* __restrict__ b,
                                                       float* __restrict__ x,
                                                       __nv_bfloat16* __restrict__ hi,
                                                       __nv_bfloat16* __restrict__ lo) {
    int row = blockIdx.x;
    int tid = threadIdx.x;
    int token = idx[row];
    int tp = row % T_;
    size_t rb = (size_t)row * E_;
    float v[3], s = 0.f, sq = 0.f;
#pragma unroll
    for (int i = 0; i < 3; i++) {
        int e = tid + (i << 8);
        float t = tok[(size_t)token * E_ + e] + pos[(size_t)tp * E_ + e];
        x[rb + e] = t;
        v[i] = t; s += t; sq += t * t;
    }
#pragma unroll
    for (int o = 16; o > 0; o >>= 1) {
        s  += __shfl_xor_sync(0xffffffffu, s, o);
        sq += __shfl_xor_sync(0xffffffffu, sq, o);
    }
    __shared__ float ss[8], ssq[8];
    if ((tid & 31) == 0) { ss[tid >> 5] = s; ssq[tid >> 5] = sq; }
    __syncthreads();
    s = 0.f; sq = 0.f;
#pragma unroll
    for (int i = 0; i < 8; i++) { s += ss[i]; sq += ssq[i]; }
    float mean = s * (1.f / E_);
    float var  = sq * (1.f / E_) - mean * mean;
    float rstd = rsqrtf(var + 1e-5f);
#pragma unroll
    for (int i = 0; i < 3; i++) {
        int e = tid + (i << 8);
        float y = (v[i] - mean) * rstd * g[e] + b[e];
        __nv_bfloat16 h = __float2bfloat16(y);
        hi[rb + e] = h;
        lo[rb + e] = __float2bfloat16(y - __bfloat162float(h));
    }
}

// ---------------- fused split-K reduce + residual + layernorm ----------------
template<int FP16>
__global__ __launch_bounds__(256) void reduce_ln_kernel(const float* __restrict__ parts,
                                                        int nsplit,
                                                        const float* __restrict__ bias,
                                                        float* __restrict__ x,
                                                        const float* __restrict__ g,
                                                        const float* __restrict__ b,
                                                        __nv_bfloat16* __restrict__ hi,
                                                        __nv_bfloat16* __restrict__ lo) {
    int row = blockIdx.x, tid = threadIdx.x;
    size_t rb = (size_t)row * E_;
    const size_t plane = (size_t)BT * E_;
    float v[3], s = 0.f, sq = 0.f;
#pragma unroll
    for (int i = 0; i < 3; i++) {
        int e = tid + (i << 8);
        size_t ix = rb + e;
        float t = parts[ix];
        for (int p = 1; p < nsplit; p++) t += parts[plane * p + ix];
        t += bias[e] + x[ix];
        x[ix] = t;
        v[i] = t; s += t; sq += t * t;
    }
#pragma unroll
    for (int o = 16; o > 0; o >>= 1) {
        s  += __shfl_xor_sync(0xffffffffu, s, o);
        sq += __shfl_xor_sync(0xffffffffu, sq, o);
    }
    __shared__ float ss[8], ssq[8];
    if ((tid & 31) == 0) { ss[tid >> 5] = s; ssq[tid >> 5] = sq; }
    __syncthreads();
    s = 0.f; sq = 0.f;
#pragma unroll
    for (int i = 0; i < 8; i++) { s += ss[i]; sq += ssq[i]; }
    float mean = s * (1.f / E_);
    float var  = sq * (1.f / E_) - mean * mean;
    float rstd = rsqrtf(var + 1e-5f);
#pragma unroll
    for (int i = 0; i < 3; i++) {
        int e = tid + (i << 8);
        float y = (v[i] - mean) * rstd * g[e] + b[e];
        if (FP16) {
            __half h = __float2half_rn(y);
            __half l2 = __float2half_rn(y - __half2float(h));
            *(unsigned short*)&hi[rb + e] = *(unsigned short*)&h;
            *(unsigned short*)&lo[rb + e] = *(unsigned short*)&l2;
        } else {
            __nv_bfloat16 h = __float2bfloat16(y);
            hi[rb + e] = h;
            lo[rb + e] = __float2bfloat16(y - __bfloat162float(h));
        }
    }
}

// ---------------- tensor-core GEMM (bf16 hi/lo, 3-sweep, 3 stages) -----------
#define STG3 32768
#define GEMM_SMEM (3 * STG3)
__global__ __launch_bounds__(256, 2)
void gemm_tc_kernel(const __nv_bfloat16* __restrict__ Ahi,
                    const __nv_bfloat16* __restrict__ Alo,
                    const __nv_bfloat16* __restrict__ Bhi,
                    const __nv_bfloat16* __restrict__ Blo,
                    const float* __restrict__ bias,
                    float* __restrict__ C,
                    __nv_bfloat16* __restrict__ Chi,
                    __nv_bfloat16* __restrict__ Clo,
                    float* __restrict__ Cpart,
                    int N, int K, int kslen) {
    extern __shared__ __align__(16) char smem[];
    int tid = threadIdx.x, lane = tid & 31, wid = tid >> 5;
    int wm = wid >> 2, wn = wid & 3;
    int row0 = blockIdx.y << 7, col0 = blockIdx.x << 7;
    int k0base = blockIdx.z * kslen;
    uint32_t sb = smem_u32(smem);

    float acc[4][4][4] = {};

    const int nCh = kslen >> 5;
    int frow = tid >> 1;
    int fc0 = (tid & 1) << 1;
    uint32_t fsw = (uint32_t)((frow >> 1) & 3);

    auto loadStage = [&](int stg, int c) {
        if (c < nCh) {
            uint32_t st = sb + stg * STG3;
            int k0 = k0base + (c << 5);
            size_t abase = (size_t)(row0 + frow) * K + k0;
            size_t bbase = (size_t)(col0 + frow) * K + k0;
#pragma unroll
            for (int cc = 0; cc < 2; cc++) {
                int cl = fc0 + cc;
                uint32_t doff = (uint32_t)(frow << 6) + (((uint32_t)cl ^ fsw) << 4);
                cpasync16(st + doff,         Ahi + abase + (cl << 3));
                cpasync16(st + 8192 + doff,  Alo + abase + (cl << 3));
                cpasync16(st + 16384 + doff, Bhi + bbase + (cl << 3));
                cpasync16(st + 24576 + doff, Blo + bbase + (cl << 3));
            }
        }
        asm volatile("cp.async.commit_group;" ::: "memory");
    };

    int arow[4], brow[2];
    uint32_t asw[4], bsw[2];
#pragma unroll
    for (int mf = 0; mf < 4; mf++) {
        arow[mf] = (wm << 6) + (mf << 4) + (lane & 15);
        asw[mf] = (uint32_t)((arow[mf] >> 1) & 3);
    }
#pragma unroll
    for (int g = 0; g < 2; g++) {
        brow[g] = (wn << 5) + (g << 4) + (lane & 7) + (((lane >> 3) & 1) << 3);
        bsw[g] = (uint32_t)((brow[g] >> 1) & 3);
    }
    int kc = lane >> 4;

    loadStage(0, 0);
    loadStage(1, 1);

    int stg = 0;
    for (int c = 0; c < nCh; ++c) {
        asm volatile("cp.async.wait_group 1;" ::: "memory");
        __syncthreads();
        loadStage(stg == 0 ? 2 : stg - 1, c + 2);
        uint32_t st = sb + stg * STG3;
#pragma unroll
        for (int ks = 0; ks < 2; ks++) {
            int cl = (ks << 1) + kc;
            uint32_t ah[4][4], bh[2][4];
#pragma unroll
            for (int mf = 0; mf < 4; mf++)
                ldsm4(ah[mf], st + (uint32_t)(arow[mf] << 6) + (((uint32_t)cl ^ asw[mf]) << 4));
#pragma unroll
            for (int g = 0; g < 2; g++)
                ldsm4(bh[g], st + 16384 + (uint32_t)(brow[g] << 6) + (((uint32_t)cl ^ bsw[g]) << 4));
#pragma unroll
            for (int mf = 0; mf < 4; mf++)
#pragma unroll
                for (int nf = 0; nf < 4; nf++)
                    mma16816(acc[mf][nf], ah[mf], bh[nf >> 1][nf & 1], bh[nf >> 1][(nf & 1) + 2]);
            {
                uint32_t al[4][4];
#pragma unroll
                for (int mf = 0; mf < 4; mf++)
                    ldsm4(al[mf], st + 8192 + (uint32_t)(arow[mf] << 6) + (((uint32_t)cl ^ asw[mf]) << 4));
#pragma unroll
                for (int mf = 0; mf < 4; mf++)
#pragma unroll
                    for (int nf = 0; nf < 4; nf++)
                        mma16816(acc[mf][nf], al[mf], bh[nf >> 1][nf & 1], bh[nf >> 1][(nf & 1) + 2]);
            }
            {
                uint32_t bl[2][4];
#pragma unroll
                for (int g = 0; g < 2; g++)
                    ldsm4(bl[g], st + 24576 + (uint32_t)(brow[g] << 6) + (((uint32_t)cl ^ bsw[g]) << 4));
#pragma unroll
                for (int mf = 0; mf < 4; mf++)
#pragma unroll
                    for (int nf = 0; nf < 4; nf++)
                        mma16816(acc[mf][nf], ah[mf], bl[nf >> 1][nf & 1], bl[nf >> 1][(nf & 1) + 2]);
            }
        }
        stg = (stg == 2) ? 0 : stg + 1;
    }

    if (Cpart) {
        size_t plane = (size_t)blockIdx.z * (((size_t)gridDim.y << 7) * (size_t)N);
#pragma unroll
        for (int mf = 0; mf < 4; mf++) {
            int rbase = row0 + (wm << 6) + (mf << 4) + (lane >> 2);
#pragma unroll
            for (int nf = 0; nf < 4; nf++) {
                int cb = col0 + (wn << 5) + (nf << 3) + ((lane & 3) << 1);
#pragma unroll
                for (int half = 0; half < 2; half++) {
                    int r = rbase + (half << 3);
                    *(float2*)(Cpart + plane + (size_t)r * N + cb) =
                        make_float2(acc[mf][nf][half * 2], acc[mf][nf][half * 2 + 1]);
                }
            }
        }
        return;
    }
#pragma unroll
    for (int mf = 0; mf < 4; mf++) {
        int rbase = row0 + (wm << 6) + (mf << 4) + (lane >> 2);
#pragma unroll
        for (int nf = 0; nf < 4; nf++) {
            int cb = col0 + (wn << 5) + (nf << 3) + ((lane & 3) << 1);
            float b0 = bias ? bias[cb] : 0.f;
            float b1 = bias ? bias[cb + 1] : 0.f;
#pragma unroll
            for (int half = 0; half < 2; half++) {
                int r = rbase + (half << 3);
                float v0 = acc[mf][nf][half * 2 + 0] + b0;
                float v1 = acc[mf][nf][half * 2 + 1] + b1;
                size_t gi = (size_t)r * N + cb;
                if (Chi) {
                    __nv_bfloat162 h = __floats2bfloat162_rn(v0, v1);
                    float2 hf = __bfloat1622float2(h);
                    __nv_bfloat162 l = __floats2bfloat162_rn(v0 - hf.x, v1 - hf.y);
                    *(__nv_bfloat162*)(Chi + gi) = h;
                    *(__nv_bfloat162*)(Clo + gi) = l;
                } else {
                    *(float2*)(C + gi) = make_float2(v0, v1);
                }
            }
        }
    }
}

// ---------------- fp16 GEMM (single-fp16 weights, 1 or 2 sweeps) -------------
#define LSTG 24576
#define GEMM_H_SMEM (3 * LSTG)
__global__ __launch_bounds__(256, 2)
void gemm_h_kernel(const __nv_bfloat16* __restrict__ AhiB,   // fp16 bits
                   const __nv_bfloat16* __restrict__ AloB,   // fp16 bits (unused if nsweep==1)
                   const __half* __restrict__ Bt,
                   const float* __restrict__ bias,
                   float* __restrict__ C,
                   float* __restrict__ Cpart,
                   int N, int K, int kslen, int nsweep) {
    extern __shared__ __align__(16) char smem[];
    int tid = threadIdx.x, lane = tid & 31, wid = tid >> 5;
    int wm = wid >> 2, wn = wid & 3;
    int row0 = blockIdx.y << 7, col0 = blockIdx.x << 7;
    int k0base = blockIdx.z * kslen;
    uint32_t sb = smem_u32(smem);
    const __half* Ahi = (const __half*)AhiB;
    const __half* Alo = (const __half*)AloB;

    float acc[4][4][4] = {};
    const int nCh = kslen >> 5;
    int frow = tid >> 1;
    int fc0 = (tid & 1) << 1;
    uint32_t fsw = (uint32_t)((frow >> 1) & 3);

    auto loadStage = [&](int stg, int c) {
        if (c < nCh) {
            uint32_t st = sb + stg * LSTG;
            int k0 = k0base + (c << 5);
            size_t abase = (size_t)(row0 + frow) * K + k0;
            size_t bbase = (size_t)(col0 + frow) * K + k0;
#pragma unroll
            for (int cc = 0; cc < 2; cc++) {
                int cl = fc0 + cc;
                uint32_t doff = (uint32_t)(frow << 6) + (((uint32_t)cl ^ fsw) << 4);
                cpasync16(st + doff,         Ahi + abase + (cl << 3));
                if (nsweep > 1)
                    cpasync16(st + 8192 + doff, Alo + abase + (cl << 3));
                cpasync16(st + 16384 + doff, Bt + bbase + (cl << 3));
            }
        }
        asm volatile("cp.async.commit_group;" ::: "memory");
    };

    int arow[4], brow[2];
    uint32_t asw[4], bsw[2];
#pragma unroll
    for (int mf = 0; mf < 4; mf++) {
        arow[mf] = (wm << 6) + (mf << 4) + (lane & 15);
        asw[mf] = (uint32_t)((arow[mf] >> 1) & 3);
    }
#pragma unroll
    for (int g = 0; g < 2; g++) {
        brow[g] = (wn << 5) + (g << 4) + (lane & 7) + (((lane >> 3) & 1) << 3);
        bsw[g] = (uint32_t)((brow[g] >> 1) & 3);
    }
    int kc = lane >> 4;

    loadStage(0, 0);
    loadStage(1, 1);

    int stg = 0;
    for (int c = 0; c < nCh; ++c) {
        asm volatile("cp.async.wait_group 1;" ::: "memory");
        __syncthreads();
        loadStage(stg == 0 ? 2 : stg - 1, c + 2);
        uint32_t st = sb + stg * LSTG;
#pragma unroll
        for (int ks = 0; ks < 2; ks++) {
            int cl = (ks << 1) + kc;
            uint32_t ah[4][4], bb[2][4];
#pragma unroll
            for (int mf = 0; mf < 4; mf++)
                ldsm4(ah[mf], st + (uint32_t)(arow[mf] << 6) + (((uint32_t)cl ^ asw[mf]) << 4));
#pragma unroll
            for (int g = 0; g < 2; g++)
                ldsm4(bb[g], st + 16384 + (uint32_t)(brow[g] << 6) + (((uint32_t)cl ^ bsw[g]) << 4));
#pragma unroll
            for (int mf = 0; mf < 4; mf++)
#pragma unroll
                for (int nf = 0; nf < 4; nf++)
                    mma16816h(acc[mf][nf], ah[mf], bb[nf >> 1][nf & 1], bb[nf >> 1][(nf & 1) + 2]);
            if (nsweep > 1) {
                uint32_t al[4][4];
#pragma unroll
                for (int mf = 0; mf < 4; mf++)
                    ldsm4(al[mf], st + 8192 + (uint32_t)(arow[mf] << 6) + (((uint32_t)cl ^ asw[mf]) << 4));
#pragma unroll
                for (int mf = 0; mf < 4; mf++)
#pragma unroll
                    for (int nf = 0; nf < 4; nf++)
                        mma16816h(acc[mf][nf], al[mf], bb[nf >> 1][nf & 1], bb[nf >> 1][(nf & 1) + 2]);
            }
        }
        stg = (stg == 2) ? 0 : stg + 1;
    }

    if (Cpart) {
        size_t plane = (size_t)blockIdx.z * (((size_t)gridDim.y << 7) * (size_t)N);
#pragma unroll
        for (int mf = 0; mf < 4; mf++) {
            int rbase = row0 + (wm << 6) + (mf << 4) + (lane >> 2);
#pragma unroll
            for (int nf = 0; nf < 4; nf++) {
                int cb = col0 + (wn << 5) + (nf << 3) + ((lane & 3) << 1);
#pragma unroll
                for (int half = 0; half < 2; half++) {
                    int r = rbase + (half << 3);
                    *(float2*)(Cpart + plane + (size_t)r * N + cb) =
                        make_float2(acc[mf][nf][half * 2], acc[mf][nf][half * 2 + 1]);
                }
            }
        }
        return;
    }
#pragma unroll
    for (int mf = 0; mf < 4; mf++) {
        int rbase = row0 + (wm << 6) + (mf << 4) + (lane >> 2);
#pragma unroll
        for (int nf = 0; nf < 4; nf++) {
            int cb = col0 + (wn << 5) + (nf << 3) + ((lane & 3) << 1);
            float b0 = bias[cb], b1 = bias[cb + 1];
#pragma unroll
            for (int half = 0; half < 2; half++) {
                int r = rbase + (half << 3);
                size_t gi = (size_t)r * N + cb;
                *(float2*)(C + gi) = make_float2(acc[mf][nf][half * 2] + b0,
                                                 acc[mf][nf][half * 2 + 1] + b1);
            }
        }
    }
}

// ---------------- split-K reduce (W1 path: relu + fp16 hi/lo out) ------------
__global__ __launch_bounds__(256) void reduce_kernel(const float* __restrict__ parts,
                                                     int nsplit,
                                                     const float* __restrict__ bias,
                                                     __nv_bfloat16* __restrict__ outHi,
                                                     __nv_bfloat16* __restrict__ outLo,
                                                     int N) {
    size_t i = ((size_t)blockIdx.x * 256 + threadIdx.x) * 4;
    size_t plane = (size_t)BT * N;
    int col = (int)(i % N);
    float4 s = *(const float4*)(parts + i);
    for (int p = 1; p < nsplit; p++) {
        float4 t = *(const float4*)(parts + plane * p + i);
        s.x += t.x; s.y += t.y; s.z += t.z; s.w += t.w;
    }
    float4 b = *(const float4*)(bias + col);
    s.x = fmaxf(s.x + b.x, 0.f); s.y = fmaxf(s.y + b.y, 0.f);
    s.z = fmaxf(s.z + b.z, 0.f); s.w = fmaxf(s.w + b.w, 0.f);
    __half2 h0 = __floats2half2_rn(s.x, s.y);
    __half2 h1 = __floats2half2_rn(s.z, s.w);
    float2 f0 = __half22float2(h0), f1 = __half22float2(h1);
    __half2 l0 = __floats2half2_rn(s.x - f0.x, s.y - f0.y);
    __half2 l1 = __floats2half2_rn(s.z - f1.x, s.w - f1.y);
    *(__half2*)(outHi + i) = h0;
    *(__half2*)(outHi + i + 2) = h1;
    *(__half2*)(outLo + i) = l0;
    *(__half2*)(outLo + i + 2) = l1;
}

// ---------------- tensor-core flash attention --------------------------------
#define ATT_SMEM 49152
__global__ __launch_bounds__(128)
void attn_kernel(const __nv_bfloat16* __restrict__ qkvhi,
                 const __nv_bfloat16* __restrict__ qkvlo,
                 __nv_bfloat16* __restrict__ ohi,
                 __nv_bfloat16* __restrict__ olo) {
    extern __shared__ __align__(16) char smem[];
    uint32_t sb = smem_u32(smem);
    const uint32_t Q_HI = 0, Q_LO = 8192, K_HI = 16384, K_LO = 24576,
                   VT_HI = 32768, VT_LO = 40960;
    int tid = threadIdx.x, lane = tid & 31, w = tid >> 5;
    int qt = (int)gridDim.x - 1 - (int)blockIdx.x;
    int bh = blockIdx.y;
    int bb = bh / H_, hh = bh % H_;
    size_t qrowbase = (size_t)(bb * T_ + (qt << 6));
    const int coff = hh * 64;
    int kc = lane >> 4;

    {
        int r0 = tid >> 1;
        int c0 = (tid & 1) << 2;
        size_t g = (qrowbase + r0) * (size_t)NQKV + coff;
#pragma unroll
        for (int i = 0; i < 4; i++) {
            int c = c0 + i;
            uint32_t d = (uint32_t)(r0 << 7) + (((uint32_t)(c ^ (r0 & 7))) << 4);
            cpasync16(sb + Q_HI + d, qkvhi + g + (c << 3));
            cpasync16(sb + Q_LO + d, qkvlo + g + (c << 3));
        }
        asm volatile("cp.async.commit_group;\n\tcp.async.wait_group 0;" ::: "memory");
    }
    __syncthreads();
    uint32_t qh[4][4], ql[4][4];
    {
        int aRow = (w << 4) + (lane & 15);
#pragma unroll
        for (int ks = 0; ks < 4; ks++) {
            int cl = (ks << 1) + kc;
            uint32_t ad = (uint32_t)(aRow << 7) + (((uint32_t)(cl ^ (aRow & 7))) << 4);
            ldsm4(qh[ks], sb + Q_HI + ad);
            ldsm4(ql[ks], sb + Q_LO + ad);
        }
    }

    float oacc[8][4] = {};
    float m1 = -INFINITY, m2 = -INFINITY, l1 = 0.f, l2 = 0.f;
    int r1 = lane >> 2;
    int rowg1 = (qt << 6) + (w << 4) + r1;
    int rowg2 = rowg1 + 8;

    for (int kt = 0; kt <= qt; kt++) {
        __syncthreads();
        size_t kbase = (size_t)(bb * T_ + (kt << 6));
        {
            int r0 = tid >> 1;
            int c0 = (tid & 1) << 2;
            size_t g = (kbase + r0) * (size_t)NQKV + E_ + coff;
#pragma unroll
            for (int i = 0; i < 4; i++) {
                int c = c0 + i;
                uint32_t d = (uint32_t)(r0 << 7) + (((uint32_t)(c ^ (r0 & 7))) << 4);
                cpasync16(sb + K_HI + d, qkvhi + g + (c << 3));
                cpasync16(sb + K_LO + d, qkvlo + g + (c << 3));
            }
            asm volatile("cp.async.commit_group;" ::: "memory");
        }
        {
            int kvp = tid & 31;
            int dg0 = tid >> 5;
            int kv = kvp << 1;
#pragma unroll
            for (int t = 0; t < 2; t++) {
                int d0 = (dg0 + (t << 2)) << 3;
                size_t g0 = (kbase + kv) * (size_t)NQKV + 2 * E_ + coff + d0;
                uint4 h0 = *(const uint4*)(qkvhi + g0);
                uint4 h1 = *(const uint4*)(qkvhi + g0 + NQKV);
                uint4 l0 = *(const uint4*)(qkvlo + g0);
                uint4 l1v = *(const uint4*)(qkvlo + g0 + NQKV);
                const __nv_bfloat16* ph0 = (const __nv_bfloat16*)&h0;
                const __nv_bfloat16* ph1 = (const __nv_bfloat16*)&h1;
                const __nv_bfloat16* pl0 = (const __nv_bfloat16*)&l0;
                const __nv_bfloat16* pl1 = (const __nv_bfloat16*)&l1v;
#pragma unroll
                for (int j = 0; j < 8; j++) {
                    int d = d0 + j;
                    uint32_t ad = (uint32_t)(d << 7) +
                                  ((((uint32_t)(kvp >> 2) ^ (uint32_t)(d & 7)) << 4)) +
                                  ((uint32_t)(kvp & 3) << 2);
                    __nv_bfloat162 hw; hw.x = ph0[j]; hw.y = ph1[j];
                    __nv_bfloat162 lw; lw.x = pl0[j]; lw.y = pl1[j];
                    *(__nv_bfloat162*)(smem + VT_HI + ad) = hw;
                    *(__nv_bfloat162*)(smem + VT_LO + ad) = lw;
                }
            }
        }
        asm volatile("cp.async.wait_group 0;" ::: "memory");
        __syncthreads();

        float sacc[8][4] = {};
#pragma unroll
        for (int ks = 0; ks < 4; ks++) {
            int cl = (ks << 1) + kc;
            uint32_t kh[4][4], kl2[4][4];
#pragma unroll
            for (int g = 0; g < 4; g++) {
                int bRow = (g << 4) + (lane & 7) + (((lane >> 3) & 1) << 3);
                uint32_t bd = (uint32_t)(bRow << 7) + (((uint32_t)(cl ^ (bRow & 7))) << 4);
                ldsm4(kh[g], sb + K_HI + bd);
                ldsm4(kl2[g], sb + K_LO + bd);
            }
#pragma unroll
            for (int g = 0; g < 4; g++)
#pragma unroll
                for (int nfp = 0; nfp < 2; nfp++)
                    mma16816(sacc[2 * g + nfp], qh[ks], kh[g][nfp], kh[g][nfp + 2]);
#pragma unroll
            for (int g = 0; g < 4; g++)
#pragma unroll
                for (int nfp = 0; nfp < 2; nfp++)
                    mma16816(sacc[2 * g + nfp], ql[ks], kh[g][nfp], kh[g][nfp + 2]);
#pragma unroll
            for (int g = 0; g < 4; g++)
#pragma unroll
                for (int nfp = 0; nfp < 2; nfp++)
                    mma16816(sacc[2 * g + nfp], qh[ks], kl2[g][nfp], kl2[g][nfp + 2]);
        }
#pragma unroll
        for (int nf = 0; nf < 8; nf++) {
            sacc[nf][0] *= 0.125f; sacc[nf][1] *= 0.125f;
            sacc[nf][2] *= 0.125f; sacc[nf][3] *= 0.125f;
        }
        if (kt == qt) {
#pragma unroll
            for (int nf = 0; nf < 8; nf++) {
                int colb = (kt << 6) + (nf << 3) + ((lane & 3) << 1);
                if (colb > rowg1)     sacc[nf][0] = -INFINITY;
                if (colb + 1 > rowg1) sacc[nf][1] = -INFINITY;
                if (colb > rowg2)     sacc[nf][2] = -INFINITY;
                if (colb + 1 > rowg2) sacc[nf][3] = -INFINITY;
            }
        }
        float t1 = -INFINITY, t2 = -INFINITY;
#pragma unroll
        for (int nf = 0; nf < 8; nf++) {
            t1 = fmaxf(t1, fmaxf(sacc[nf][0], sacc[nf][1]));
            t2 = fmaxf(t2, fmaxf(sacc[nf][2], sacc[nf][3]));
        }
        t1 = fmaxf(t1, __shfl_xor_sync(0xffffffffu, t1, 1));
        t1 = fmaxf(t1, __shfl_xor_sync(0xffffffffu, t1, 2));
        t2 = fmaxf(t2, __shfl_xor_sync(0xffffffffu, t2, 1));
        t2 = fmaxf(t2, __shfl_xor_sync(0xffffffffu, t2, 2));
        float mn1 = fmaxf(m1, t1), mn2 = fmaxf(m2, t2);
        float a1 = __expf(m1 - mn1), a2 = __expf(m2 - mn2);
        float ps1 = 0.f, ps2 = 0.f;
#pragma unroll
        for (int nf = 0; nf < 8; nf++) {
            sacc[nf][0] = __expf(sacc[nf][0] - mn1);
            sacc[nf][1] = __expf(sacc[nf][1] - mn1);
            sacc[nf][2] = __expf(sacc[nf][2] - mn2);
            sacc[nf][3] = __expf(sacc[nf][3] - mn2);
            ps1 += sacc[nf][0] + sacc[nf][1];
            ps2 += sacc[nf][2] + sacc[nf][3];
        }
        ps1 += __shfl_xor_sync(0xffffffffu, ps1, 1);
        ps1 += __shfl_xor_sync(0xffffffffu, ps1, 2);
        ps2 += __shfl_xor_sync(0xffffffffu, ps2, 1);
        ps2 += __shfl_xor_sync(0xffffffffu, ps2, 2);
        l1 = l1 * a1 + ps1;
        l2 = l2 * a2 + ps2;
        m1 = mn1; m2 = mn2;
#pragma unroll
        for (int nf = 0; nf < 8; nf++) {
            oacc[nf][0] *= a1; oacc[nf][1] *= a1;
            oacc[nf][2] *= a2; oacc[nf][3] *= a2;
        }
#pragma unroll
        for (int j = 0; j < 4; j++) {
            uint32_t pah[4], pal[4];
#pragma unroll
            for (int half = 0; half < 2; half++) {
                float x0 = sacc[2 * j + half][0], x1 = sacc[2 * j + half][1];
                float x2 = sacc[2 * j + half][2], x3 = sacc[2 * j + half][3];
                __nv_bfloat162 h01 = __floats2bfloat162_rn(x0, x1);
                __nv_bfloat162 h23 = __floats2bfloat162_rn(x2, x3);
                float2 f01 = __bfloat1622float2(h01), f23 = __bfloat1622float2(h23);
                __nv_bfloat162 lo01 = __floats2bfloat162_rn(x0 - f01.x, x1 - f01.y);
                __nv_bfloat162 lo23 = __floats2bfloat162_rn(x2 - f23.x, x3 - f23.y);
                pah[2 * half + 0] = *(uint32_t*)&h01;
                pah[2 * half + 1] = *(uint32_t*)&h23;
                pal[2 * half + 0] = *(uint32_t*)&lo01;
                pal[2 * half + 1] = *(uint32_t*)&lo23;
            }
            int cl = (j << 1) + kc;
            uint32_t vh[4][4], vl[4][4];
#pragma unroll
            for (int g = 0; g < 4; g++) {
                int bRow = (g << 4) + (lane & 7) + (((lane >> 3) & 1) << 3);
                uint32_t bd = (uint32_t)(bRow << 7) + (((uint32_t)(cl ^ (bRow & 7))) << 4);
                ldsm4(vh[g], sb + VT_HI + bd);
                ldsm4(vl[g], sb + VT_LO + bd);
            }
#pragma unroll
            for (int g = 0; g < 4; g++)
#pragma unroll
                for (int nfp = 0; nfp < 2; nfp++)
                    mma16816(oacc[2 * g + nfp], pah, vh[g][nfp], vh[g][nfp + 2]);
#pragma unroll
            for (int g = 0; g < 4; g++)
#pragma unroll
                for (int nfp = 0; nfp < 2; nfp++)
                    mma16816(oacc[2 * g + nfp], pal, vh[g][nfp], vh[g][nfp + 2]);
#pragma unroll
            for (int g = 0; g < 4; g++)
#pragma unroll
                for (int nfp = 0; nfp < 2; nfp++)
                    mma16816(oacc[2 * g + nfp], pah, vl[g][nfp], vl[g][nfp + 2]);
        }
    }

    float li1 = 1.f / l1, li2 = 1.f / l2;
    size_t ob1 = (qrowbase + (w << 4) + r1) * (size_t)E_ + coff;
    size_t ob2 = ob1 + (size_t)8 * E_;
#pragma unroll
    for (int nf = 0; nf < 8; nf++) {
        int d = (nf << 3) + ((lane & 3) << 1);
        float v0 = oacc[nf][0] * li1, v1 = oacc[nf][1] * li1;
        __nv_bfloat162 h = __floats2bfloat162_rn(v0, v1);
        float2 hf = __bfloat1622float2(h);
        __nv_bfloat162 lo = __floats2bfloat162_rn(v0 - hf.x, v1 - hf.y);
        *(__nv_bfloat162*)(ohi + ob1 + d) = h;
        *(__nv_bfloat162*)(olo + ob1 + d) = lo;
        float v2 = oacc[nf][2] * li2, v3 = oacc[nf][3] * li2;
        __nv_bfloat162 h2 = __floats2bfloat162_rn(v2, v3);
        float2 hf2 = __bfloat1622float2(h2);
        __nv_bfloat162 lo2 = __floats2bfloat162_rn(v2 - hf2.x, v3 - hf2.y);
        *(__nv_bfloat162*)(ohi + ob2 + d) = h2;
        *(__nv_bfloat16*)(olo + ob2 + d) = lo2.x;
        *(__nv_bfloat16*)(olo + ob2 + d + 1) = lo2.y;
    }
}

// ---------------- loss ------------------------------------------------------
__global__ __launch_bounds__(256) void row_lse_kernel(const float* __restrict__ logits,
                                                      const int* __restrict__ targets,
                                                      float* __restrict__ rowloss) {
    int row = blockIdx.x, tid = threadIdx.x;
    const float* lr = logits + (size_t)row * V_;
    float mx = -INFINITY;
    for (int i = tid; i < V_; i += 256) mx = fmaxf(mx, lr[i]);
#pragma unroll
    for (int o = 16; o > 0; o >>= 1) mx = fmaxf(mx, __shfl_xor_sync(0xffffffffu, mx, o));
    __shared__ float sm[8];
    if ((tid & 31) == 0) sm[tid >> 5] = mx;
    __syncthreads();
    float m2 = -INFINITY;
#pragma unroll
    for (int i = 0; i < 8; i++) m2 = fmaxf(m2, sm[i]);
    float se = 0.f;
    for (int i = tid; i < V_; i += 256) se += __expf(lr[i] - m2);
#pragma unroll
    for (int o = 16; o > 0; o >>= 1) se += __shfl_xor_sync(0xffffffffu, se, o);
    __shared__ float ssum[8];
    if ((tid & 31) == 0) ssum[tid >> 5] = se;
    __syncthreads();
    if (tid == 0) {
        float tot = 0.f;
#pragma unroll
        for (int i = 0; i < 8; i++) tot += ssum[i];
        rowloss[row] = (logf(tot) + m2) - lr[targets[row]];
    }
}

__global__ __launch_bounds__(256) void loss_reduce_kernel(const float* __restrict__ rowloss,
                                                          float* __restrict__ out) {
    int tid = threadIdx.x;
    float s = 0.f;
    for (int i = tid; i < BT; i += 256) s += rowloss[i];
#pragma unroll
    for (int o = 16; o > 0; o >>= 1) s += __shfl_xor_sync(0xffffffffu, s, o);
    __shared__ float sm[8];
    if ((tid & 31) == 0) sm[tid >> 5] = s;
    __syncthreads();
    if (tid == 0) {
        float t = 0.f;
#pragma unroll
        for (int i = 0; i < 8; i++) t += sm[i];
        out[0] = t * (1.f / BT);
    }
}

// ---------------- launch ----------------------------------------------------
extern "C" void kernel_launch(void* const* d_in, const int* in_sizes, int n_in,
                              void* d_out, int out_size) {
    const int*   idx     = (const int*)d_in[0];
    const int*   targets = (const int*)d_in[1];
    const float* tok_emb = (const float*)d_in[2];
    const float* pos_emb = (const float*)d_in[3];
    const float* Wq  = (const float*)d_in[4];
    const float* bq  = (const float*)d_in[5];
    const float* Wk  = (const float*)d_in[6];
    const float* bk  = (const float*)d_in[7];
    const float* Wv  = (const float*)d_in[8];
    const float* bv  = (const float*)d_in[9];
    const float* Wo  = (const float*)d_in[10];
    const float* bo  = (const float*)d_in[11];
    const float* ln1g = (const float*)d_in[12];
    const float* ln1b = (const float*)d_in[13];
    const float* W1  = (const float*)d_in[14];
    const float* b1  = (const float*)d_in[15];
    const float* W2  = (const float*)d_in[16];
    const float* b2  = (const float*)d_in[17];
    const float* ln2g = (const float*)d_in[18];
    const float* ln2b = (const float*)d_in[19];
    const float* lnfg = (const float*)d_in[20];
    const float* lnfb = (const float*)d_in[21];
    const float* Wlm = (const float*)d_in[22];
    const float* blm = (const float*)d_in[23];
    float* out = (float*)d_out;

    float *px, *pbqkv, *ppart, *prl, *plg;
    __nv_bfloat16 *pqkvhi, *pqkvlo, *phhi, *phlo, *pohi, *polo, *pffhi, *pfflo, *pwthi, *pwtlo;
    __half *pwlmh;
    cudaGetSymbolAddress((void**)&px,     g_x);
    cudaGetSymbolAddress((void**)&pqkvhi, g_qkvhi);
    cudaGetSymbolAddress((void**)&pqkvlo, g_qkvlo);
    cudaGetSymbolAddress((void**)&phhi,   g_hhi);
    cudaGetSymbolAddress((void**)&phlo,   g_hlo);
    cudaGetSymbolAddress((void**)&pohi,   g_ohi);
    cudaGetSymbolAddress((void**)&polo,   g_olo);
    cudaGetSymbolAddress((void**)&pffhi,  g_ffhi);
    cudaGetSymbolAddress((void**)&pfflo,  g_fflo);
    cudaGetSymbolAddress((void**)&pbqkv,  g_bqkv);
    cudaGetSymbolAddress((void**)&ppart,  g_part);
    cudaGetSymbolAddress((void**)&pwthi,  g_wthi);
    cudaGetSymbolAddress((void**)&pwtlo,  g_wtlo);
    cudaGetSymbolAddress((void**)&pwlmh,  g_wlmh);
    cudaGetSymbolAddress((void**)&prl,    g_rowloss);
    cudaGetSymbolAddress((void**)&plg,    g_logits_scratch);

    cudaFuncSetAttribute(gemm_tc_kernel, cudaFuncAttributeMaxDynamicSharedMemorySize, GEMM_SMEM);
    cudaFuncSetAttribute(gemm_h_kernel,  cudaFuncAttributeMaxDynamicSharedMemorySize, GEMM_H_SMEM);
    cudaFuncSetAttribute(attn_kernel,    cudaFuncAttributeMaxDynamicSharedMemorySize, ATT_SMEM);

    const long long NLOG = (long long)BT * V_;
    float* logits = (out_size >= NLOG) ? out : plg;

    dim3 cb(32, 8);
    dim3 gQKVw(E_ / 32, NQKV / 32);
    dim3 gQKV(NQKV / 128, BT / 128);
    dim3 gWo(E_ / 128, BT / 128, 3);
    dim3 gW1(FF / 128, BT / 128, 2);
    dim3 gW2(E_ / 128, BT / 128, 3);
    dim3 gVd(V_ / 128, BT / 128);
    dim3 gAttn(T_ / 64, B_ * H_);
    int rF = BT * FF / 1024;

    for (int l = 0; l < L_; l++) {
        size_t wel = (size_t)l * E_ * E_;
        if (l == 0)
            embed_ln_kernel<<<BT, 256>>>(idx, tok_emb, pos_emb, ln1g, ln1b, px, phhi, phlo); // 0
        wconv_qkv_kernel<<<gQKVw, cb>>>(Wq, Wk, Wv, bq, bk, bv,
                                        pwthi + OFF_QKV(l), pwtlo + OFF_QKV(l), pbqkv, l);  // 1
        gemm_tc_kernel<<<gQKV, 256, GEMM_SMEM>>>(phhi, phlo,                                // 2
            pwthi + OFF_QKV(l), pwtlo + OFF_QKV(l), pbqkv + l * NQKV,
            nullptr, pqkvhi, pqkvlo, nullptr, NQKV, E_, E_);
        attn_kernel<<<gAttn, 128, ATT_SMEM>>>(pqkvhi, pqkvlo, pohi, polo);                  // 3 (= global 5)
        wconvt_kernel<<<dim3(E_ / 32, E_ / 32), cb>>>(Wo + wel, pwthi + OFF_O(l), pwtlo + OFF_O(l), E_, E_);
        gemm_tc_kernel<<<gWo, 256, GEMM_SMEM>>>(pohi, polo,
            pwthi + OFF_O(l), pwtlo + OFF_O(l), nullptr,
            nullptr, nullptr, nullptr, ppart, E_, E_, 256);
        // ln2 output in fp16 (feeds fp16 W1 gemm)
        reduce_ln_kernel<1><<<BT, 256>>>(ppart, 3, bo + l * E_, px,
                                         ln2g + l * E_, ln2b + l * E_, phhi, phlo);
        wconvt_h_kernel<<<dim3(FF / 32, E_ / 32), cb>>>(W1 + (size_t)l * E_ * FF,
            (__half*)(pwthi + OFF_W1(l)), E_, FF);
        gemm_h_kernel<<<gW1, 256, GEMM_H_SMEM>>>(phhi, phlo,
            (const __half*)(pwthi + OFF_W1(l)), nullptr,
            nullptr, ppart, FF, E_, 384, 2);
        reduce_kernel<<<rF, 256>>>(ppart, 2, b1 + l * FF, pffhi, pfflo, FF);
        wconvt_h_kernel<<<dim3(E_ / 32, FF / 32), cb>>>(W2 + (size_t)l * FF * E_,
            (__half*)(pwthi + OFF_W2(l)), FF, E_);
        gemm_h_kernel<<<gW2, 256, GEMM_H_SMEM>>>(pffhi, pfflo,
            (const __half*)(pwthi + OFF_W2(l)), nullptr,
            nullptr, ppart, E_, FF, 1024, 2);
        if (l < L_ - 1)
            reduce_ln_kernel<0><<<BT, 256>>>(ppart, 3, b2 + l * E_, px,
                                             ln1g + (l + 1) * E_, ln1b + (l + 1) * E_, phhi, phlo);
        else
            reduce_ln_kernel<1><<<BT, 256>>>(ppart, 3, b2 + l * E_, px,
                                             lnfg, lnfb, phhi, phlo);   // fp16 for LM head
    }
    wconvt_h_kernel<<<dim3(V_ / 32, E_ / 32), cb>>>(Wlm, pwlmh, E_, V_);
    // LM head: 1-sweep fp16 (activation hi only)
    gemm_h_kernel<<<gVd, 256, GEMM_H_SMEM>>>(phhi, phlo, pwlmh, blm,
                                             logits, nullptr, V_, E_, E_, 1);

    // --- loss ---
    float* loss_dst = nullptr;
    if (out_size == 1)        loss_dst = out;
    else if (out_size > NLOG) loss_dst = out + NLOG;
    if (loss_dst) {
        row_lse_kernel<<<BT, 256>>>(logits, targets, prl);
        loss_reduce_kernel<<<1, 256>>>(prl, loss_dst);
    }
}

// round 11
// speedup vs baseline: 4.6123x; 1.0963x over previous
#include <cuda_runtime.h>
#include <cuda_bf16.h>
#include <cuda_fp16.h>
#include <math.h>
#include <stdint.h>

#define L_  4
#define H_  12
#define E_  768
#define HS_ 64
#define V_  32000
#define B_  2
#define T_  1024
#define BT  2048
#define FF  3072
#define NQKV 2304

// ---- weight scratch offsets (fp16 elements) ----
#define WPL 7077888ull
#define OFF_QKV(l) ((size_t)(l) * WPL)
#define OFF_O(l)   (OFF_QKV(l) + 1769472ull)
#define OFF_W1(l)  (OFF_QKV(l) + 2359296ull)
#define OFF_W2(l)  (OFF_QKV(l) + 4718592ull)
#define WTOT       ((size_t)4 * WPL)

// ---------------- scratch (static device globals) ----------------------------
__device__ float g_x[BT * E_];
__device__ __half g_qkvhi[BT * NQKV];
__device__ __half g_qkvlo[BT * NQKV];
__device__ __half g_hhi[BT * E_];
__device__ __half g_hlo[BT * E_];
__device__ __half g_ohi[BT * E_];
__device__ __half g_olo[BT * E_];
__device__ __half g_ffhi[BT * FF];
__device__ __half g_fflo[BT * FF];
__device__ float g_bqkv[L_ * NQKV];
__device__ float g_part[2ull * BT * FF];
__device__ __half g_wth[WTOT];
__device__ __half g_wlmh[(size_t)V_ * E_];
__device__ float g_rowloss[BT];
__device__ float g_logits_scratch[(size_t)BT * V_];

// ---------------- PTX helpers ------------------------------------------------
__device__ __forceinline__ uint32_t smem_u32(const void* p) {
    uint32_t a;
    asm("{ .reg .u64 t; cvta.to.shared.u64 t, %1; cvt.u32.u64 %0, t; }" : "=r"(a) : "l"(p));
    return a;
}
__device__ __forceinline__ void mma16816h(float* c, const uint32_t* a, uint32_t b0, uint32_t b1) {
    asm volatile(
        "mma.sync.aligned.m16n8k16.row.col.f32.f16.f16.f32 "
        "{%0,%1,%2,%3}, {%4,%5,%6,%7}, {%8,%9}, {%0,%1,%2,%3};"
        : "+f"(c[0]), "+f"(c[1]), "+f"(c[2]), "+f"(c[3])
        : "r"(a[0]), "r"(a[1]), "r"(a[2]), "r"(a[3]), "r"(b0), "r"(b1));
}
__device__ __forceinline__ void ldsm4(uint32_t* r, uint32_t addr) {
    asm volatile("ldmatrix.sync.aligned.m8n8.x4.shared.b16 {%0,%1,%2,%3}, [%4];"
                 : "=r"(r[0]), "=r"(r[1]), "=r"(r[2]), "=r"(r[3]) : "r"(addr));
}
__device__ __forceinline__ void cpasync16(uint32_t dst, const void* src) {
    asm volatile("cp.async.cg.shared.global [%0], [%1], 16;" :: "r"(dst), "l"(src));
}

// ---------------- fused QKV weight repack+transpose -> fp16 + bias concat ----
__global__ __launch_bounds__(256) void wconv_qkv_kernel(const float* __restrict__ Wq,
                                                        const float* __restrict__ Wk,
                                                        const float* __restrict__ Wv,
                                                        const float* __restrict__ bq,
                                                        const float* __restrict__ bk,
                                                        const float* __restrict__ bv,
                                                        __half* __restrict__ Wt,
                                                        float* __restrict__ bqkv,
                                                        int l) {
    __shared__ float s[32][33];
    int n0 = blockIdx.y * 32, e0 = blockIdx.x * 32;
    int tx = threadIdx.x, ty = threadIdx.y;
    int sel = n0 / E_;
    int nn = n0 % E_;
    int h = nn >> 6, hs0 = nn & 63;
    const float* src = sel == 0 ? Wq : (sel == 1 ? Wk : Wv);
    const float* base = src + ((size_t)(l * H_ + h) * E_) * 64;
#pragma unroll
    for (int i = 0; i < 4; i++) {
        int e = ty + 8 * i;
        s[e][tx] = base[(size_t)(e0 + e) * 64 + hs0 + tx];
    }
    __syncthreads();
#pragma unroll
    for (int i = 0; i < 4; i++) {
        int nl = ty + 8 * i;
        Wt[(size_t)(n0 + nl) * E_ + e0 + tx] = __float2half_rn(s[tx][nl]);
    }
    int gid = (blockIdx.y * gridDim.x + blockIdx.x) * 256 + ty * 32 + tx;
    if (gid < NQKV) {
        float v;
        if (gid < E_)            v = bq[l * E_ + gid];
        else if (gid < 2 * E_)   v = bk[l * E_ + gid - E_];
        else                     v = bv[l * E_ + gid - 2 * E_];
        bqkv[l * NQKV + gid] = v;
    }
}

// ---------------- generic weight transpose -> single fp16 --------------------
__global__ __launch_bounds__(256) void wconvt_h_kernel(const float* __restrict__ W,
                                                       __half* __restrict__ Wt,
                                                       int K, int N) {
    __shared__ float s[32][33];
    int k0 = blockIdx.y * 32, n0 = blockIdx.x * 32;
    int tx = threadIdx.x, ty = threadIdx.y;
#pragma unroll
    for (int i = 0; i < 4; i++)
        s[ty + 8 * i][tx] = W[(size_t)(k0 + ty + 8 * i) * N + n0 + tx];
    __syncthreads();
#pragma unroll
    for (int i = 0; i < 4; i++) {
        int n = ty + 8 * i;
        Wt[(size_t)(n0 + n) * K + k0 + tx] = __float2half_rn(s[tx][n]);
    }
}

// ---------------- fused embedding + layernorm -> fp16 hi/lo -------------------
__global__ __launch_bounds__(256) void embed_ln_kernel(const int* __restrict__ idx,
                                                       const float* __restrict__ tok,
                                                       const float* __restrict__ pos,
                                                       const float* __restrict__ g,
                                                       const float* __restrict__ b,
                                                       float* __restrict__ x,
                                                       __half* __restrict__ hi,
                                                       __half* __restrict__ lo) {
    int row = blockIdx.x;
    int tid = threadIdx.x;
    int token = idx[row];
    int tp = row % T_;
    size_t rb = (size_t)row * E_;
    float v[3], s = 0.f, sq = 0.f;
#pragma unroll
    for (int i = 0; i < 3; i++) {
        int e = tid + (i << 8);
        float t = tok[(size_t)token * E_ + e] + pos[(size_t)tp * E_ + e];
        x[rb + e] = t;
        v[i] = t; s += t; sq += t * t;
    }
#pragma unroll
    for (int o = 16; o > 0; o >>= 1) {
        s  += __shfl_xor_sync(0xffffffffu, s, o);
        sq += __shfl_xor_sync(0xffffffffu, sq, o);
    }
    __shared__ float ss[8], ssq[8];
    if ((tid & 31) == 0) { ss[tid >> 5] = s; ssq[tid >> 5] = sq; }
    __syncthreads();
    s = 0.f; sq = 0.f;
#pragma unroll
    for (int i = 0; i < 8; i++) { s += ss[i]; sq += ssq[i]; }
    float mean = s * (1.f / E_);
    float var  = sq * (1.f / E_) - mean * mean;
    float rstd = rsqrtf(var + 1e-5f);
#pragma unroll
    for (int i = 0; i < 3; i++) {
        int e = tid + (i << 8);
        float y = (v[i] - mean) * rstd * g[e] + b[e];
        __half h = __float2half_rn(y);
        hi[rb + e] = h;
        lo[rb + e] = __float2half_rn(y - __half2float(h));
    }
}

// ---------------- fused split-K reduce + residual + layernorm (fp16 out) -----
__global__ __launch_bounds__(256) void reduce_ln_kernel(const float* __restrict__ parts,
                                                        int nsplit,
                                                        const float* __restrict__ bias,
                                                        float* __restrict__ x,
                                                        const float* __restrict__ g,
                                                        const float* __restrict__ b,
                                                        __half* __restrict__ hi,
                                                        __half* __restrict__ lo) {
    int row = blockIdx.x, tid = threadIdx.x;
    size_t rb = (size_t)row * E_;
    const size_t plane = (size_t)BT * E_;
    float v[3], s = 0.f, sq = 0.f;
#pragma unroll
    for (int i = 0; i < 3; i++) {
        int e = tid + (i << 8);
        size_t ix = rb + e;
        float t = parts[ix];
        for (int p = 1; p < nsplit; p++) t += parts[plane * p + ix];
        t += bias[e] + x[ix];
        x[ix] = t;
        v[i] = t; s += t; sq += t * t;
    }
#pragma unroll
    for (int o = 16; o > 0; o >>= 1) {
        s  += __shfl_xor_sync(0xffffffffu, s, o);
        sq += __shfl_xor_sync(0xffffffffu, sq, o);
    }
    __shared__ float ss[8], ssq[8];
    if ((tid & 31) == 0) { ss[tid >> 5] = s; ssq[tid >> 5] = sq; }
    __syncthreads();
    s = 0.f; sq = 0.f;
#pragma unroll
    for (int i = 0; i < 8; i++) { s += ss[i]; sq += ssq[i]; }
    float mean = s * (1.f / E_);
    float var  = sq * (1.f / E_) - mean * mean;
    float rstd = rsqrtf(var + 1e-5f);
#pragma unroll
    for (int i = 0; i < 3; i++) {
        int e = tid + (i << 8);
        float y = (v[i] - mean) * rstd * g[e] + b[e];
        __half h = __float2half_rn(y);
        hi[rb + e] = h;
        lo[rb + e] = __float2half_rn(y - __half2float(h));
    }
}

// ---------------- fp16 tensor-core GEMM (1 or 2 sweeps, 3 stages) ------------
#define LSTG 24576
#define GEMM_H_SMEM (3 * LSTG)
__global__ __launch_bounds__(256, 2)
void gemm_h_kernel(const __half* __restrict__ Ahi,
                   const __half* __restrict__ Alo,
                   const __half* __restrict__ Bt,
                   const float* __restrict__ bias,
                   float* __restrict__ C,
                   __half* __restrict__ Chi,
                   __half* __restrict__ Clo,
                   float* __restrict__ Cpart,
                   int N, int K, int kslen, int nsweep) {
    extern __shared__ __align__(16) char smem[];
    int tid = threadIdx.x, lane = tid & 31, wid = tid >> 5;
    int wm = wid >> 2, wn = wid & 3;
    int row0 = blockIdx.y << 7, col0 = blockIdx.x << 7;
    int k0base = blockIdx.z * kslen;
    uint32_t sb = smem_u32(smem);

    float acc[4][4][4] = {};
    const int nCh = kslen >> 5;
    int frow = tid >> 1;
    int fc0 = (tid & 1) << 1;
    uint32_t fsw = (uint32_t)((frow >> 1) & 3);

    auto loadStage = [&](int stg, int c) {
        if (c < nCh) {
            uint32_t st = sb + stg * LSTG;
            int k0 = k0base + (c << 5);
            size_t abase = (size_t)(row0 + frow) * K + k0;
            size_t bbase = (size_t)(col0 + frow) * K + k0;
#pragma unroll
            for (int cc = 0; cc < 2; cc++) {
                int cl = fc0 + cc;
                uint32_t doff = (uint32_t)(frow << 6) + (((uint32_t)cl ^ fsw) << 4);
                cpasync16(st + doff,         Ahi + abase + (cl << 3));
                if (nsweep > 1)
                    cpasync16(st + 8192 + doff, Alo + abase + (cl << 3));
                cpasync16(st + 16384 + doff, Bt + bbase + (cl << 3));
            }
        }
        asm volatile("cp.async.commit_group;" ::: "memory");
    };

    int arow[4], brow[2];
    uint32_t asw[4], bsw[2];
#pragma unroll
    for (int mf = 0; mf < 4; mf++) {
        arow[mf] = (wm << 6) + (mf << 4) + (lane & 15);
        asw[mf] = (uint32_t)((arow[mf] >> 1) & 3);
    }
#pragma unroll
    for (int g = 0; g < 2; g++) {
        brow[g] = (wn << 5) + (g << 4) + (lane & 7) + (((lane >> 3) & 1) << 3);
        bsw[g] = (uint32_t)((brow[g] >> 1) & 3);
    }
    int kc = lane >> 4;

    loadStage(0, 0);
    loadStage(1, 1);

    int stg = 0;
    for (int c = 0; c < nCh; ++c) {
        asm volatile("cp.async.wait_group 1;" ::: "memory");
        __syncthreads();
        loadStage(stg == 0 ? 2 : stg - 1, c + 2);
        uint32_t st = sb + stg * LSTG;
#pragma unroll
        for (int ks = 0; ks < 2; ks++) {
            int cl = (ks << 1) + kc;
            uint32_t ah[4][4], bb[2][4];
#pragma unroll
            for (int mf = 0; mf < 4; mf++)
                ldsm4(ah[mf], st + (uint32_t)(arow[mf] << 6) + (((uint32_t)cl ^ asw[mf]) << 4));
#pragma unroll
            for (int g = 0; g < 2; g++)
                ldsm4(bb[g], st + 16384 + (uint32_t)(brow[g] << 6) + (((uint32_t)cl ^ bsw[g]) << 4));
#pragma unroll
            for (int mf = 0; mf < 4; mf++)
#pragma unroll
                for (int nf = 0; nf < 4; nf++)
                    mma16816h(acc[mf][nf], ah[mf], bb[nf >> 1][nf & 1], bb[nf >> 1][(nf & 1) + 2]);
            if (nsweep > 1) {
                uint32_t al[4][4];
#pragma unroll
                for (int mf = 0; mf < 4; mf++)
                    ldsm4(al[mf], st + 8192 + (uint32_t)(arow[mf] << 6) + (((uint32_t)cl ^ asw[mf]) << 4));
#pragma unroll
                for (int mf = 0; mf < 4; mf++)
#pragma unroll
                    for (int nf = 0; nf < 4; nf++)
                        mma16816h(acc[mf][nf], al[mf], bb[nf >> 1][nf & 1], bb[nf >> 1][(nf & 1) + 2]);
            }
        }
        stg = (stg == 2) ? 0 : stg + 1;
    }

    if (Cpart) {
        size_t plane = (size_t)blockIdx.z * (((size_t)gridDim.y << 7) * (size_t)N);
#pragma unroll
        for (int mf = 0; mf < 4; mf++) {
            int rbase = row0 + (wm << 6) + (mf << 4) + (lane >> 2);
#pragma unroll
            for (int nf = 0; nf < 4; nf++) {
                int cb = col0 + (wn << 5) + (nf << 3) + ((lane & 3) << 1);
#pragma unroll
                for (int half = 0; half < 2; half++) {
                    int r = rbase + (half << 3);
                    *(float2*)(Cpart + plane + (size_t)r * N + cb) =
                        make_float2(acc[mf][nf][half * 2], acc[mf][nf][half * 2 + 1]);
                }
            }
        }
        return;
    }
#pragma unroll
    for (int mf = 0; mf < 4; mf++) {
        int rbase = row0 + (wm << 6) + (mf << 4) + (lane >> 2);
#pragma unroll
        for (int nf = 0; nf < 4; nf++) {
            int cb = col0 + (wn << 5) + (nf << 3) + ((lane & 3) << 1);
            float b0 = bias ? bias[cb] : 0.f;
            float b1 = bias ? bias[cb + 1] : 0.f;
#pragma unroll
            for (int half = 0; half < 2; half++) {
                int r = rbase + (half << 3);
                float v0 = acc[mf][nf][half * 2 + 0] + b0;
                float v1 = acc[mf][nf][half * 2 + 1] + b1;
                size_t gi = (size_t)r * N + cb;
                if (Chi) {
                    __half2 h = __floats2half2_rn(v0, v1);
                    float2 hf = __half22float2(h);
                    __half2 l = __floats2half2_rn(v0 - hf.x, v1 - hf.y);
                    *(__half2*)(Chi + gi) = h;
                    *(__half2*)(Clo + gi) = l;
                } else {
                    *(float2*)(C + gi) = make_float2(v0, v1);
                }
            }
        }
    }
}

// ---------------- split-K reduce (W1 path: relu + fp16 hi/lo out) ------------
__global__ __launch_bounds__(256) void reduce_kernel(const float* __restrict__ parts,
                                                     int nsplit,
                                                     const float* __restrict__ bias,
                                                     __half* __restrict__ outHi,
                                                     __half* __restrict__ outLo,
                                                     int N) {
    size_t i = ((size_t)blockIdx.x * 256 + threadIdx.x) * 4;
    size_t plane = (size_t)BT * N;
    int col = (int)(i % N);
    float4 s = *(const float4*)(parts + i);
    for (int p = 1; p < nsplit; p++) {
        float4 t = *(const float4*)(parts + plane * p + i);
        s.x += t.x; s.y += t.y; s.z += t.z; s.w += t.w;
    }
    float4 b = *(const float4*)(bias + col);
    s.x = fmaxf(s.x + b.x, 0.f); s.y = fmaxf(s.y + b.y, 0.f);
    s.z = fmaxf(s.z + b.z, 0.f); s.w = fmaxf(s.w + b.w, 0.f);
    __half2 h0 = __floats2half2_rn(s.x, s.y);
    __half2 h1 = __floats2half2_rn(s.z, s.w);
    float2 f0 = __half22float2(h0), f1 = __half22float2(h1);
    __half2 l0 = __floats2half2_rn(s.x - f0.x, s.y - f0.y);
    __half2 l1 = __floats2half2_rn(s.z - f1.x, s.w - f1.y);
    *(__half2*)(outHi + i) = h0;
    *(__half2*)(outHi + i + 2) = h1;
    *(__half2*)(outLo + i) = l0;
    *(__half2*)(outLo + i + 2) = l1;
}

// ---------------- tensor-core flash attention (fp16 3-sweep) ------------------
// smem: Q 16K, K 16K, Vstage 16K, Vt 16K = 64KB. V loaded via cp.async rows
// then transposed smem->smem (conflict-free writes, 4-way-conflict 16B reads).
#define ATT_SMEM 65536
__global__ __launch_bounds__(128)
void attn_kernel(const __half* __restrict__ qkvhi,
                 const __half* __restrict__ qkvlo,
                 __half* __restrict__ ohi,
                 __half* __restrict__ olo) {
    extern __shared__ __align__(16) char smem[];
    uint32_t sb = smem_u32(smem);
    const uint32_t Q_HI = 0, Q_LO = 8192, K_HI = 16384, K_LO = 24576,
                   VS_HI = 32768, VS_LO = 40960, VT_HI = 49152, VT_LO = 57344;
    int tid = threadIdx.x, lane = tid & 31, w = tid >> 5;
    int qt = (int)gridDim.x - 1 - (int)blockIdx.x;   // heavy tiles first
    int bh = blockIdx.y;
    int bb = bh / H_, hh = bh % H_;
    size_t qrowbase = (size_t)(bb * T_ + (qt << 6));
    const int coff = hh * 64;
    int kc = lane >> 4;

    // ---- load Q tile hi/lo ----
    {
        int r0 = tid >> 1;
        int c0 = (tid & 1) << 2;
        size_t g = (qrowbase + r0) * (size_t)NQKV + coff;
#pragma unroll
        for (int i = 0; i < 4; i++) {
            int c = c0 + i;
            uint32_t d = (uint32_t)(r0 << 7) + (((uint32_t)(c ^ (r0 & 7))) << 4);
            cpasync16(sb + Q_HI + d, qkvhi + g + (c << 3));
            cpasync16(sb + Q_LO + d, qkvlo + g + (c << 3));
        }
        asm volatile("cp.async.commit_group;\n\tcp.async.wait_group 0;" ::: "memory");
    }
    __syncthreads();
    uint32_t qh[4][4], ql[4][4];
    {
        int aRow = (w << 4) + (lane & 15);
#pragma unroll
        for (int ks = 0; ks < 4; ks++) {
            int cl = (ks << 1) + kc;
            uint32_t ad = (uint32_t)(aRow << 7) + (((uint32_t)(cl ^ (aRow & 7))) << 4);
            ldsm4(qh[ks], sb + Q_HI + ad);
            ldsm4(ql[ks], sb + Q_LO + ad);
        }
    }

    float oacc[8][4] = {};
    float m1 = -INFINITY, m2 = -INFINITY, l1 = 0.f, l2 = 0.f;
    int r1 = lane >> 2;
    int rowg1 = (qt << 6) + (w << 4) + r1;
    int rowg2 = rowg1 + 8;

    for (int kt = 0; kt <= qt; kt++) {
        __syncthreads();   // prior tile consumers done
        size_t kbase = (size_t)(bb * T_ + (kt << 6));
        // K + V-stage fill (all cp.async, row-coalesced)
        {
            int r0 = tid >> 1;
            int c0 = (tid & 1) << 2;
            size_t gk = (kbase + r0) * (size_t)NQKV + E_ + coff;
            size_t gv = (kbase + r0) * (size_t)NQKV + 2 * E_ + coff;
#pragma unroll
            for (int i = 0; i < 4; i++) {
                int c = c0 + i;
                uint32_t d = (uint32_t)(r0 << 7) + (((uint32_t)(c ^ (r0 & 7))) << 4);
                cpasync16(sb + K_HI + d,  qkvhi + gk + (c << 3));
                cpasync16(sb + K_LO + d,  qkvlo + gk + (c << 3));
                cpasync16(sb + VS_HI + d, qkvhi + gv + (c << 3));
                cpasync16(sb + VS_LO + d, qkvlo + gv + (c << 3));
            }
            asm volatile("cp.async.commit_group;\n\tcp.async.wait_group 0;" ::: "memory");
        }
        __syncthreads();
        // transpose Vstage -> Vt (smem->smem)
        {
            int kvp = tid & 31;
            int dg0 = tid >> 5;
            int kv = kvp << 1;
#pragma unroll
            for (int t = 0; t < 2; t++) {
                int ch = dg0 + (t << 2);
                int d0 = ch << 3;
                uint32_t a0 = (uint32_t)(kv << 7) + (((uint32_t)ch ^ (uint32_t)(kv & 7)) << 4);
                uint32_t a1 = (uint32_t)((kv + 1) << 7) + (((uint32_t)ch ^ (uint32_t)((kv + 1) & 7)) << 4);
                uint4 h0 = *(const uint4*)(smem + VS_HI + a0);
                uint4 h1 = *(const uint4*)(smem + VS_HI + a1);
                uint4 l0 = *(const uint4*)(smem + VS_LO + a0);
                uint4 l1v = *(const uint4*)(smem + VS_LO + a1);
                const __half* ph0 = (const __half*)&h0;
                const __half* ph1 = (const __half*)&h1;
                const __half* pl0 = (const __half*)&l0;
                const __half* pl1 = (const __half*)&l1v;
#pragma unroll
                for (int j = 0; j < 8; j++) {
                    int d = d0 + j;
                    uint32_t ad = (uint32_t)(d << 7) +
                                  ((((uint32_t)(kvp >> 2) ^ (uint32_t)(d & 7)) << 4)) +
                                  ((uint32_t)(kvp & 3) << 2);
                    __half2 hw; hw.x = ph0[j]; hw.y = ph1[j];
                    __half2 lw; lw.x = pl0[j]; lw.y = pl1[j];
                    *(__half2*)(smem + VT_HI + ad) = hw;
                    *(__half2*)(smem + VT_LO + ad) = lw;
                }
            }
        }
        __syncthreads();

        // ---- S = Q K^T (3-sweep fp16) ----
        float sacc[8][4] = {};
#pragma unroll
        for (int ks = 0; ks < 4; ks++) {
            int cl = (ks << 1) + kc;
            uint32_t kh[4][4], kl2[4][4];
#pragma unroll
            for (int g = 0; g < 4; g++) {
                int bRow = (g << 4) + (lane & 7) + (((lane >> 3) & 1) << 3);
                uint32_t bd = (uint32_t)(bRow << 7) + (((uint32_t)(cl ^ (bRow & 7))) << 4);
                ldsm4(kh[g], sb + K_HI + bd);
                ldsm4(kl2[g], sb + K_LO + bd);
            }
#pragma unroll
            for (int g = 0; g < 4; g++)
#pragma unroll
                for (int nfp = 0; nfp < 2; nfp++)
                    mma16816h(sacc[2 * g + nfp], qh[ks], kh[g][nfp], kh[g][nfp + 2]);
#pragma unroll
            for (int g = 0; g < 4; g++)
#pragma unroll
                for (int nfp = 0; nfp < 2; nfp++)
                    mma16816h(sacc[2 * g + nfp], ql[ks], kh[g][nfp], kh[g][nfp + 2]);
#pragma unroll
            for (int g = 0; g < 4; g++)
#pragma unroll
                for (int nfp = 0; nfp < 2; nfp++)
                    mma16816h(sacc[2 * g + nfp], qh[ks], kl2[g][nfp], kl2[g][nfp + 2]);
        }
#pragma unroll
        for (int nf = 0; nf < 8; nf++) {
            sacc[nf][0] *= 0.125f; sacc[nf][1] *= 0.125f;
            sacc[nf][2] *= 0.125f; sacc[nf][3] *= 0.125f;
        }
        if (kt == qt) {
#pragma unroll
            for (int nf = 0; nf < 8; nf++) {
                int colb = (kt << 6) + (nf << 3) + ((lane & 3) << 1);
                if (colb > rowg1)     sacc[nf][0] = -INFINITY;
                if (colb + 1 > rowg1) sacc[nf][1] = -INFINITY;
                if (colb > rowg2)     sacc[nf][2] = -INFINITY;
                if (colb + 1 > rowg2) sacc[nf][3] = -INFINITY;
            }
        }
        // ---- online softmax ----
        float t1 = -INFINITY, t2 = -INFINITY;
#pragma unroll
        for (int nf = 0; nf < 8; nf++) {
            t1 = fmaxf(t1, fmaxf(sacc[nf][0], sacc[nf][1]));
            t2 = fmaxf(t2, fmaxf(sacc[nf][2], sacc[nf][3]));
        }
        t1 = fmaxf(t1, __shfl_xor_sync(0xffffffffu, t1, 1));
        t1 = fmaxf(t1, __shfl_xor_sync(0xffffffffu, t1, 2));
        t2 = fmaxf(t2, __shfl_xor_sync(0xffffffffu, t2, 1));
        t2 = fmaxf(t2, __shfl_xor_sync(0xffffffffu, t2, 2));
        float mn1 = fmaxf(m1, t1), mn2 = fmaxf(m2, t2);
        float a1 = __expf(m1 - mn1), a2 = __expf(m2 - mn2);
        float ps1 = 0.f, ps2 = 0.f;
#pragma unroll
        for (int nf = 0; nf < 8; nf++) {
            sacc[nf][0] = __expf(sacc[nf][0] - mn1);
            sacc[nf][1] = __expf(sacc[nf][1] - mn1);
            sacc[nf][2] = __expf(sacc[nf][2] - mn2);
            sacc[nf][3] = __expf(sacc[nf][3] - mn2);
            ps1 += sacc[nf][0] + sacc[nf][1];
            ps2 += sacc[nf][2] + sacc[nf][3];
        }
        ps1 += __shfl_xor_sync(0xffffffffu, ps1, 1);
        ps1 += __shfl_xor_sync(0xffffffffu, ps1, 2);
        ps2 += __shfl_xor_sync(0xffffffffu, ps2, 1);
        ps2 += __shfl_xor_sync(0xffffffffu, ps2, 2);
        l1 = l1 * a1 + ps1;
        l2 = l2 * a2 + ps2;
        m1 = mn1; m2 = mn2;
#pragma unroll
        for (int nf = 0; nf < 8; nf++) {
            oacc[nf][0] *= a1; oacc[nf][1] *= a1;
            oacc[nf][2] *= a2; oacc[nf][3] *= a2;
        }
        // ---- O += P V (3-sweep); P c-frags -> fp16 a-frags in regs ----
#pragma unroll
        for (int j = 0; j < 4; j++) {
            uint32_t pah[4], pal[4];
#pragma unroll
            for (int half = 0; half < 2; half++) {
                float x0 = sacc[2 * j + half][0], x1 = sacc[2 * j + half][1];
                float x2 = sacc[2 * j + half][2], x3 = sacc[2 * j + half][3];
                __half2 h01 = __floats2half2_rn(x0, x1);
                __half2 h23 = __floats2half2_rn(x2, x3);
                float2 f01 = __half22float2(h01), f23 = __half22float2(h23);
                __half2 lo01 = __floats2half2_rn(x0 - f01.x, x1 - f01.y);
                __half2 lo23 = __floats2half2_rn(x2 - f23.x, x3 - f23.y);
                pah[2 * half + 0] = *(uint32_t*)&h01;
                pah[2 * half + 1] = *(uint32_t*)&h23;
                pal[2 * half + 0] = *(uint32_t*)&lo01;
                pal[2 * half + 1] = *(uint32_t*)&lo23;
            }
            int cl = (j << 1) + kc;
            uint32_t vh[4][4], vl[4][4];
#pragma unroll
            for (int g = 0; g < 4; g++) {
                int bRow = (g << 4) + (lane & 7) + (((lane >> 3) & 1) << 3);
                uint32_t bd = (uint32_t)(bRow << 7) + (((uint32_t)(cl ^ (bRow & 7))) << 4);
                ldsm4(vh[g], sb + VT_HI + bd);
                ldsm4(vl[g], sb + VT_LO + bd);
            }
#pragma unroll
            for (int g = 0; g < 4; g++)
#pragma unroll
                for (int nfp = 0; nfp < 2; nfp++)
                    mma16816h(oacc[2 * g + nfp], pah, vh[g][nfp], vh[g][nfp + 2]);
#pragma unroll
            for (int g = 0; g < 4; g++)
#pragma unroll
                for (int nfp = 0; nfp < 2; nfp++)
                    mma16816h(oacc[2 * g + nfp], pal, vh[g][nfp], vh[g][nfp + 2]);
#pragma unroll
            for (int g = 0; g < 4; g++)
#pragma unroll
                for (int nfp = 0; nfp < 2; nfp++)
                    mma16816h(oacc[2 * g + nfp], pah, vl[g][nfp], vl[g][nfp + 2]);
        }
    }

    // ---- output (fp16 hi/lo) ----
    float li1 = 1.f / l1, li2 = 1.f / l2;
    size_t ob1 = (qrowbase + (w << 4) + r1) * (size_t)E_ + coff;
    size_t ob2 = ob1 + (size_t)8 * E_;
#pragma unroll
    for (int nf = 0; nf < 8; nf++) {
        int d = (nf << 3) + ((lane & 3) << 1);
        float v0 = oacc[nf][0] * li1, v1 = oacc[nf][1] * li1;
        __half2 h = __floats2half2_rn(v0, v1);
        float2 hf = __half22float2(h);
        __half2 lo = __floats2half2_rn(v0 - hf.x, v1 - hf.y);
        *(__half2*)(ohi + ob1 + d) = h;
        *(__half2*)(olo + ob1 + d) = lo;
        float v2 = oacc[nf][2] * li2, v3 = oacc[nf][3] * li2;
        __half2 h2 = __floats2half2_rn(v2, v3);
        float2 hf2 = __half22float2(h2);
        __half2 lo2 = __floats2half2_rn(v2 - hf2.x, v3 - hf2.y);
        *(__half2*)(ohi + ob2 + d) = h2;
        *(__half2*)(olo + ob2 + d) = lo2;
    }
}

// ---------------- loss ------------------------------------------------------
__global__ __launch_bounds__(256) void row_lse_kernel(const float* __restrict__ logits,
                                                      const int* __restrict__ targets,
                                                      float* __restrict__ rowloss) {
    int row = blockIdx.x, tid = threadIdx.x;
    const float* lr = logits + (size_t)row * V_;
    float mx = -INFINITY;
    for (int i = tid; i < V_; i += 256) mx = fmaxf(mx, lr[i]);
#pragma unroll
    for (int o = 16; o > 0; o >>= 1) mx = fmaxf(mx, __shfl_xor_sync(0xffffffffu, mx, o));
    __shared__ float sm[8];
    if ((tid & 31) == 0) sm[tid >> 5] = mx;
    __syncthreads();
    float m2 = -INFINITY;
#pragma unroll
    for (int i = 0; i < 8; i++) m2 = fmaxf(m2, sm[i]);
    float se = 0.f;
    for (int i = tid; i < V_; i += 256) se += __expf(lr[i] - m2);
#pragma unroll
    for (int o = 16; o > 0; o >>= 1) se += __shfl_xor_sync(0xffffffffu, se, o);
    __shared__ float ssum[8];
    if ((tid & 31) == 0) ssum[tid >> 5] = se;
    __syncthreads();
    if (tid == 0) {
        float tot = 0.f;
#pragma unroll
        for (int i = 0; i < 8; i++) tot += ssum[i];
        rowloss[row] = (logf(tot) + m2) - lr[targets[row]];
    }
}

__global__ __launch_bounds__(256) void loss_reduce_kernel(const float* __restrict__ rowloss,
                                                          float* __restrict__ out) {
    int tid = threadIdx.x;
    float s = 0.f;
    for (int i = tid; i < BT; i += 256) s += rowloss[i];
#pragma unroll
    for (int o = 16; o > 0; o >>= 1) s += __shfl_xor_sync(0xffffffffu, s, o);
    __shared__ float sm[8];
    if ((tid & 31) == 0) sm[tid >> 5] = s;
    __syncthreads();
    if (tid == 0) {
        float t = 0.f;
#pragma unroll
        for (int i = 0; i < 8; i++) t += sm[i];
        out[0] = t * (1.f / BT);
    }
}

// ---------------- launch ----------------------------------------------------
extern "C" void kernel_launch(void* const* d_in, const int* in_sizes, int n_in,
                              void* d_out, int out_size) {
    const int*   idx     = (const int*)d_in[0];
    const int*   targets = (const int*)d_in[1];
    const float* tok_emb = (const float*)d_in[2];
    const float* pos_emb = (const float*)d_in[3];
    const float* Wq  = (const float*)d_in[4];
    const float* bq  = (const float*)d_in[5];
    const float* Wk  = (const float*)d_in[6];
    const float* bk  = (const float*)d_in[7];
    const float* Wv  = (const float*)d_in[8];
    const float* bv  = (const float*)d_in[9];
    const float* Wo  = (const float*)d_in[10];
    const float* bo  = (const float*)d_in[11];
    const float* ln1g = (const float*)d_in[12];
    const float* ln1b = (const float*)d_in[13];
    const float* W1  = (const float*)d_in[14];
    const float* b1  = (const float*)d_in[15];
    const float* W2  = (const float*)d_in[16];
    const float* b2  = (const float*)d_in[17];
    const float* ln2g = (const float*)d_in[18];
    const float* ln2b = (const float*)d_in[19];
    const float* lnfg = (const float*)d_in[20];
    const float* lnfb = (const float*)d_in[21];
    const float* Wlm = (const float*)d_in[22];
    const float* blm = (const float*)d_in[23];
    float* out = (float*)d_out;

    float *px, *pbqkv, *ppart, *prl, *plg;
    __half *pqkvhi, *pqkvlo, *phhi, *phlo, *pohi, *polo, *pffhi, *pfflo, *pwth, *pwlmh;
    cudaGetSymbolAddress((void**)&px,     g_x);
    cudaGetSymbolAddress((void**)&pqkvhi, g_qkvhi);
    cudaGetSymbolAddress((void**)&pqkvlo, g_qkvlo);
    cudaGetSymbolAddress((void**)&phhi,   g_hhi);
    cudaGetSymbolAddress((void**)&phlo,   g_hlo);
    cudaGetSymbolAddress((void**)&pohi,   g_ohi);
    cudaGetSymbolAddress((void**)&polo,   g_olo);
    cudaGetSymbolAddress((void**)&pffhi,  g_ffhi);
    cudaGetSymbolAddress((void**)&pfflo,  g_fflo);
    cudaGetSymbolAddress((void**)&pbqkv,  g_bqkv);
    cudaGetSymbolAddress((void**)&ppart,  g_part);
    cudaGetSymbolAddress((void**)&pwth,   g_wth);
    cudaGetSymbolAddress((void**)&pwlmh,  g_wlmh);
    cudaGetSymbolAddress((void**)&prl,    g_rowloss);
    cudaGetSymbolAddress((void**)&plg,    g_logits_scratch);

    cudaFuncSetAttribute(gemm_h_kernel, cudaFuncAttributeMaxDynamicSharedMemorySize, GEMM_H_SMEM);
    cudaFuncSetAttribute(attn_kernel,   cudaFuncAttributeMaxDynamicSharedMemorySize, ATT_SMEM);

    const long long NLOG = (long long)BT * V_;
    float* logits = (out_size >= NLOG) ? out : plg;

    dim3 cb(32, 8);
    dim3 gQKVw(E_ / 32, NQKV / 32);
    dim3 gQKV(NQKV / 128, BT / 128);
    dim3 gWo(E_ / 128, BT / 128, 3);
    dim3 gW1(FF / 128, BT / 128, 2);
    dim3 gW2(E_ / 128, BT / 128, 3);
    dim3 gVd(V_ / 128, BT / 128);
    dim3 gAttn(T_ / 64, B_ * H_);
    int rF = BT * FF / 1024;

    for (int l = 0; l < L_; l++) {
        if (l == 0)
            embed_ln_kernel<<<BT, 256>>>(idx, tok_emb, pos_emb, ln1g, ln1b, px, phhi, phlo); // 0
        wconv_qkv_kernel<<<gQKVw, cb>>>(Wq, Wk, Wv, bq, bk, bv,
                                        pwth + OFF_QKV(l), pbqkv, l);                        // 1
        gemm_h_kernel<<<gQKV, 256, GEMM_H_SMEM>>>(phhi, phlo, pwth + OFF_QKV(l),             // 2
            pbqkv + l * NQKV, nullptr, pqkvhi, pqkvlo, nullptr, NQKV, E_, E_, 2);
        attn_kernel<<<gAttn, 128, ATT_SMEM>>>(pqkvhi, pqkvlo, pohi, polo);                   // 3 (= global 5)
        wconvt_h_kernel<<<dim3(E_ / 32, E_ / 32), cb>>>(Wo + (size_t)l * E_ * E_,
            pwth + OFF_O(l), E_, E_);
        gemm_h_kernel<<<gWo, 256, GEMM_H_SMEM>>>(pohi, polo, pwth + OFF_O(l),
            nullptr, nullptr, nullptr, nullptr, ppart, E_, E_, 256, 2);
        reduce_ln_kernel<<<BT, 256>>>(ppart, 3, bo + l * E_, px,
                                      ln2g + l * E_, ln2b + l * E_, phhi, phlo);
        wconvt_h_kernel<<<dim3(FF / 32, E_ / 32), cb>>>(W1 + (size_t)l * E_ * FF,
            pwth + OFF_W1(l), E_, FF);
        gemm_h_kernel<<<gW1, 256, GEMM_H_SMEM>>>(phhi, phlo, pwth + OFF_W1(l),
            nullptr, nullptr, nullptr, nullptr, ppart, FF, E_, 384, 2);
        reduce_kernel<<<rF, 256>>>(ppart, 2, b1 + l * FF, pffhi, pfflo, FF);
        wconvt_h_kernel<<<dim3(E_ / 32, FF / 32), cb>>>(W2 + (size_t)l * FF * E_,
            pwth + OFF_W2(l), FF, E_);
        gemm_h_kernel<<<gW2, 256, GEMM_H_SMEM>>>(pffhi, pfflo, pwth + OFF_W2(l),
            nullptr, nullptr, nullptr, nullptr, ppart, E_, FF, 1024, 2);
        if (l < L_ - 1)
            reduce_ln_kernel<<<BT, 256>>>(ppart, 3, b2 + l * E_, px,
                                          ln1g + (l + 1) * E_, ln1b + (l + 1) * E_, phhi, phlo);
        else
            reduce_ln_kernel<<<BT, 256>>>(ppart, 3, b2 + l * E_, px,
                                          lnfg, lnfb, phhi, phlo);
    }
    wconvt_h_kernel<<<dim3(V_ / 32, E_ / 32), cb>>>(Wlm, pwlmh, E_, V_);
    gemm_h_kernel<<<gVd, 256, GEMM_H_SMEM>>>(phhi, phlo, pwlmh, blm,
                                             logits, nullptr, nullptr, nullptr, V_, E_, E_, 1);

    // --- loss ---
    float* loss_dst = nullptr;
    if (out_size == 1)        loss_dst = out;
    else if (out_size > NLOG) loss_dst = out + NLOG;
    if (loss_dst) {
        row_lse_kernel<<<BT, 256>>>(logits, targets, prl);
        loss_reduce_kernel<<<1, 256>>>(prl, loss_dst);
    }
}

// round 13
// speedup vs baseline: 4.8738x; 1.0567x over previous
#include <cuda_runtime.h>
#include <cuda_bf16.h>
#include <cuda_fp16.h>
#include <math.h>
#include <stdint.h>

#define L_  4
#define H_  12
#define E_  768
#define HS_ 64
#define V_  32000
#define B_  2
#define T_  1024
#define BT  2048
#define FF  3072
#define NQKV 2304

// ---- weight scratch offsets (fp16 elements) ----
#define WPL 7077888ull
#define OFF_QKV(l) ((size_t)(l) * WPL)
#define OFF_O(l)   (OFF_QKV(l) + 1769472ull)
#define OFF_W1(l)  (OFF_QKV(l) + 2359296ull)
#define OFF_W2(l)  (OFF_QKV(l) + 4718592ull)
#define WTOT       ((size_t)4 * WPL)

// ---------------- scratch (static device globals) ----------------------------
__device__ float g_x[BT * E_];
__device__ __half g_qkvhi[BT * NQKV];
__device__ __half g_qkvlo[BT * NQKV];
__device__ __half g_hhi[BT * E_];
__device__ __half g_hlo[BT * E_];
__device__ __half g_ohi[BT * E_];
__device__ __half g_olo[BT * E_];
__device__ __half g_ffhi[BT * FF];
__device__ __half g_fflo[BT * FF];
__device__ float g_bqkv[L_ * NQKV];
__device__ float g_part[2ull * BT * FF];
__device__ __half g_wth[WTOT];
__device__ __half g_wlmh[(size_t)V_ * E_];
__device__ float g_rowloss[BT];
__device__ float g_logits_scratch[(size_t)BT * V_];

// ---------------- PTX helpers ------------------------------------------------
__device__ __forceinline__ uint32_t smem_u32(const void* p) {
    uint32_t a;
    asm("{ .reg .u64 t; cvta.to.shared.u64 t, %1; cvt.u32.u64 %0, t; }" : "=r"(a) : "l"(p));
    return a;
}
__device__ __forceinline__ void mma16816h(float* c, const uint32_t* a, uint32_t b0, uint32_t b1) {
    asm volatile(
        "mma.sync.aligned.m16n8k16.row.col.f32.f16.f16.f32 "
        "{%0,%1,%2,%3}, {%4,%5,%6,%7}, {%8,%9}, {%0,%1,%2,%3};"
        : "+f"(c[0]), "+f"(c[1]), "+f"(c[2]), "+f"(c[3])
        : "r"(a[0]), "r"(a[1]), "r"(a[2]), "r"(a[3]), "r"(b0), "r"(b1));
}
__device__ __forceinline__ void ldsm4(uint32_t* r, uint32_t addr) {
    asm volatile("ldmatrix.sync.aligned.m8n8.x4.shared.b16 {%0,%1,%2,%3}, [%4];"
                 : "=r"(r[0]), "=r"(r[1]), "=r"(r[2]), "=r"(r[3]) : "r"(addr));
}
__device__ __forceinline__ void cpasync16(uint32_t dst, const void* src) {
    asm volatile("cp.async.cg.shared.global [%0], [%1], 16;" :: "r"(dst), "l"(src));
}

// ---------------- fused QKV weight repack+transpose -> fp16 + bias concat ----
__global__ __launch_bounds__(256) void wconv_qkv_kernel(const float* __restrict__ Wq,
                                                        const float* __restrict__ Wk,
                                                        const float* __restrict__ Wv,
                                                        const float* __restrict__ bq,
                                                        const float* __restrict__ bk,
                                                        const float* __restrict__ bv,
                                                        __half* __restrict__ Wt,
                                                        float* __restrict__ bqkv,
                                                        int l) {
    __shared__ float s[32][33];
    int n0 = blockIdx.y * 32, e0 = blockIdx.x * 32;
    int tx = threadIdx.x, ty = threadIdx.y;
    int sel = n0 / E_;
    int nn = n0 % E_;
    int h = nn >> 6, hs0 = nn & 63;
    const float* src = sel == 0 ? Wq : (sel == 1 ? Wk : Wv);
    const float* base = src + ((size_t)(l * H_ + h) * E_) * 64;
#pragma unroll
    for (int i = 0; i < 4; i++) {
        int e = ty + 8 * i;
        s[e][tx] = base[(size_t)(e0 + e) * 64 + hs0 + tx];
    }
    __syncthreads();
#pragma unroll
    for (int i = 0; i < 4; i++) {
        int nl = ty + 8 * i;
        Wt[(size_t)(n0 + nl) * E_ + e0 + tx] = __float2half_rn(s[tx][nl]);
    }
    int gid = (blockIdx.y * gridDim.x + blockIdx.x) * 256 + ty * 32 + tx;
    if (gid < NQKV) {
        float v;
        if (gid < E_)            v = bq[l * E_ + gid];
        else if (gid < 2 * E_)   v = bk[l * E_ + gid - E_];
        else                     v = bv[l * E_ + gid - 2 * E_];
        bqkv[l * NQKV + gid] = v;
    }
}

// ---------------- generic weight transpose -> single fp16 --------------------
__global__ __launch_bounds__(256) void wconvt_h_kernel(const float* __restrict__ W,
                                                       __half* __restrict__ Wt,
                                                       int K, int N) {
    __shared__ float s[32][33];
    int k0 = blockIdx.y * 32, n0 = blockIdx.x * 32;
    int tx = threadIdx.x, ty = threadIdx.y;
#pragma unroll
    for (int i = 0; i < 4; i++)
        s[ty + 8 * i][tx] = W[(size_t)(k0 + ty + 8 * i) * N + n0 + tx];
    __syncthreads();
#pragma unroll
    for (int i = 0; i < 4; i++) {
        int n = ty + 8 * i;
        Wt[(size_t)(n0 + n) * K + k0 + tx] = __float2half_rn(s[tx][n]);
    }
}

// ---------------- fused embedding + layernorm -> fp16 hi/lo -------------------
__global__ __launch_bounds__(256) void embed_ln_kernel(const int* __restrict__ idx,
                                                       const float* __restrict__ tok,
                                                       const float* __restrict__ pos,
                                                       const float* __restrict__ g,
                                                       const float* __restrict__ b,
                                                       float* __restrict__ x,
                                                       __half* __restrict__ hi,
                                                       __half* __restrict__ lo) {
    int row = blockIdx.x;
    int tid = threadIdx.x;
    int token = idx[row];
    int tp = row % T_;
    size_t rb = (size_t)row * E_;
    float v[3], s = 0.f, sq = 0.f;
#pragma unroll
    for (int i = 0; i < 3; i++) {
        int e = tid + (i << 8);
        float t = tok[(size_t)token * E_ + e] + pos[(size_t)tp * E_ + e];
        x[rb + e] = t;
        v[i] = t; s += t; sq += t * t;
    }
#pragma unroll
    for (int o = 16; o > 0; o >>= 1) {
        s  += __shfl_xor_sync(0xffffffffu, s, o);
        sq += __shfl_xor_sync(0xffffffffu, sq, o);
    }
    __shared__ float ss[8], ssq[8];
    if ((tid & 31) == 0) { ss[tid >> 5] = s; ssq[tid >> 5] = sq; }
    __syncthreads();
    s = 0.f; sq = 0.f;
#pragma unroll
    for (int i = 0; i < 8; i++) { s += ss[i]; sq += ssq[i]; }
    float mean = s * (1.f / E_);
    float var  = sq * (1.f / E_) - mean * mean;
    float rstd = rsqrtf(var + 1e-5f);
#pragma unroll
    for (int i = 0; i < 3; i++) {
        int e = tid + (i << 8);
        float y = (v[i] - mean) * rstd * g[e] + b[e];
        __half h = __float2half_rn(y);
        hi[rb + e] = h;
        lo[rb + e] = __float2half_rn(y - __half2float(h));
    }
}

// ---------------- fused split-K reduce + residual + layernorm (fp16 out) -----
__global__ __launch_bounds__(256) void reduce_ln_kernel(const float* __restrict__ parts,
                                                        int nsplit,
                                                        const float* __restrict__ bias,
                                                        float* __restrict__ x,
                                                        const float* __restrict__ g,
                                                        const float* __restrict__ b,
                                                        __half* __restrict__ hi,
                                                        __half* __restrict__ lo) {
    int row = blockIdx.x, tid = threadIdx.x;
    size_t rb = (size_t)row * E_;
    const size_t plane = (size_t)BT * E_;
    float v[3], s = 0.f, sq = 0.f;
#pragma unroll
    for (int i = 0; i < 3; i++) {
        int e = tid + (i << 8);
        size_t ix = rb + e;
        float t = parts[ix];
        for (int p = 1; p < nsplit; p++) t += parts[plane * p + ix];
        t += bias[e] + x[ix];
        x[ix] = t;
        v[i] = t; s += t; sq += t * t;
    }
#pragma unroll
    for (int o = 16; o > 0; o >>= 1) {
        s  += __shfl_xor_sync(0xffffffffu, s, o);
        sq += __shfl_xor_sync(0xffffffffu, sq, o);
    }
    __shared__ float ss[8], ssq[8];
    if ((tid & 31) == 0) { ss[tid >> 5] = s; ssq[tid >> 5] = sq; }
    __syncthreads();
    s = 0.f; sq = 0.f;
#pragma unroll
    for (int i = 0; i < 8; i++) { s += ss[i]; sq += ssq[i]; }
    float mean = s * (1.f / E_);
    float var  = sq * (1.f / E_) - mean * mean;
    float rstd = rsqrtf(var + 1e-5f);
#pragma unroll
    for (int i = 0; i < 3; i++) {
        int e = tid + (i << 8);
        float y = (v[i] - mean) * rstd * g[e] + b[e];
        __half h = __float2half_rn(y);
        hi[rb + e] = h;
        lo[rb + e] = __float2half_rn(y - __half2float(h));
    }
}

// ---------------- fp16 tensor-core GEMM (1/2 sweeps, 4 stages) ----------------
#define LSTG 24576
#define GEMM_H_SMEM (4 * LSTG)
__global__ __launch_bounds__(256, 2)
void gemm_h_kernel(const __half* __restrict__ Ahi,
                   const __half* __restrict__ Alo,
                   const __half* __restrict__ Bt,
                   const float* __restrict__ bias,
                   float* __restrict__ C,
                   __half* __restrict__ Chi,
                   __half* __restrict__ Clo,
                   float* __restrict__ Cpart,
                   int N, int K, int kslen, int nsweep) {
    extern __shared__ __align__(16) char smem[];
    int tid = threadIdx.x, lane = tid & 31, wid = tid >> 5;
    int wm = wid >> 2, wn = wid & 3;
    int row0 = blockIdx.y << 7, col0 = blockIdx.x << 7;
    int k0base = blockIdx.z * kslen;
    uint32_t sb = smem_u32(smem);

    float acc[4][4][4] = {};
    const int nCh = kslen >> 5;
    int frow = tid >> 1;
    int fc0 = (tid & 1) << 1;
    uint32_t fsw = (uint32_t)((frow >> 1) & 3);

    auto loadStage = [&](int stg, int c) {
        if (c < nCh) {
            uint32_t st = sb + stg * LSTG;
            int k0 = k0base + (c << 5);
            size_t abase = (size_t)(row0 + frow) * K + k0;
            size_t bbase = (size_t)(col0 + frow) * K + k0;
#pragma unroll
            for (int cc = 0; cc < 2; cc++) {
                int cl = fc0 + cc;
                uint32_t doff = (uint32_t)(frow << 6) + (((uint32_t)cl ^ fsw) << 4);
                cpasync16(st + doff,         Ahi + abase + (cl << 3));
                if (nsweep > 1)
                    cpasync16(st + 8192 + doff, Alo + abase + (cl << 3));
                cpasync16(st + 16384 + doff, Bt + bbase + (cl << 3));
            }
        }
        asm volatile("cp.async.commit_group;" ::: "memory");
    };

    int arow[4], brow[2];
    uint32_t asw[4], bsw[2];
#pragma unroll
    for (int mf = 0; mf < 4; mf++) {
        arow[mf] = (wm << 6) + (mf << 4) + (lane & 15);
        asw[mf] = (uint32_t)((arow[mf] >> 1) & 3);
    }
#pragma unroll
    for (int g = 0; g < 2; g++) {
        brow[g] = (wn << 5) + (g << 4) + (lane & 7) + (((lane >> 3) & 1) << 3);
        bsw[g] = (uint32_t)((brow[g] >> 1) & 3);
    }
    int kc = lane >> 4;

    loadStage(0, 0);
    loadStage(1, 1);
    loadStage(2, 2);

    int stg = 0;
    for (int c = 0; c < nCh; ++c) {
        asm volatile("cp.async.wait_group 2;" ::: "memory");
        __syncthreads();
        loadStage((stg + 3) & 3, c + 3);
        uint32_t st = sb + stg * LSTG;
#pragma unroll
        for (int ks = 0; ks < 2; ks++) {
            int cl = (ks << 1) + kc;
            uint32_t ah[4][4], bb[2][4];
#pragma unroll
            for (int mf = 0; mf < 4; mf++)
                ldsm4(ah[mf], st + (uint32_t)(arow[mf] << 6) + (((uint32_t)cl ^ asw[mf]) << 4));
#pragma unroll
            for (int g = 0; g < 2; g++)
                ldsm4(bb[g], st + 16384 + (uint32_t)(brow[g] << 6) + (((uint32_t)cl ^ bsw[g]) << 4));
#pragma unroll
            for (int mf = 0; mf < 4; mf++)
#pragma unroll
                for (int nf = 0; nf < 4; nf++)
                    mma16816h(acc[mf][nf], ah[mf], bb[nf >> 1][nf & 1], bb[nf >> 1][(nf & 1) + 2]);
            if (nsweep > 1) {
                uint32_t al[4][4];
#pragma unroll
                for (int mf = 0; mf < 4; mf++)
                    ldsm4(al[mf], st + 8192 + (uint32_t)(arow[mf] << 6) + (((uint32_t)cl ^ asw[mf]) << 4));
#pragma unroll
                for (int mf = 0; mf < 4; mf++)
#pragma unroll
                    for (int nf = 0; nf < 4; nf++)
                        mma16816h(acc[mf][nf], al[mf], bb[nf >> 1][nf & 1], bb[nf >> 1][(nf & 1) + 2]);
            }
        }
        stg = (stg + 1) & 3;
    }

    if (Cpart) {
        size_t plane = (size_t)blockIdx.z * (((size_t)gridDim.y << 7) * (size_t)N);
#pragma unroll
        for (int mf = 0; mf < 4; mf++) {
            int rbase = row0 + (wm << 6) + (mf << 4) + (lane >> 2);
#pragma unroll
            for (int nf = 0; nf < 4; nf++) {
                int cb = col0 + (wn << 5) + (nf << 3) + ((lane & 3) << 1);
#pragma unroll
                for (int half = 0; half < 2; half++) {
                    int r = rbase + (half << 3);
                    *(float2*)(Cpart + plane + (size_t)r * N + cb) =
                        make_float2(acc[mf][nf][half * 2], acc[mf][nf][half * 2 + 1]);
                }
            }
        }
        return;
    }
#pragma unroll
    for (int mf = 0; mf < 4; mf++) {
        int rbase = row0 + (wm << 6) + (mf << 4) + (lane >> 2);
#pragma unroll
        for (int nf = 0; nf < 4; nf++) {
            int cb = col0 + (wn << 5) + (nf << 3) + ((lane & 3) << 1);
            float b0 = bias ? bias[cb] : 0.f;
            float b1 = bias ? bias[cb + 1] : 0.f;
#pragma unroll
            for (int half = 0; half < 2; half++) {
                int r = rbase + (half << 3);
                float v0 = acc[mf][nf][half * 2 + 0] + b0;
                float v1 = acc[mf][nf][half * 2 + 1] + b1;
                size_t gi = (size_t)r * N + cb;
                if (Chi) {
                    __half2 h = __floats2half2_rn(v0, v1);
                    float2 hf = __half22float2(h);
                    __half2 l = __floats2half2_rn(v0 - hf.x, v1 - hf.y);
                    *(__half2*)(Chi + gi) = h;
                    *(__half2*)(Clo + gi) = l;
                } else {
                    *(float2*)(C + gi) = make_float2(v0, v1);
                }
            }
        }
    }
}

// ---------------- split-K reduce (W1 path: relu + fp16 hi/lo out) ------------
__global__ __launch_bounds__(256) void reduce_kernel(const float* __restrict__ parts,
                                                     int nsplit,
                                                     const float* __restrict__ bias,
                                                     __half* __restrict__ outHi,
                                                     __half* __restrict__ outLo,
                                                     int N) {
    size_t i = ((size_t)blockIdx.x * 256 + threadIdx.x) * 4;
    size_t plane = (size_t)BT * N;
    int col = (int)(i % N);
    float4 s = *(const float4*)(parts + i);
    for (int p = 1; p < nsplit; p++) {
        float4 t = *(const float4*)(parts + plane * p + i);
        s.x += t.x; s.y += t.y; s.z += t.z; s.w += t.w;
    }
    float4 b = *(const float4*)(bias + col);
    s.x = fmaxf(s.x + b.x, 0.f); s.y = fmaxf(s.y + b.y, 0.f);
    s.z = fmaxf(s.z + b.z, 0.f); s.w = fmaxf(s.w + b.w, 0.f);
    __half2 h0 = __floats2half2_rn(s.x, s.y);
    __half2 h1 = __floats2half2_rn(s.z, s.w);
    float2 f0 = __half22float2(h0), f1 = __half22float2(h1);
    __half2 l0 = __floats2half2_rn(s.x - f0.x, s.y - f0.y);
    __half2 l1 = __floats2half2_rn(s.z - f1.x, s.w - f1.y);
    *(__half2*)(outHi + i) = h0;
    *(__half2*)(outHi + i + 2) = h1;
    *(__half2*)(outLo + i) = l0;
    *(__half2*)(outLo + i + 2) = l1;
}

// ---------------- tensor-core flash attention (fp16 2-sweep, 40KB smem) ------
// S = (q_hi+q_lo)·k_hi ; O += (p_hi+p_lo)·v_hi.  K/V lo never loaded.
#define ATT_SMEM 40960
__global__ __launch_bounds__(128)
void attn_kernel(const __half* __restrict__ qkvhi,
                 const __half* __restrict__ qkvlo,
                 __half* __restrict__ ohi,
                 __half* __restrict__ olo) {
    extern __shared__ __align__(16) char smem[];
    uint32_t sb = smem_u32(smem);
    const uint32_t Q_HI = 0, Q_LO = 8192, K_HI = 16384, VS_HI = 24576, VT_HI = 32768;
    int tid = threadIdx.x, lane = tid & 31, w = tid >> 5;
    int qt = (int)gridDim.x - 1 - (int)blockIdx.x;   // heavy tiles first
    int bh = blockIdx.y;
    int bb = bh / H_, hh = bh % H_;
    size_t qrowbase = (size_t)(bb * T_ + (qt << 6));
    const int coff = hh * 64;
    int kc = lane >> 4;

    // ---- load Q tile hi/lo ----
    {
        int r0 = tid >> 1;
        int c0 = (tid & 1) << 2;
        size_t g = (qrowbase + r0) * (size_t)NQKV + coff;
#pragma unroll
        for (int i = 0; i < 4; i++) {
            int c = c0 + i;
            uint32_t d = (uint32_t)(r0 << 7) + (((uint32_t)(c ^ (r0 & 7))) << 4);
            cpasync16(sb + Q_HI + d, qkvhi + g + (c << 3));
            cpasync16(sb + Q_LO + d, qkvlo + g + (c << 3));
        }
        asm volatile("cp.async.commit_group;\n\tcp.async.wait_group 0;" ::: "memory");
    }
    __syncthreads();
    uint32_t qh[4][4], ql[4][4];
    {
        int aRow = (w << 4) + (lane & 15);
#pragma unroll
        for (int ks = 0; ks < 4; ks++) {
            int cl = (ks << 1) + kc;
            uint32_t ad = (uint32_t)(aRow << 7) + (((uint32_t)(cl ^ (aRow & 7))) << 4);
            ldsm4(qh[ks], sb + Q_HI + ad);
            ldsm4(ql[ks], sb + Q_LO + ad);
        }
    }

    float oacc[8][4] = {};
    float m1 = -INFINITY, m2 = -INFINITY, l1 = 0.f, l2 = 0.f;
    int r1 = lane >> 2;
    int rowg1 = (qt << 6) + (w << 4) + r1;
    int rowg2 = rowg1 + 8;

    for (int kt = 0; kt <= qt; kt++) {
        __syncthreads();
        size_t kbase = (size_t)(bb * T_ + (kt << 6));
        // K + V-stage fill (hi only, cp.async row-coalesced)
        {
            int r0 = tid >> 1;
            int c0 = (tid & 1) << 2;
            size_t gk = (kbase + r0) * (size_t)NQKV + E_ + coff;
            size_t gv = (kbase + r0) * (size_t)NQKV + 2 * E_ + coff;
#pragma unroll
            for (int i = 0; i < 4; i++) {
                int c = c0 + i;
                uint32_t d = (uint32_t)(r0 << 7) + (((uint32_t)(c ^ (r0 & 7))) << 4);
                cpasync16(sb + K_HI + d,  qkvhi + gk + (c << 3));
                cpasync16(sb + VS_HI + d, qkvhi + gv + (c << 3));
            }
            asm volatile("cp.async.commit_group;\n\tcp.async.wait_group 0;" ::: "memory");
        }
        __syncthreads();
        // transpose Vstage -> Vt (hi only)
        {
            int kvp = tid & 31;
            int dg0 = tid >> 5;
            int kv = kvp << 1;
#pragma unroll
            for (int t = 0; t < 2; t++) {
                int ch = dg0 + (t << 2);
                int d0 = ch << 3;
                uint32_t a0 = (uint32_t)(kv << 7) + (((uint32_t)ch ^ (uint32_t)(kv & 7)) << 4);
                uint32_t a1 = (uint32_t)((kv + 1) << 7) + (((uint32_t)ch ^ (uint32_t)((kv + 1) & 7)) << 4);
                uint4 h0 = *(const uint4*)(smem + VS_HI + a0);
                uint4 h1 = *(const uint4*)(smem + VS_HI + a1);
                const __half* ph0 = (const __half*)&h0;
                const __half* ph1 = (const __half*)&h1;
#pragma unroll
                for (int j = 0; j < 8; j++) {
                    int d = d0 + j;
                    uint32_t ad = (uint32_t)(d << 7) +
                                  ((((uint32_t)(kvp >> 2) ^ (uint32_t)(d & 7)) << 4)) +
                                  ((uint32_t)(kvp & 3) << 2);
                    __half2 hw; hw.x = ph0[j]; hw.y = ph1[j];
                    *(__half2*)(smem + VT_HI + ad) = hw;
                }
            }
        }
        __syncthreads();

        // ---- S = Q K^T (2-sweep fp16) ----
        float sacc[8][4] = {};
#pragma unroll
        for (int ks = 0; ks < 4; ks++) {
            int cl = (ks << 1) + kc;
            uint32_t kh[4][4];
#pragma unroll
            for (int g = 0; g < 4; g++) {
                int bRow = (g << 4) + (lane & 7) + (((lane >> 3) & 1) << 3);
                uint32_t bd = (uint32_t)(bRow << 7) + (((uint32_t)(cl ^ (bRow & 7))) << 4);
                ldsm4(kh[g], sb + K_HI + bd);
            }
#pragma unroll
            for (int g = 0; g < 4; g++)
#pragma unroll
                for (int nfp = 0; nfp < 2; nfp++)
                    mma16816h(sacc[2 * g + nfp], qh[ks], kh[g][nfp], kh[g][nfp + 2]);
#pragma unroll
            for (int g = 0; g < 4; g++)
#pragma unroll
                for (int nfp = 0; nfp < 2; nfp++)
                    mma16816h(sacc[2 * g + nfp], ql[ks], kh[g][nfp], kh[g][nfp + 2]);
        }
#pragma unroll
        for (int nf = 0; nf < 8; nf++) {
            sacc[nf][0] *= 0.125f; sacc[nf][1] *= 0.125f;
            sacc[nf][2] *= 0.125f; sacc[nf][3] *= 0.125f;
        }
        if (kt == qt) {
#pragma unroll
            for (int nf = 0; nf < 8; nf++) {
                int colb = (kt << 6) + (nf << 3) + ((lane & 3) << 1);
                if (colb > rowg1)     sacc[nf][0] = -INFINITY;
                if (colb + 1 > rowg1) sacc[nf][1] = -INFINITY;
                if (colb > rowg2)     sacc[nf][2] = -INFINITY;
                if (colb + 1 > rowg2) sacc[nf][3] = -INFINITY;
            }
        }
        // ---- online softmax ----
        float t1 = -INFINITY, t2 = -INFINITY;
#pragma unroll
        for (int nf = 0; nf < 8; nf++) {
            t1 = fmaxf(t1, fmaxf(sacc[nf][0], sacc[nf][1]));
            t2 = fmaxf(t2, fmaxf(sacc[nf][2], sacc[nf][3]));
        }
        t1 = fmaxf(t1, __shfl_xor_sync(0xffffffffu, t1, 1));
        t1 = fmaxf(t1, __shfl_xor_sync(0xffffffffu, t1, 2));
        t2 = fmaxf(t2, __shfl_xor_sync(0xffffffffu, t2, 1));
        t2 = fmaxf(t2, __shfl_xor_sync(0xffffffffu, t2, 2));
        float mn1 = fmaxf(m1, t1), mn2 = fmaxf(m2, t2);
        float a1 = __expf(m1 - mn1), a2 = __expf(m2 - mn2);
        float ps1 = 0.f, ps2 = 0.f;
#pragma unroll
        for (int nf = 0; nf < 8; nf++) {
            sacc[nf][0] = __expf(sacc[nf][0] - mn1);
            sacc[nf][1] = __expf(sacc[nf][1] - mn1);
            sacc[nf][2] = __expf(sacc[nf][2] - mn2);
            sacc[nf][3] = __expf(sacc[nf][3] - mn2);
            ps1 += sacc[nf][0] + sacc[nf][1];
            ps2 += sacc[nf][2] + sacc[nf][3];
        }
        ps1 += __shfl_xor_sync(0xffffffffu, ps1, 1);
        ps1 += __shfl_xor_sync(0xffffffffu, ps1, 2);
        ps2 += __shfl_xor_sync(0xffffffffu, ps2, 1);
        ps2 += __shfl_xor_sync(0xffffffffu, ps2, 2);
        l1 = l1 * a1 + ps1;
        l2 = l2 * a2 + ps2;
        m1 = mn1; m2 = mn2;
#pragma unroll
        for (int nf = 0; nf < 8; nf++) {
            oacc[nf][0] *= a1; oacc[nf][1] *= a1;
            oacc[nf][2] *= a2; oacc[nf][3] *= a2;
        }
        // ---- O += P V (2-sweep); P hi/lo split in regs ----
#pragma unroll
        for (int j = 0; j < 4; j++) {
            uint32_t pah[4], pal[4];
#pragma unroll
            for (int half = 0; half < 2; half++) {
                float x0 = sacc[2 * j + half][0], x1 = sacc[2 * j + half][1];
                float x2 = sacc[2 * j + half][2], x3 = sacc[2 * j + half][3];
                __half2 h01 = __floats2half2_rn(x0, x1);
                __half2 h23 = __floats2half2_rn(x2, x3);
                float2 f01 = __half22float2(h01), f23 = __half22float2(h23);
                __half2 lo01 = __floats2half2_rn(x0 - f01.x, x1 - f01.y);
                __half2 lo23 = __floats2half2_rn(x2 - f23.x, x3 - f23.y);
                pah[2 * half + 0] = *(uint32_t*)&h01;
                pah[2 * half + 1] = *(uint32_t*)&h23;
                pal[2 * half + 0] = *(uint32_t*)&lo01;
                pal[2 * half + 1] = *(uint32_t*)&lo23;
            }
            int cl = (j << 1) + kc;
            uint32_t vh[4][4];
#pragma unroll
            for (int g = 0; g < 4; g++) {
                int bRow = (g << 4) + (lane & 7) + (((lane >> 3) & 1) << 3);
                uint32_t bd = (uint32_t)(bRow << 7) + (((uint32_t)(cl ^ (bRow & 7))) << 4);
                ldsm4(vh[g], sb + VT_HI + bd);
            }
#pragma unroll
            for (int g = 0; g < 4; g++)
#pragma unroll
                for (int nfp = 0; nfp < 2; nfp++)
                    mma16816h(oacc[2 * g + nfp], pah, vh[g][nfp], vh[g][nfp + 2]);
#pragma unroll
            for (int g = 0; g < 4; g++)
#pragma unroll
                for (int nfp = 0; nfp < 2; nfp++)
                    mma16816h(oacc[2 * g + nfp], pal, vh[g][nfp], vh[g][nfp + 2]);
        }
    }

    // ---- output (fp16 hi/lo) ----
    float li1 = 1.f / l1, li2 = 1.f / l2;
    size_t ob1 = (qrowbase + (w << 4) + r1) * (size_t)E_ + coff;
    size_t ob2 = ob1 + (size_t)8 * E_;
#pragma unroll
    for (int nf = 0; nf < 8; nf++) {
        int d = (nf << 3) + ((lane & 3) << 1);
        float v0 = oacc[nf][0] * li1, v1 = oacc[nf][1] * li1;
        __half2 h = __floats2half2_rn(v0, v1);
        float2 hf = __half22float2(h);
        __half2 lo = __floats2half2_rn(v0 - hf.x, v1 - hf.y);
        *(__half2*)(ohi + ob1 + d) = h;
        *(__half2*)(olo + ob1 + d) = lo;
        float v2 = oacc[nf][2] * li2, v3 = oacc[nf][3] * li2;
        __half2 h2 = __floats2half2_rn(v2, v3);
        float2 hf2 = __half22float2(h2);
        __half2 lo2 = __floats2half2_rn(v2 - hf2.x, v3 - hf2.y);
        *(__half2*)(ohi + ob2 + d) = h2;
        *(__half2*)(olo + ob2 + d) = lo2;
    }
}

// ---------------- loss ------------------------------------------------------
__global__ __launch_bounds__(256) void row_lse_kernel(const float* __restrict__ logits,
                                                      const int* __restrict__ targets,
                                                      float* __restrict__ rowloss) {
    int row = blockIdx.x, tid = threadIdx.x;
    const float* lr = logits + (size_t)row * V_;
    float mx = -INFINITY;
    for (int i = tid; i < V_; i += 256) mx = fmaxf(mx, lr[i]);
#pragma unroll
    for (int o = 16; o > 0; o >>= 1) mx = fmaxf(mx, __shfl_xor_sync(0xffffffffu, mx, o));
    __shared__ float sm[8];
    if ((tid & 31) == 0) sm[tid >> 5] = mx;
    __syncthreads();
    float m2 = -INFINITY;
#pragma unroll
    for (int i = 0; i < 8; i++) m2 = fmaxf(m2, sm[i]);
    float se = 0.f;
    for (int i = tid; i < V_; i += 256) se += __expf(lr[i] - m2);
#pragma unroll
    for (int o = 16; o > 0; o >>= 1) se += __shfl_xor_sync(0xffffffffu, se, o);
    __shared__ float ssum[8];
    if ((tid & 31) == 0) ssum[tid >> 5] = se;
    __syncthreads();
    if (tid == 0) {
        float tot = 0.f;
#pragma unroll
        for (int i = 0; i < 8; i++) tot += ssum[i];
        rowloss[row] = (logf(tot) + m2) - lr[targets[row]];
    }
}

__global__ __launch_bounds__(256) void loss_reduce_kernel(const float* __restrict__ rowloss,
                                                          float* __restrict__ out) {
    int tid = threadIdx.x;
    float s = 0.f;
    for (int i = tid; i < BT; i += 256) s += rowloss[i];
#pragma unroll
    for (int o = 16; o > 0; o >>= 1) s += __shfl_xor_sync(0xffffffffu, s, o);
    __shared__ float sm[8];
    if ((tid & 31) == 0) sm[tid >> 5] = s;
    __syncthreads();
    if (tid == 0) {
        float t = 0.f;
#pragma unroll
        for (int i = 0; i < 8; i++) t += sm[i];
        out[0] = t * (1.f / BT);
    }
}

// ---------------- launch ----------------------------------------------------
extern "C" void kernel_launch(void* const* d_in, const int* in_sizes, int n_in,
                              void* d_out, int out_size) {
    const int*   idx     = (const int*)d_in[0];
    const int*   targets = (const int*)d_in[1];
    const float* tok_emb = (const float*)d_in[2];
    const float* pos_emb = (const float*)d_in[3];
    const float* Wq  = (const float*)d_in[4];
    const float* bq  = (const float*)d_in[5];
    const float* Wk  = (const float*)d_in[6];
    const float* bk  = (const float*)d_in[7];
    const float* Wv  = (const float*)d_in[8];
    const float* bv  = (const float*)d_in[9];
    const float* Wo  = (const float*)d_in[10];
    const float* bo  = (const float*)d_in[11];
    const float* ln1g = (const float*)d_in[12];
    const float* ln1b = (const float*)d_in[13];
    const float* W1  = (const float*)d_in[14];
    const float* b1  = (const float*)d_in[15];
    const float* W2  = (const float*)d_in[16];
    const float* b2  = (const float*)d_in[17];
    const float* ln2g = (const float*)d_in[18];
    const float* ln2b = (const float*)d_in[19];
    const float* lnfg = (const float*)d_in[20];
    const float* lnfb = (const float*)d_in[21];
    const float* Wlm = (const float*)d_in[22];
    const float* blm = (const float*)d_in[23];
    float* out = (float*)d_out;

    float *px, *pbqkv, *ppart, *prl, *plg;
    __half *pqkvhi, *pqkvlo, *phhi, *phlo, *pohi, *polo, *pffhi, *pfflo, *pwth, *pwlmh;
    cudaGetSymbolAddress((void**)&px,     g_x);
    cudaGetSymbolAddress((void**)&pqkvhi, g_qkvhi);
    cudaGetSymbolAddress((void**)&pqkvlo, g_qkvlo);
    cudaGetSymbolAddress((void**)&phhi,   g_hhi);
    cudaGetSymbolAddress((void**)&phlo,   g_hlo);
    cudaGetSymbolAddress((void**)&pohi,   g_ohi);
    cudaGetSymbolAddress((void**)&polo,   g_olo);
    cudaGetSymbolAddress((void**)&pffhi,  g_ffhi);
    cudaGetSymbolAddress((void**)&pfflo,  g_fflo);
    cudaGetSymbolAddress((void**)&pbqkv,  g_bqkv);
    cudaGetSymbolAddress((void**)&ppart,  g_part);
    cudaGetSymbolAddress((void**)&pwth,   g_wth);
    cudaGetSymbolAddress((void**)&pwlmh,  g_wlmh);
    cudaGetSymbolAddress((void**)&prl,    g_rowloss);
    cudaGetSymbolAddress((void**)&plg,    g_logits_scratch);

    cudaFuncSetAttribute(gemm_h_kernel, cudaFuncAttributeMaxDynamicSharedMemorySize, GEMM_H_SMEM);
    cudaFuncSetAttribute(attn_kernel,   cudaFuncAttributeMaxDynamicSharedMemorySize, ATT_SMEM);

    const long long NLOG = (long long)BT * V_;
    float* logits = (out_size >= NLOG) ? out : plg;

    dim3 cb(32, 8);
    dim3 gQKVw(E_ / 32, NQKV / 32);
    dim3 gQKV(NQKV / 128, BT / 128);
    dim3 gWo(E_ / 128, BT / 128, 3);
    dim3 gW1(FF / 128, BT / 128, 2);
    dim3 gW2(E_ / 128, BT / 128, 3);
    dim3 gVd(V_ / 128, BT / 128);
    dim3 gAttn(T_ / 64, B_ * H_);
    int rF = BT * FF / 1024;

    for (int l = 0; l < L_; l++) {
        if (l == 0)
            embed_ln_kernel<<<BT, 256>>>(idx, tok_emb, pos_emb, ln1g, ln1b, px, phhi, phlo); // 0
        wconv_qkv_kernel<<<gQKVw, cb>>>(Wq, Wk, Wv, bq, bk, bv,
                                        pwth + OFF_QKV(l), pbqkv, l);                        // 1
        gemm_h_kernel<<<gQKV, 256, GEMM_H_SMEM>>>(phhi, phlo, pwth + OFF_QKV(l),             // 2
            pbqkv + l * NQKV, nullptr, pqkvhi, pqkvlo, nullptr, NQKV, E_, E_, 2);
        attn_kernel<<<gAttn, 128, ATT_SMEM>>>(pqkvhi, pqkvlo, pohi, polo);                   // 3 (= global 5)
        wconvt_h_kernel<<<dim3(E_ / 32, E_ / 32), cb>>>(Wo + (size_t)l * E_ * E_,
            pwth + OFF_O(l), E_, E_);
        gemm_h_kernel<<<gWo, 256, GEMM_H_SMEM>>>(pohi, polo, pwth + OFF_O(l),
            nullptr, nullptr, nullptr, nullptr, ppart, E_, E_, 256, 2);
        reduce_ln_kernel<<<BT, 256>>>(ppart, 3, bo + l * E_, px,
                                      ln2g + l * E_, ln2b + l * E_, phhi, phlo);
        wconvt_h_kernel<<<dim3(FF / 32, E_ / 32), cb>>>(W1 + (size_t)l * E_ * FF,
            pwth + OFF_W1(l), E_, FF);
        gemm_h_kernel<<<gW1, 256, GEMM_H_SMEM>>>(phhi, phlo, pwth + OFF_W1(l),
            nullptr, nullptr, nullptr, nullptr, ppart, FF, E_, 384, 2);
        reduce_kernel<<<rF, 256>>>(ppart, 2, b1 + l * FF, pffhi, pfflo, FF);
        wconvt_h_kernel<<<dim3(E_ / 32, FF / 32), cb>>>(W2 + (size_t)l * FF * E_,
            pwth + OFF_W2(l), FF, E_);
        gemm_h_kernel<<<gW2, 256, GEMM_H_SMEM>>>(pffhi, pfflo, pwth + OFF_W2(l),
            nullptr, nullptr, nullptr, nullptr, ppart, E_, FF, 1024, 2);
        if (l < L_ - 1)
            reduce_ln_kernel<<<BT, 256>>>(ppart, 3, b2 + l * E_, px,
                                          ln1g + (l + 1) * E_, ln1b + (l + 1) * E_, phhi, phlo);
        else
            reduce_ln_kernel<<<BT, 256>>>(ppart, 3, b2 + l * E_, px,
                                          lnfg, lnfb, phhi, phlo);
    }
    wconvt_h_kernel<<<dim3(V_ / 32, E_ / 32), cb>>>(Wlm, pwlmh, E_, V_);
    gemm_h_kernel<<<gVd, 256, GEMM_H_SMEM>>>(phhi, phlo, pwlmh, blm,
                                             logits, nullptr, nullptr, nullptr, V_, E_, E_, 1);

    // --- loss ---
    float* loss_dst = nullptr;
    if (out_size == 1)        loss_dst = out;
    else if (out_size > NLOG) loss_dst = out + NLOG;
    if (loss_dst) {
        row_lse_kernel<<<BT, 256>>>(logits, targets, prl);
        loss_reduce_kernel<<<1, 256>>>(prl, loss_dst);
    }
}

// round 15
// speedup vs baseline: 5.5839x; 1.1457x over previous
#include <cuda_runtime.h>
#include <cuda_bf16.h>
#include <cuda_fp16.h>
#include <math.h>
#include <stdint.h>

#define L_  4
#define H_  12
#define E_  768
#define HS_ 64
#define V_  32000
#define B_  2
#define T_  1024
#define BT  2048
#define FF  3072
#define NQKV 2304

// ---- weight scratch offsets (fp16 elements) ----
#define WPL 7077888ull
#define OFF_QKV(l) ((size_t)(l) * WPL)
#define OFF_O(l)   (OFF_QKV(l) + 1769472ull)
#define OFF_W1(l)  (OFF_QKV(l) + 2359296ull)
#define OFF_W2(l)  (OFF_QKV(l) + 4718592ull)
#define WTOT       ((size_t)4 * WPL)

// ---------------- scratch (static device globals) ----------------------------
__device__ float g_x[BT * E_];
__device__ __half g_qkvhi[BT * NQKV];
__device__ __half g_qkvlo[BT * NQKV];
__device__ __half g_hhi[BT * E_];
__device__ __half g_hlo[BT * E_];
__device__ __half g_ohi[BT * E_];
__device__ __half g_olo[BT * E_];
__device__ __half g_ffhi[BT * FF];
__device__ float g_bqkv[L_ * NQKV];
__device__ float g_part[2ull * BT * FF];
__device__ __half g_wth[WTOT];
__device__ __half g_wlmh[(size_t)V_ * E_];
__device__ float g_rowloss[BT];
__device__ float g_logits_scratch[(size_t)BT * V_];

// ---------------- PTX helpers ------------------------------------------------
__device__ __forceinline__ uint32_t smem_u32(const void* p) {
    uint32_t a;
    asm("{ .reg .u64 t; cvta.to.shared.u64 t, %1; cvt.u32.u64 %0, t; }" : "=r"(a) : "l"(p));
    return a;
}
__device__ __forceinline__ void mma16816h(float* c, const uint32_t* a, uint32_t b0, uint32_t b1) {
    asm volatile(
        "mma.sync.aligned.m16n8k16.row.col.f32.f16.f16.f32 "
        "{%0,%1,%2,%3}, {%4,%5,%6,%7}, {%8,%9}, {%0,%1,%2,%3};"
        : "+f"(c[0]), "+f"(c[1]), "+f"(c[2]), "+f"(c[3])
        : "r"(a[0]), "r"(a[1]), "r"(a[2]), "r"(a[3]), "r"(b0), "r"(b1));
}
__device__ __forceinline__ void ldsm4(uint32_t* r, uint32_t addr) {
    asm volatile("ldmatrix.sync.aligned.m8n8.x4.shared.b16 {%0,%1,%2,%3}, [%4];"
                 : "=r"(r[0]), "=r"(r[1]), "=r"(r[2]), "=r"(r[3]) : "r"(addr));
}
__device__ __forceinline__ void cpasync16(uint32_t dst, const void* src) {
    asm volatile("cp.async.cg.shared.global [%0], [%1], 16;" :: "r"(dst), "l"(src));
}

// ---------------- fused QKV weight repack+transpose -> fp16 + bias concat ----
__global__ __launch_bounds__(256) void wconv_qkv_kernel(const float* __restrict__ Wq,
                                                        const float* __restrict__ Wk,
                                                        const float* __restrict__ Wv,
                                                        const float* __restrict__ bq,
                                                        const float* __restrict__ bk,
                                                        const float* __restrict__ bv,
                                                        __half* __restrict__ Wt,
                                                        float* __restrict__ bqkv,
                                                        int l) {
    __shared__ float s[32][33];
    int n0 = blockIdx.y * 32, e0 = blockIdx.x * 32;
    int tx = threadIdx.x, ty = threadIdx.y;
    int sel = n0 / E_;
    int nn = n0 % E_;
    int h = nn >> 6, hs0 = nn & 63;
    const float* src = sel == 0 ? Wq : (sel == 1 ? Wk : Wv);
    const float* base = src + ((size_t)(l * H_ + h) * E_) * 64;
#pragma unroll
    for (int i = 0; i < 4; i++) {
        int e = ty + 8 * i;
        s[e][tx] = base[(size_t)(e0 + e) * 64 + hs0 + tx];
    }
    __syncthreads();
#pragma unroll
    for (int i = 0; i < 4; i++) {
        int nl = ty + 8 * i;
        Wt[(size_t)(n0 + nl) * E_ + e0 + tx] = __float2half_rn(s[tx][nl]);
    }
    int gid = (blockIdx.y * gridDim.x + blockIdx.x) * 256 + ty * 32 + tx;
    if (gid < NQKV) {
        float v;
        if (gid < E_)            v = bq[l * E_ + gid];
        else if (gid < 2 * E_)   v = bk[l * E_ + gid - E_];
        else                     v = bv[l * E_ + gid - 2 * E_];
        bqkv[l * NQKV + gid] = v;
    }
}

// ---------------- generic weight transpose -> single fp16 --------------------
__global__ __launch_bounds__(256) void wconvt_h_kernel(const float* __restrict__ W,
                                                       __half* __restrict__ Wt,
                                                       int K, int N) {
    __shared__ float s[32][33];
    int k0 = blockIdx.y * 32, n0 = blockIdx.x * 32;
    int tx = threadIdx.x, ty = threadIdx.y;
#pragma unroll
    for (int i = 0; i < 4; i++)
        s[ty + 8 * i][tx] = W[(size_t)(k0 + ty + 8 * i) * N + n0 + tx];
    __syncthreads();
#pragma unroll
    for (int i = 0; i < 4; i++) {
        int n = ty + 8 * i;
        Wt[(size_t)(n0 + n) * K + k0 + tx] = __float2half_rn(s[tx][n]);
    }
}

// ---------------- fused embedding + layernorm -> fp16 hi/lo -------------------
__global__ __launch_bounds__(256) void embed_ln_kernel(const int* __restrict__ idx,
                                                       const float* __restrict__ tok,
                                                       const float* __restrict__ pos,
                                                       const float* __restrict__ g,
                                                       const float* __restrict__ b,
                                                       float* __restrict__ x,
                                                       __half* __restrict__ hi,
                                                       __half* __restrict__ lo) {
    int row = blockIdx.x;
    int tid = threadIdx.x;
    int token = idx[row];
    int tp = row % T_;
    size_t rb = (size_t)row * E_;
    float v[3], s = 0.f, sq = 0.f;
#pragma unroll
    for (int i = 0; i < 3; i++) {
        int e = tid + (i << 8);
        float t = tok[(size_t)token * E_ + e] + pos[(size_t)tp * E_ + e];
        x[rb + e] = t;
        v[i] = t; s += t; sq += t * t;
    }
#pragma unroll
    for (int o = 16; o > 0; o >>= 1) {
        s  += __shfl_xor_sync(0xffffffffu, s, o);
        sq += __shfl_xor_sync(0xffffffffu, sq, o);
    }
    __shared__ float ss[8], ssq[8];
    if ((tid & 31) == 0) { ss[tid >> 5] = s; ssq[tid >> 5] = sq; }
    __syncthreads();
    s = 0.f; sq = 0.f;
#pragma unroll
    for (int i = 0; i < 8; i++) { s += ss[i]; sq += ssq[i]; }
    float mean = s * (1.f / E_);
    float var  = sq * (1.f / E_) - mean * mean;
    float rstd = rsqrtf(var + 1e-5f);
#pragma unroll
    for (int i = 0; i < 3; i++) {
        int e = tid + (i << 8);
        float y = (v[i] - mean) * rstd * g[e] + b[e];
        __half h = __float2half_rn(y);
        hi[rb + e] = h;
        lo[rb + e] = __float2half_rn(y - __half2float(h));
    }
}

// ---------------- fused split-K reduce + residual + layernorm ----------------
// WRITE_LO=0 when the consumer GEMM is 1-sweep (lo never read).
template<int WRITE_LO>
__global__ __launch_bounds__(256) void reduce_ln_kernel(const float* __restrict__ parts,
                                                        int nsplit,
                                                        const float* __restrict__ bias,
                                                        float* __restrict__ x,
                                                        const float* __restrict__ g,
                                                        const float* __restrict__ b,
                                                        __half* __restrict__ hi,
                                                        __half* __restrict__ lo) {
    int row = blockIdx.x, tid = threadIdx.x;
    size_t rb = (size_t)row * E_;
    const size_t plane = (size_t)BT * E_;
    float v[3], s = 0.f, sq = 0.f;
#pragma unroll
    for (int i = 0; i < 3; i++) {
        int e = tid + (i << 8);
        size_t ix = rb + e;
        float t = parts[ix];
        for (int p = 1; p < nsplit; p++) t += parts[plane * p + ix];
        t += bias[e] + x[ix];
        x[ix] = t;
        v[i] = t; s += t; sq += t * t;
    }
#pragma unroll
    for (int o = 16; o > 0; o >>= 1) {
        s  += __shfl_xor_sync(0xffffffffu, s, o);
        sq += __shfl_xor_sync(0xffffffffu, sq, o);
    }
    __shared__ float ss[8], ssq[8];
    if ((tid & 31) == 0) { ss[tid >> 5] = s; ssq[tid >> 5] = sq; }
    __syncthreads();
    s = 0.f; sq = 0.f;
#pragma unroll
    for (int i = 0; i < 8; i++) { s += ss[i]; sq += ssq[i]; }
    float mean = s * (1.f / E_);
    float var  = sq * (1.f / E_) - mean * mean;
    float rstd = rsqrtf(var + 1e-5f);
#pragma unroll
    for (int i = 0; i < 3; i++) {
        int e = tid + (i << 8);
        float y = (v[i] - mean) * rstd * g[e] + b[e];
        __half h = __float2half_rn(y);
        hi[rb + e] = h;
        if (WRITE_LO)
            lo[rb + e] = __float2half_rn(y - __half2float(h));
    }
}

// ---------------- fp16 tensor-core GEMM (1/2 sweeps, 4 stages) ----------------
#define LSTG 24576
#define GEMM_H_SMEM (4 * LSTG)
__global__ __launch_bounds__(256, 2)
void gemm_h_kernel(const __half* __restrict__ Ahi,
                   const __half* __restrict__ Alo,
                   const __half* __restrict__ Bt,
                   const float* __restrict__ bias,
                   float* __restrict__ C,
                   __half* __restrict__ Chi,
                   __half* __restrict__ Clo,
                   float* __restrict__ Cpart,
                   int N, int K, int kslen, int nsweep) {
    extern __shared__ __align__(16) char smem[];
    int tid = threadIdx.x, lane = tid & 31, wid = tid >> 5;
    int wm = wid >> 2, wn = wid & 3;
    int row0 = blockIdx.y << 7, col0 = blockIdx.x << 7;
    int k0base = blockIdx.z * kslen;
    uint32_t sb = smem_u32(smem);

    float acc[4][4][4] = {};
    const int nCh = kslen >> 5;
    int frow = tid >> 1;
    int fc0 = (tid & 1) << 1;
    uint32_t fsw = (uint32_t)((frow >> 1) & 3);

    auto loadStage = [&](int stg, int c) {
        if (c < nCh) {
            uint32_t st = sb + stg * LSTG;
            int k0 = k0base + (c << 5);
            size_t abase = (size_t)(row0 + frow) * K + k0;
            size_t bbase = (size_t)(col0 + frow) * K + k0;
#pragma unroll
            for (int cc = 0; cc < 2; cc++) {
                int cl = fc0 + cc;
                uint32_t doff = (uint32_t)(frow << 6) + (((uint32_t)cl ^ fsw) << 4);
                cpasync16(st + doff,         Ahi + abase + (cl << 3));
                if (nsweep > 1)
                    cpasync16(st + 8192 + doff, Alo + abase + (cl << 3));
                cpasync16(st + 16384 + doff, Bt + bbase + (cl << 3));
            }
        }
        asm volatile("cp.async.commit_group;" ::: "memory");
    };

    int arow[4], brow[2];
    uint32_t asw[4], bsw[2];
#pragma unroll
    for (int mf = 0; mf < 4; mf++) {
        arow[mf] = (wm << 6) + (mf << 4) + (lane & 15);
        asw[mf] = (uint32_t)((arow[mf] >> 1) & 3);
    }
#pragma unroll
    for (int g = 0; g < 2; g++) {
        brow[g] = (wn << 5) + (g << 4) + (lane & 7) + (((lane >> 3) & 1) << 3);
        bsw[g] = (uint32_t)((brow[g] >> 1) & 3);
    }
    int kc = lane >> 4;

    loadStage(0, 0);
    loadStage(1, 1);
    loadStage(2, 2);

    int stg = 0;
    for (int c = 0; c < nCh; ++c) {
        asm volatile("cp.async.wait_group 2;" ::: "memory");
        __syncthreads();
        loadStage((stg + 3) & 3, c + 3);
        uint32_t st = sb + stg * LSTG;
#pragma unroll
        for (int ks = 0; ks < 2; ks++) {
            int cl = (ks << 1) + kc;
            uint32_t ah[4][4], bb[2][4];
#pragma unroll
            for (int mf = 0; mf < 4; mf++)
                ldsm4(ah[mf], st + (uint32_t)(arow[mf] << 6) + (((uint32_t)cl ^ asw[mf]) << 4));
#pragma unroll
            for (int g = 0; g < 2; g++)
                ldsm4(bb[g], st + 16384 + (uint32_t)(brow[g] << 6) + (((uint32_t)cl ^ bsw[g]) << 4));
#pragma unroll
            for (int mf = 0; mf < 4; mf++)
#pragma unroll
                for (int nf = 0; nf < 4; nf++)
                    mma16816h(acc[mf][nf], ah[mf], bb[nf >> 1][nf & 1], bb[nf >> 1][(nf & 1) + 2]);
            if (nsweep > 1) {
                uint32_t al[4][4];
#pragma unroll
                for (int mf = 0; mf < 4; mf++)
                    ldsm4(al[mf], st + 8192 + (uint32_t)(arow[mf] << 6) + (((uint32_t)cl ^ asw[mf]) << 4));
#pragma unroll
                for (int mf = 0; mf < 4; mf++)
#pragma unroll
                    for (int nf = 0; nf < 4; nf++)
                        mma16816h(acc[mf][nf], al[mf], bb[nf >> 1][nf & 1], bb[nf >> 1][(nf & 1) + 2]);
            }
        }
        stg = (stg + 1) & 3;
    }

    if (Cpart) {
        size_t plane = (size_t)blockIdx.z * (((size_t)gridDim.y << 7) * (size_t)N);
#pragma unroll
        for (int mf = 0; mf < 4; mf++) {
            int rbase = row0 + (wm << 6) + (mf << 4) + (lane >> 2);
#pragma unroll
            for (int nf = 0; nf < 4; nf++) {
                int cb = col0 + (wn << 5) + (nf << 3) + ((lane & 3) << 1);
#pragma unroll
                for (int half = 0; half < 2; half++) {
                    int r = rbase + (half << 3);
                    *(float2*)(Cpart + plane + (size_t)r * N + cb) =
                        make_float2(acc[mf][nf][half * 2], acc[mf][nf][half * 2 + 1]);
                }
            }
        }
        return;
    }
#pragma unroll
    for (int mf = 0; mf < 4; mf++) {
        int rbase = row0 + (wm << 6) + (mf << 4) + (lane >> 2);
#pragma unroll
        for (int nf = 0; nf < 4; nf++) {
            int cb = col0 + (wn << 5) + (nf << 3) + ((lane & 3) << 1);
            float b0 = bias ? bias[cb] : 0.f;
            float b1 = bias ? bias[cb + 1] : 0.f;
#pragma unroll
            for (int half = 0; half < 2; half++) {
                int r = rbase + (half << 3);
                float v0 = acc[mf][nf][half * 2 + 0] + b0;
                float v1 = acc[mf][nf][half * 2 + 1] + b1;
                size_t gi = (size_t)r * N + cb;
                if (Chi) {
                    __half2 h = __floats2half2_rn(v0, v1);
                    float2 hf = __half22float2(h);
                    __half2 l = __floats2half2_rn(v0 - hf.x, v1 - hf.y);
                    *(__half2*)(Chi + gi) = h;
                    *(__half2*)(Clo + gi) = l;
                } else {
                    *(float2*)(C + gi) = make_float2(v0, v1);
                }
            }
        }
    }
}

// ---------------- split-K reduce (W1 path: relu + fp16 hi out only) ----------
__global__ __launch_bounds__(256) void reduce_kernel(const float* __restrict__ parts,
                                                     int nsplit,
                                                     const float* __restrict__ bias,
                                                     __half* __restrict__ outHi,
                                                     int N) {
    size_t i = ((size_t)blockIdx.x * 256 + threadIdx.x) * 4;
    size_t plane = (size_t)BT * N;
    int col = (int)(i % N);
    float4 s = *(const float4*)(parts + i);
    for (int p = 1; p < nsplit; p++) {
        float4 t = *(const float4*)(parts + plane * p + i);
        s.x += t.x; s.y += t.y; s.z += t.z; s.w += t.w;
    }
    float4 b = *(const float4*)(bias + col);
    s.x = fmaxf(s.x + b.x, 0.f); s.y = fmaxf(s.y + b.y, 0.f);
    s.z = fmaxf(s.z + b.z, 0.f); s.w = fmaxf(s.w + b.w, 0.f);
    __half2 h0 = __floats2half2_rn(s.x, s.y);
    __half2 h1 = __floats2half2_rn(s.z, s.w);
    *(__half2*)(outHi + i) = h0;
    *(__half2*)(outHi + i + 2) = h1;
}

// ---------------- tensor-core flash attention (fp16 2-sweep, 40KB smem) ------
#define ATT_SMEM 40960
__global__ __launch_bounds__(128)
void attn_kernel(const __half* __restrict__ qkvhi,
                 const __half* __restrict__ qkvlo,
                 __half* __restrict__ ohi,
                 __half* __restrict__ olo) {
    extern __shared__ __align__(16) char smem[];
    uint32_t sb = smem_u32(smem);
    const uint32_t Q_HI = 0, Q_LO = 8192, K_HI = 16384, VS_HI = 24576, VT_HI = 32768;
    int tid = threadIdx.x, lane = tid & 31, w = tid >> 5;
    int qt = (int)gridDim.x - 1 - (int)blockIdx.x;
    int bh = blockIdx.y;
    int bb = bh / H_, hh = bh % H_;
    size_t qrowbase = (size_t)(bb * T_ + (qt << 6));
    const int coff = hh * 64;
    int kc = lane >> 4;

    {
        int r0 = tid >> 1;
        int c0 = (tid & 1) << 2;
        size_t g = (qrowbase + r0) * (size_t)NQKV + coff;
#pragma unroll
        for (int i = 0; i < 4; i++) {
            int c = c0 + i;
            uint32_t d = (uint32_t)(r0 << 7) + (((uint32_t)(c ^ (r0 & 7))) << 4);
            cpasync16(sb + Q_HI + d, qkvhi + g + (c << 3));
            cpasync16(sb + Q_LO + d, qkvlo + g + (c << 3));
        }
        asm volatile("cp.async.commit_group;\n\tcp.async.wait_group 0;" ::: "memory");
    }
    __syncthreads();
    uint32_t qh[4][4], ql[4][4];
    {
        int aRow = (w << 4) + (lane & 15);
#pragma unroll
        for (int ks = 0; ks < 4; ks++) {
            int cl = (ks << 1) + kc;
            uint32_t ad = (uint32_t)(aRow << 7) + (((uint32_t)(cl ^ (aRow & 7))) << 4);
            ldsm4(qh[ks], sb + Q_HI + ad);
            ldsm4(ql[ks], sb + Q_LO + ad);
        }
    }

    float oacc[8][4] = {};
    float m1 = -INFINITY, m2 = -INFINITY, l1 = 0.f, l2 = 0.f;
    int r1 = lane >> 2;
    int rowg1 = (qt << 6) + (w << 4) + r1;
    int rowg2 = rowg1 + 8;

    for (int kt = 0; kt <= qt; kt++) {
        __syncthreads();
        size_t kbase = (size_t)(bb * T_ + (kt << 6));
        {
            int r0 = tid >> 1;
            int c0 = (tid & 1) << 2;
            size_t gk = (kbase + r0) * (size_t)NQKV + E_ + coff;
            size_t gv = (kbase + r0) * (size_t)NQKV + 2 * E_ + coff;
#pragma unroll
            for (int i = 0; i < 4; i++) {
                int c = c0 + i;
                uint32_t d = (uint32_t)(r0 << 7) + (((uint32_t)(c ^ (r0 & 7))) << 4);
                cpasync16(sb + K_HI + d,  qkvhi + gk + (c << 3));
                cpasync16(sb + VS_HI + d, qkvhi + gv + (c << 3));
            }
            asm volatile("cp.async.commit_group;\n\tcp.async.wait_group 0;" ::: "memory");
        }
        __syncthreads();
        {
            int kvp = tid & 31;
            int dg0 = tid >> 5;
            int kv = kvp << 1;
#pragma unroll
            for (int t = 0; t < 2; t++) {
                int ch = dg0 + (t << 2);
                int d0 = ch << 3;
                uint32_t a0 = (uint32_t)(kv << 7) + (((uint32_t)ch ^ (uint32_t)(kv & 7)) << 4);
                uint32_t a1 = (uint32_t)((kv + 1) << 7) + (((uint32_t)ch ^ (uint32_t)((kv + 1) & 7)) << 4);
                uint4 h0 = *(const uint4*)(smem + VS_HI + a0);
                uint4 h1 = *(const uint4*)(smem + VS_HI + a1);
                const __half* ph0 = (const __half*)&h0;
                const __half* ph1 = (const __half*)&h1;
#pragma unroll
                for (int j = 0; j < 8; j++) {
                    int d = d0 + j;
                    uint32_t ad = (uint32_t)(d << 7) +
                                  ((((uint32_t)(kvp >> 2) ^ (uint32_t)(d & 7)) << 4)) +
                                  ((uint32_t)(kvp & 3) << 2);
                    __half2 hw; hw.x = ph0[j]; hw.y = ph1[j];
                    *(__half2*)(smem + VT_HI + ad) = hw;
                }
            }
        }
        __syncthreads();

        float sacc[8][4] = {};
#pragma unroll
        for (int ks = 0; ks < 4; ks++) {
            int cl = (ks << 1) + kc;
            uint32_t kh[4][4];
#pragma unroll
            for (int g = 0; g < 4; g++) {
                int bRow = (g << 4) + (lane & 7) + (((lane >> 3) & 1) << 3);
                uint32_t bd = (uint32_t)(bRow << 7) + (((uint32_t)(cl ^ (bRow & 7))) << 4);
                ldsm4(kh[g], sb + K_HI + bd);
            }
#pragma unroll
            for (int g = 0; g < 4; g++)
#pragma unroll
                for (int nfp = 0; nfp < 2; nfp++)
                    mma16816h(sacc[2 * g + nfp], qh[ks], kh[g][nfp], kh[g][nfp + 2]);
#pragma unroll
            for (int g = 0; g < 4; g++)
#pragma unroll
                for (int nfp = 0; nfp < 2; nfp++)
                    mma16816h(sacc[2 * g + nfp], ql[ks], kh[g][nfp], kh[g][nfp + 2]);
        }
#pragma unroll
        for (int nf = 0; nf < 8; nf++) {
            sacc[nf][0] *= 0.125f; sacc[nf][1] *= 0.125f;
            sacc[nf][2] *= 0.125f; sacc[nf][3] *= 0.125f;
        }
        if (kt == qt) {
#pragma unroll
            for (int nf = 0; nf < 8; nf++) {
                int colb = (kt << 6) + (nf << 3) + ((lane & 3) << 1);
                if (colb > rowg1)     sacc[nf][0] = -INFINITY;
                if (colb + 1 > rowg1) sacc[nf][1] = -INFINITY;
                if (colb > rowg2)     sacc[nf][2] = -INFINITY;
                if (colb + 1 > rowg2) sacc[nf][3] = -INFINITY;
            }
        }
        float t1 = -INFINITY, t2 = -INFINITY;
#pragma unroll
        for (int nf = 0; nf < 8; nf++) {
            t1 = fmaxf(t1, fmaxf(sacc[nf][0], sacc[nf][1]));
            t2 = fmaxf(t2, fmaxf(sacc[nf][2], sacc[nf][3]));
        }
        t1 = fmaxf(t1, __shfl_xor_sync(0xffffffffu, t1, 1));
        t1 = fmaxf(t1, __shfl_xor_sync(0xffffffffu, t1, 2));
        t2 = fmaxf(t2, __shfl_xor_sync(0xffffffffu, t2, 1));
        t2 = fmaxf(t2, __shfl_xor_sync(0xffffffffu, t2, 2));
        float mn1 = fmaxf(m1, t1), mn2 = fmaxf(m2, t2);
        float a1 = __expf(m1 - mn1), a2 = __expf(m2 - mn2);
        float ps1 = 0.f, ps2 = 0.f;
#pragma unroll
        for (int nf = 0; nf < 8; nf++) {
            sacc[nf][0] = __expf(sacc[nf][0] - mn1);
            sacc[nf][1] = __expf(sacc[nf][1] - mn1);
            sacc[nf][2] = __expf(sacc[nf][2] - mn2);
            sacc[nf][3] = __expf(sacc[nf][3] - mn2);
            ps1 += sacc[nf][0] + sacc[nf][1];
            ps2 += sacc[nf][2] + sacc[nf][3];
        }
        ps1 += __shfl_xor_sync(0xffffffffu, ps1, 1);
        ps1 += __shfl_xor_sync(0xffffffffu, ps1, 2);
        ps2 += __shfl_xor_sync(0xffffffffu, ps2, 1);
        ps2 += __shfl_xor_sync(0xffffffffu, ps2, 2);
        l1 = l1 * a1 + ps1;
        l2 = l2 * a2 + ps2;
        m1 = mn1; m2 = mn2;
#pragma unroll
        for (int nf = 0; nf < 8; nf++) {
            oacc[nf][0] *= a1; oacc[nf][1] *= a1;
            oacc[nf][2] *= a2; oacc[nf][3] *= a2;
        }
#pragma unroll
        for (int j = 0; j < 4; j++) {
            uint32_t pah[4], pal[4];
#pragma unroll
            for (int half = 0; half < 2; half++) {
                float x0 = sacc[2 * j + half][0], x1 = sacc[2 * j + half][1];
                float x2 = sacc[2 * j + half][2], x3 = sacc[2 * j + half][3];
                __half2 h01 = __floats2half2_rn(x0, x1);
                __half2 h23 = __floats2half2_rn(x2, x3);
                float2 f01 = __half22float2(h01), f23 = __half22float2(h23);
                __half2 lo01 = __floats2half2_rn(x0 - f01.x, x1 - f01.y);
                __half2 lo23 = __floats2half2_rn(x2 - f23.x, x3 - f23.y);
                pah[2 * half + 0] = *(uint32_t*)&h01;
                pah[2 * half + 1] = *(uint32_t*)&h23;
                pal[2 * half + 0] = *(uint32_t*)&lo01;
                pal[2 * half + 1] = *(uint32_t*)&lo23;
            }
            int cl = (j << 1) + kc;
            uint32_t vh[4][4];
#pragma unroll
            for (int g = 0; g < 4; g++) {
                int bRow = (g << 4) + (lane & 7) + (((lane >> 3) & 1) << 3);
                uint32_t bd = (uint32_t)(bRow << 7) + (((uint32_t)(cl ^ (bRow & 7))) << 4);
                ldsm4(vh[g], sb + VT_HI + bd);
            }
#pragma unroll
            for (int g = 0; g < 4; g++)
#pragma unroll
                for (int nfp = 0; nfp < 2; nfp++)
                    mma16816h(oacc[2 * g + nfp], pah, vh[g][nfp], vh[g][nfp + 2]);
#pragma unroll
            for (int g = 0; g < 4; g++)
#pragma unroll
                for (int nfp = 0; nfp < 2; nfp++)
                    mma16816h(oacc[2 * g + nfp], pal, vh[g][nfp], vh[g][nfp + 2]);
        }
    }

    float li1 = 1.f / l1, li2 = 1.f / l2;
    size_t ob1 = (qrowbase + (w << 4) + r1) * (size_t)E_ + coff;
    size_t ob2 = ob1 + (size_t)8 * E_;
#pragma unroll
    for (int nf = 0; nf < 8; nf++) {
        int d = (nf << 3) + ((lane & 3) << 1);
        float v0 = oacc[nf][0] * li1, v1 = oacc[nf][1] * li1;
        __half2 h = __floats2half2_rn(v0, v1);
        float2 hf = __half22float2(h);
        __half2 lo = __floats2half2_rn(v0 - hf.x, v1 - hf.y);
        *(__half2*)(ohi + ob1 + d) = h;
        *(__half2*)(olo + ob1 + d) = lo;
        float v2 = oacc[nf][2] * li2, v3 = oacc[nf][3] * li2;
        __half2 h2 = __floats2half2_rn(v2, v3);
        float2 hf2 = __half22float2(h2);
        __half2 lo2 = __floats2half2_rn(v2 - hf2.x, v3 - hf2.y);
        *(__half2*)(ohi + ob2 + d) = h2;
        *(__half2*)(olo + ob2 + d) = lo2;
    }
}

// ---------------- loss ------------------------------------------------------
__global__ __launch_bounds__(256) void row_lse_kernel(const float* __restrict__ logits,
                                                      const int* __restrict__ targets,
                                                      float* __restrict__ rowloss) {
    int row = blockIdx.x, tid = threadIdx.x;
    const float* lr = logits + (size_t)row * V_;
    float mx = -INFINITY;
    for (int i = tid; i < V_; i += 256) mx = fmaxf(mx, lr[i]);
#pragma unroll
    for (int o = 16; o > 0; o >>= 1) mx = fmaxf(mx, __shfl_xor_sync(0xffffffffu, mx, o));
    __shared__ float sm[8];
    if ((tid & 31) == 0) sm[tid >> 5] = mx;
    __syncthreads();
    float m2 = -INFINITY;
#pragma unroll
    for (int i = 0; i < 8; i++) m2 = fmaxf(m2, sm[i]);
    float se = 0.f;
    for (int i = tid; i < V_; i += 256) se += __expf(lr[i] - m2);
#pragma unroll
    for (int o = 16; o > 0; o >>= 1) se += __shfl_xor_sync(0xffffffffu, se, o);
    __shared__ float ssum[8];
    if ((tid & 31) == 0) ssum[tid >> 5] = se;
    __syncthreads();
    if (tid == 0) {
        float tot = 0.f;
#pragma unroll
        for (int i = 0; i < 8; i++) tot += ssum[i];
        rowloss[row] = (logf(tot) + m2) - lr[targets[row]];
    }
}

__global__ __launch_bounds__(256) void loss_reduce_kernel(const float* __restrict__ rowloss,
                                                          float* __restrict__ out) {
    int tid = threadIdx.x;
    float s = 0.f;
    for (int i = tid; i < BT; i += 256) s += rowloss[i];
#pragma unroll
    for (int o = 16; o > 0; o >>= 1) s += __shfl_xor_sync(0xffffffffu, s, o);
    __shared__ float sm[8];
    if ((tid & 31) == 0) sm[tid >> 5] = s;
    __syncthreads();
    if (tid == 0) {
        float t = 0.f;
#pragma unroll
        for (int i = 0; i < 8; i++) t += sm[i];
        out[0] = t * (1.f / BT);
    }
}

// ---------------- launch ----------------------------------------------------
extern "C" void kernel_launch(void* const* d_in, const int* in_sizes, int n_in,
                              void* d_out, int out_size) {
    const int*   idx     = (const int*)d_in[0];
    const int*   targets = (const int*)d_in[1];
    const float* tok_emb = (const float*)d_in[2];
    const float* pos_emb = (const float*)d_in[3];
    const float* Wq  = (const float*)d_in[4];
    const float* bq  = (const float*)d_in[5];
    const float* Wk  = (const float*)d_in[6];
    const float* bk  = (const float*)d_in[7];
    const float* Wv  = (const float*)d_in[8];
    const float* bv  = (const float*)d_in[9];
    const float* Wo  = (const float*)d_in[10];
    const float* bo  = (const float*)d_in[11];
    const float* ln1g = (const float*)d_in[12];
    const float* ln1b = (const float*)d_in[13];
    const float* W1  = (const float*)d_in[14];
    const float* b1  = (const float*)d_in[15];
    const float* W2  = (const float*)d_in[16];
    const float* b2  = (const float*)d_in[17];
    const float* ln2g = (const float*)d_in[18];
    const float* ln2b = (const float*)d_in[19];
    const float* lnfg = (const float*)d_in[20];
    const float* lnfb = (const float*)d_in[21];
    const float* Wlm = (const float*)d_in[22];
    const float* blm = (const float*)d_in[23];
    float* out = (float*)d_out;

    float *px, *pbqkv, *ppart, *prl, *plg;
    __half *pqkvhi, *pqkvlo, *phhi, *phlo, *pohi, *polo, *pffhi, *pwth, *pwlmh;
    cudaGetSymbolAddress((void**)&px,     g_x);
    cudaGetSymbolAddress((void**)&pqkvhi, g_qkvhi);
    cudaGetSymbolAddress((void**)&pqkvlo, g_qkvlo);
    cudaGetSymbolAddress((void**)&phhi,   g_hhi);
    cudaGetSymbolAddress((void**)&phlo,   g_hlo);
    cudaGetSymbolAddress((void**)&pohi,   g_ohi);
    cudaGetSymbolAddress((void**)&polo,   g_olo);
    cudaGetSymbolAddress((void**)&pffhi,  g_ffhi);
    cudaGetSymbolAddress((void**)&pbqkv,  g_bqkv);
    cudaGetSymbolAddress((void**)&ppart,  g_part);
    cudaGetSymbolAddress((void**)&pwth,   g_wth);
    cudaGetSymbolAddress((void**)&pwlmh,  g_wlmh);
    cudaGetSymbolAddress((void**)&prl,    g_rowloss);
    cudaGetSymbolAddress((void**)&plg,    g_logits_scratch);

    cudaFuncSetAttribute(gemm_h_kernel, cudaFuncAttributeMaxDynamicSharedMemorySize, GEMM_H_SMEM);
    cudaFuncSetAttribute(attn_kernel,   cudaFuncAttributeMaxDynamicSharedMemorySize, ATT_SMEM);

    const long long NLOG = (long long)BT * V_;
    float* logits = (out_size >= NLOG) ? out : plg;

    dim3 cb(32, 8);
    dim3 gQKVw(E_ / 32, NQKV / 32);
    dim3 gQKV(NQKV / 128, BT / 128);
    dim3 gWo(E_ / 128, BT / 128, 3);
    dim3 gW1(FF / 128, BT / 128, 2);
    dim3 gW2(E_ / 128, BT / 128, 3);
    dim3 gVd(V_ / 128, BT / 128);
    dim3 gAttn(T_ / 64, B_ * H_);
    int rF = BT * FF / 1024;

    for (int l = 0; l < L_; l++) {
        if (l == 0)
            embed_ln_kernel<<<BT, 256>>>(idx, tok_emb, pos_emb, ln1g, ln1b, px, phhi, phlo); // 0
        wconv_qkv_kernel<<<gQKVw, cb>>>(Wq, Wk, Wv, bq, bk, bv,
                                        pwth + OFF_QKV(l), pbqkv, l);                        // 1
        gemm_h_kernel<<<gQKV, 256, GEMM_H_SMEM>>>(phhi, phlo, pwth + OFF_QKV(l),             // 2
            pbqkv + l * NQKV, nullptr, pqkvhi, pqkvlo, nullptr, NQKV, E_, E_, 2);
        attn_kernel<<<gAttn, 128, ATT_SMEM>>>(pqkvhi, pqkvlo, pohi, polo);                   // 3 (= global 5)
        wconvt_h_kernel<<<dim3(E_ / 32, E_ / 32), cb>>>(Wo + (size_t)l * E_ * E_,
            pwth + OFF_O(l), E_, E_);
        gemm_h_kernel<<<gWo, 256, GEMM_H_SMEM>>>(pohi, polo, pwth + OFF_O(l),
            nullptr, nullptr, nullptr, nullptr, ppart, E_, E_, 256, 2);
        // ln2 -> hi only (W1 is 1-sweep)
        reduce_ln_kernel<0><<<BT, 256>>>(ppart, 3, bo + l * E_, px,
                                         ln2g + l * E_, ln2b + l * E_, phhi, nullptr);
        wconvt_h_kernel<<<dim3(FF / 32, E_ / 32), cb>>>(W1 + (size_t)l * E_ * FF,
            pwth + OFF_W1(l), E_, FF);
        gemm_h_kernel<<<gW1, 256, GEMM_H_SMEM>>>(phhi, nullptr, pwth + OFF_W1(l),
            nullptr, nullptr, nullptr, nullptr, ppart, FF, E_, 384, 1);
        reduce_kernel<<<rF, 256>>>(ppart, 2, b1 + l * FF, pffhi, FF);
        wconvt_h_kernel<<<dim3(E_ / 32, FF / 32), cb>>>(W2 + (size_t)l * FF * E_,
            pwth + OFF_W2(l), FF, E_);
        gemm_h_kernel<<<gW2, 256, GEMM_H_SMEM>>>(pffhi, nullptr, pwth + OFF_W2(l),
            nullptr, nullptr, nullptr, nullptr, ppart, E_, FF, 1024, 1);
        if (l < L_ - 1)
            reduce_ln_kernel<1><<<BT, 256>>>(ppart, 3, b2 + l * E_, px,
                                             ln1g + (l + 1) * E_, ln1b + (l + 1) * E_, phhi, phlo);
        else
            reduce_ln_kernel<0><<<BT, 256>>>(ppart, 3, b2 + l * E_, px,
                                             lnfg, lnfb, phhi, nullptr);   // LM is 1-sweep
    }
    wconvt_h_kernel<<<dim3(V_ / 32, E_ / 32), cb>>>(Wlm, pwlmh, E_, V_);
    gemm_h_kernel<<<gVd, 256, GEMM_H_SMEM>>>(phhi, nullptr, pwlmh, blm,
                                             logits, nullptr, nullptr, nullptr, V_, E_, E_, 1);

    // --- loss ---
    float* loss_dst = nullptr;
    if (out_size == 1)        loss_dst = out;
    else if (out_size > NLOG) loss_dst = out + NLOG;
    if (loss_dst) {
        row_lse_kernel<<<BT, 256>>>(logits, targets, prl);
        loss_reduce_kernel<<<1, 256>>>(prl, loss_dst);
    }
}

// round 16
// speedup vs baseline: 5.6546x; 1.0127x over previous
#include <cuda_runtime.h>
#include <cuda_bf16.h>
#include <cuda_fp16.h>
#include <math.h>
#include <stdint.h>

#define L_  4
#define H_  12
#define E_  768
#define HS_ 64
#define V_  32000
#define B_  2
#define T_  1024
#define BT  2048
#define FF  3072
#define NQKV 2304

// ---- weight scratch offsets (fp16 elements) ----
#define WPL 7077888ull
#define OFF_QKV(l) ((size_t)(l) * WPL)
#define OFF_O(l)   (OFF_QKV(l) + 1769472ull)
#define OFF_W1(l)  (OFF_QKV(l) + 2359296ull)
#define OFF_W2(l)  (OFF_QKV(l) + 4718592ull)
#define WTOT       ((size_t)4 * WPL)

// ---------------- scratch (static device globals) ----------------------------
__device__ float g_x[BT * E_];
__device__ __half g_qkvhi[BT * NQKV];
__device__ __half g_qkvlo[BT * NQKV];
__device__ __half g_hhi[BT * E_];
__device__ __half g_hlo[BT * E_];
__device__ __half g_ohi[BT * E_];
__device__ __half g_olo[BT * E_];
__device__ __half g_ffhi[BT * FF];
__device__ float g_bqkv[L_ * NQKV];
__device__ float g_part[2ull * BT * FF];
__device__ __half g_wth[WTOT];
__device__ __half g_wlmh[(size_t)V_ * E_];
__device__ float g_rowloss[BT];
__device__ float g_logits_scratch[(size_t)BT * V_];

// ---------------- PTX helpers ------------------------------------------------
__device__ __forceinline__ uint32_t smem_u32(const void* p) {
    uint32_t a;
    asm("{ .reg .u64 t; cvta.to.shared.u64 t, %1; cvt.u32.u64 %0, t; }" : "=r"(a) : "l"(p));
    return a;
}
__device__ __forceinline__ void mma16816h(float* c, const uint32_t* a, uint32_t b0, uint32_t b1) {
    asm volatile(
        "mma.sync.aligned.m16n8k16.row.col.f32.f16.f16.f32 "
        "{%0,%1,%2,%3}, {%4,%5,%6,%7}, {%8,%9}, {%0,%1,%2,%3};"
        : "+f"(c[0]), "+f"(c[1]), "+f"(c[2]), "+f"(c[3])
        : "r"(a[0]), "r"(a[1]), "r"(a[2]), "r"(a[3]), "r"(b0), "r"(b1));
}
__device__ __forceinline__ void ldsm4(uint32_t* r, uint32_t addr) {
    asm volatile("ldmatrix.sync.aligned.m8n8.x4.shared.b16 {%0,%1,%2,%3}, [%4];"
                 : "=r"(r[0]), "=r"(r[1]), "=r"(r[2]), "=r"(r[3]) : "r"(addr));
}
__device__ __forceinline__ void cpasync16(uint32_t dst, const void* src) {
    asm volatile("cp.async.cg.shared.global [%0], [%1], 16;" :: "r"(dst), "l"(src));
}

// ---------------- fused QKV weight repack+transpose -> fp16 + bias concat ----
__global__ __launch_bounds__(256) void wconv_qkv_kernel(const float* __restrict__ Wq,
                                                        const float* __restrict__ Wk,
                                                        const float* __restrict__ Wv,
                                                        const float* __restrict__ bq,
                                                        const float* __restrict__ bk,
                                                        const float* __restrict__ bv,
                                                        __half* __restrict__ Wt,
                                                        float* __restrict__ bqkv,
                                                        int l) {
    __shared__ float s[32][33];
    int n0 = blockIdx.y * 32, e0 = blockIdx.x * 32;
    int tx = threadIdx.x, ty = threadIdx.y;
    int sel = n0 / E_;
    int nn = n0 % E_;
    int h = nn >> 6, hs0 = nn & 63;
    const float* src = sel == 0 ? Wq : (sel == 1 ? Wk : Wv);
    const float* base = src + ((size_t)(l * H_ + h) * E_) * 64;
#pragma unroll
    for (int i = 0; i < 4; i++) {
        int e = ty + 8 * i;
        s[e][tx] = base[(size_t)(e0 + e) * 64 + hs0 + tx];
    }
    __syncthreads();
#pragma unroll
    for (int i = 0; i < 4; i++) {
        int nl = ty + 8 * i;
        Wt[(size_t)(n0 + nl) * E_ + e0 + tx] = __float2half_rn(s[tx][nl]);
    }
    int gid = (blockIdx.y * gridDim.x + blockIdx.x) * 256 + ty * 32 + tx;
    if (gid < NQKV) {
        float v;
        if (gid < E_)            v = bq[l * E_ + gid];
        else if (gid < 2 * E_)   v = bk[l * E_ + gid - E_];
        else                     v = bv[l * E_ + gid - 2 * E_];
        bqkv[l * NQKV + gid] = v;
    }
}

// ---------------- generic weight transpose -> single fp16 --------------------
__global__ __launch_bounds__(256) void wconvt_h_kernel(const float* __restrict__ W,
                                                       __half* __restrict__ Wt,
                                                       int K, int N) {
    __shared__ float s[32][33];
    int k0 = blockIdx.y * 32, n0 = blockIdx.x * 32;
    int tx = threadIdx.x, ty = threadIdx.y;
#pragma unroll
    for (int i = 0; i < 4; i++)
        s[ty + 8 * i][tx] = W[(size_t)(k0 + ty + 8 * i) * N + n0 + tx];
    __syncthreads();
#pragma unroll
    for (int i = 0; i < 4; i++) {
        int n = ty + 8 * i;
        Wt[(size_t)(n0 + n) * K + k0 + tx] = __float2half_rn(s[tx][n]);
    }
}

// ---------------- fused embedding + layernorm -> fp16 hi/lo -------------------
__global__ __launch_bounds__(256) void embed_ln_kernel(const int* __restrict__ idx,
                                                       const float* __restrict__ tok,
                                                       const float* __restrict__ pos,
                                                       const float* __restrict__ g,
                                                       const float* __restrict__ b,
                                                       float* __restrict__ x,
                                                       __half* __restrict__ hi,
                                                       __half* __restrict__ lo) {
    int row = blockIdx.x;
    int tid = threadIdx.x;
    int token = idx[row];
    int tp = row % T_;
    size_t rb = (size_t)row * E_;
    float v[3], s = 0.f, sq = 0.f;
#pragma unroll
    for (int i = 0; i < 3; i++) {
        int e = tid + (i << 8);
        float t = tok[(size_t)token * E_ + e] + pos[(size_t)tp * E_ + e];
        x[rb + e] = t;
        v[i] = t; s += t; sq += t * t;
    }
#pragma unroll
    for (int o = 16; o > 0; o >>= 1) {
        s  += __shfl_xor_sync(0xffffffffu, s, o);
        sq += __shfl_xor_sync(0xffffffffu, sq, o);
    }
    __shared__ float ss[8], ssq[8];
    if ((tid & 31) == 0) { ss[tid >> 5] = s; ssq[tid >> 5] = sq; }
    __syncthreads();
    s = 0.f; sq = 0.f;
#pragma unroll
    for (int i = 0; i < 8; i++) { s += ss[i]; sq += ssq[i]; }
    float mean = s * (1.f / E_);
    float var  = sq * (1.f / E_) - mean * mean;
    float rstd = rsqrtf(var + 1e-5f);
#pragma unroll
    for (int i = 0; i < 3; i++) {
        int e = tid + (i << 8);
        float y = (v[i] - mean) * rstd * g[e] + b[e];
        __half h = __float2half_rn(y);
        hi[rb + e] = h;
        lo[rb + e] = __float2half_rn(y - __half2float(h));
    }
}

// ---------------- fused split-K reduce + residual + layernorm ----------------
template<int WRITE_LO>
__global__ __launch_bounds__(256) void reduce_ln_kernel(const float* __restrict__ parts,
                                                        int nsplit,
                                                        const float* __restrict__ bias,
                                                        float* __restrict__ x,
                                                        const float* __restrict__ g,
                                                        const float* __restrict__ b,
                                                        __half* __restrict__ hi,
                                                        __half* __restrict__ lo) {
    int row = blockIdx.x, tid = threadIdx.x;
    size_t rb = (size_t)row * E_;
    const size_t plane = (size_t)BT * E_;
    float v[3], s = 0.f, sq = 0.f;
#pragma unroll
    for (int i = 0; i < 3; i++) {
        int e = tid + (i << 8);
        size_t ix = rb + e;
        float t = parts[ix];
        for (int p = 1; p < nsplit; p++) t += parts[plane * p + ix];
        t += bias[e] + x[ix];
        x[ix] = t;
        v[i] = t; s += t; sq += t * t;
    }
#pragma unroll
    for (int o = 16; o > 0; o >>= 1) {
        s  += __shfl_xor_sync(0xffffffffu, s, o);
        sq += __shfl_xor_sync(0xffffffffu, sq, o);
    }
    __shared__ float ss[8], ssq[8];
    if ((tid & 31) == 0) { ss[tid >> 5] = s; ssq[tid >> 5] = sq; }
    __syncthreads();
    s = 0.f; sq = 0.f;
#pragma unroll
    for (int i = 0; i < 8; i++) { s += ss[i]; sq += ssq[i]; }
    float mean = s * (1.f / E_);
    float var  = sq * (1.f / E_) - mean * mean;
    float rstd = rsqrtf(var + 1e-5f);
#pragma unroll
    for (int i = 0; i < 3; i++) {
        int e = tid + (i << 8);
        float y = (v[i] - mean) * rstd * g[e] + b[e];
        __half h = __float2half_rn(y);
        hi[rb + e] = h;
        if (WRITE_LO)
            lo[rb + e] = __float2half_rn(y - __half2float(h));
    }
}

// ---------------- fp16 tensor-core GEMM (1/2 sweeps, 4 stages) ----------------
#define LSTG 24576
#define GEMM_H_SMEM (4 * LSTG)
__global__ __launch_bounds__(256, 2)
void gemm_h_kernel(const __half* __restrict__ Ahi,
                   const __half* __restrict__ Alo,
                   const __half* __restrict__ Bt,
                   const float* __restrict__ bias,
                   float* __restrict__ C,
                   __half* __restrict__ Chi,
                   __half* __restrict__ Clo,
                   float* __restrict__ Cpart,
                   int N, int K, int kslen, int nsweep, int relu) {
    extern __shared__ __align__(16) char smem[];
    int tid = threadIdx.x, lane = tid & 31, wid = tid >> 5;
    int wm = wid >> 2, wn = wid & 3;
    int row0 = blockIdx.y << 7, col0 = blockIdx.x << 7;
    int k0base = blockIdx.z * kslen;
    uint32_t sb = smem_u32(smem);

    float acc[4][4][4] = {};
    const int nCh = kslen >> 5;
    int frow = tid >> 1;
    int fc0 = (tid & 1) << 1;
    uint32_t fsw = (uint32_t)((frow >> 1) & 3);

    auto loadStage = [&](int stg, int c) {
        if (c < nCh) {
            uint32_t st = sb + stg * LSTG;
            int k0 = k0base + (c << 5);
            size_t abase = (size_t)(row0 + frow) * K + k0;
            size_t bbase = (size_t)(col0 + frow) * K + k0;
#pragma unroll
            for (int cc = 0; cc < 2; cc++) {
                int cl = fc0 + cc;
                uint32_t doff = (uint32_t)(frow << 6) + (((uint32_t)cl ^ fsw) << 4);
                cpasync16(st + doff,         Ahi + abase + (cl << 3));
                if (nsweep > 1)
                    cpasync16(st + 8192 + doff, Alo + abase + (cl << 3));
                cpasync16(st + 16384 + doff, Bt + bbase + (cl << 3));
            }
        }
        asm volatile("cp.async.commit_group;" ::: "memory");
    };

    int arow[4], brow[2];
    uint32_t asw[4], bsw[2];
#pragma unroll
    for (int mf = 0; mf < 4; mf++) {
        arow[mf] = (wm << 6) + (mf << 4) + (lane & 15);
        asw[mf] = (uint32_t)((arow[mf] >> 1) & 3);
    }
#pragma unroll
    for (int g = 0; g < 2; g++) {
        brow[g] = (wn << 5) + (g << 4) + (lane & 7) + (((lane >> 3) & 1) << 3);
        bsw[g] = (uint32_t)((brow[g] >> 1) & 3);
    }
    int kc = lane >> 4;

    loadStage(0, 0);
    loadStage(1, 1);
    loadStage(2, 2);

    int stg = 0;
    for (int c = 0; c < nCh; ++c) {
        asm volatile("cp.async.wait_group 2;" ::: "memory");
        __syncthreads();
        loadStage((stg + 3) & 3, c + 3);
        uint32_t st = sb + stg * LSTG;
#pragma unroll
        for (int ks = 0; ks < 2; ks++) {
            int cl = (ks << 1) + kc;
            uint32_t ah[4][4], bb[2][4];
#pragma unroll
            for (int mf = 0; mf < 4; mf++)
                ldsm4(ah[mf], st + (uint32_t)(arow[mf] << 6) + (((uint32_t)cl ^ asw[mf]) << 4));
#pragma unroll
            for (int g = 0; g < 2; g++)
                ldsm4(bb[g], st + 16384 + (uint32_t)(brow[g] << 6) + (((uint32_t)cl ^ bsw[g]) << 4));
#pragma unroll
            for (int mf = 0; mf < 4; mf++)
#pragma unroll
                for (int nf = 0; nf < 4; nf++)
                    mma16816h(acc[mf][nf], ah[mf], bb[nf >> 1][nf & 1], bb[nf >> 1][(nf & 1) + 2]);
            if (nsweep > 1) {
                uint32_t al[4][4];
#pragma unroll
                for (int mf = 0; mf < 4; mf++)
                    ldsm4(al[mf], st + 8192 + (uint32_t)(arow[mf] << 6) + (((uint32_t)cl ^ asw[mf]) << 4));
#pragma unroll
                for (int mf = 0; mf < 4; mf++)
#pragma unroll
                    for (int nf = 0; nf < 4; nf++)
                        mma16816h(acc[mf][nf], al[mf], bb[nf >> 1][nf & 1], bb[nf >> 1][(nf & 1) + 2]);
            }
        }
        stg = (stg + 1) & 3;
    }

    if (Cpart) {
        size_t plane = (size_t)blockIdx.z * (((size_t)gridDim.y << 7) * (size_t)N);
#pragma unroll
        for (int mf = 0; mf < 4; mf++) {
            int rbase = row0 + (wm << 6) + (mf << 4) + (lane >> 2);
#pragma unroll
            for (int nf = 0; nf < 4; nf++) {
                int cb = col0 + (wn << 5) + (nf << 3) + ((lane & 3) << 1);
#pragma unroll
                for (int half = 0; half < 2; half++) {
                    int r = rbase + (half << 3);
                    *(float2*)(Cpart + plane + (size_t)r * N + cb) =
                        make_float2(acc[mf][nf][half * 2], acc[mf][nf][half * 2 + 1]);
                }
            }
        }
        return;
    }
#pragma unroll
    for (int mf = 0; mf < 4; mf++) {
        int rbase = row0 + (wm << 6) + (mf << 4) + (lane >> 2);
#pragma unroll
        for (int nf = 0; nf < 4; nf++) {
            int cb = col0 + (wn << 5) + (nf << 3) + ((lane & 3) << 1);
            float b0 = bias ? bias[cb] : 0.f;
            float b1 = bias ? bias[cb + 1] : 0.f;
#pragma unroll
            for (int half = 0; half < 2; half++) {
                int r = rbase + (half << 3);
                float v0 = acc[mf][nf][half * 2 + 0] + b0;
                float v1 = acc[mf][nf][half * 2 + 1] + b1;
                if (relu) { v0 = fmaxf(v0, 0.f); v1 = fmaxf(v1, 0.f); }
                size_t gi = (size_t)r * N + cb;
                if (Chi) {
                    __half2 h = __floats2half2_rn(v0, v1);
                    *(__half2*)(Chi + gi) = h;
                    if (Clo) {
                        float2 hf = __half22float2(h);
                        __half2 l = __floats2half2_rn(v0 - hf.x, v1 - hf.y);
                        *(__half2*)(Clo + gi) = l;
                    }
                } else {
                    *(float2*)(C + gi) = make_float2(v0, v1);
                }
            }
        }
    }
}

// ---------------- tensor-core flash attention (fp16 2-sweep, K/V dbl-buf) ----
// smem 56KB: Qhi 8K, Qlo 8K, K[2] 16K, VS[2] 16K, VT 8K; 3 CTAs/SM by regs.
#define ATT_SMEM 57344
__global__ __launch_bounds__(128)
void attn_kernel(const __half* __restrict__ qkvhi,
                 const __half* __restrict__ qkvlo,
                 __half* __restrict__ ohi,
                 __half* __restrict__ olo) {
    extern __shared__ __align__(16) char smem[];
    uint32_t sb = smem_u32(smem);
    const uint32_t Q_HI = 0, Q_LO = 8192, K_HI = 16384, VS_HI = 32768, VT_HI = 49152;
    int tid = threadIdx.x, lane = tid & 31, w = tid >> 5;
    int qt = (int)gridDim.x - 1 - (int)blockIdx.x;
    int bh = blockIdx.y;
    int bb = bh / H_, hh = bh % H_;
    size_t qrowbase = (size_t)(bb * T_ + (qt << 6));
    const int coff = hh * 64;
    int kc = lane >> 4;

    // ---- load Q tile hi/lo ----
    {
        int r0 = tid >> 1;
        int c0 = (tid & 1) << 2;
        size_t g = (qrowbase + r0) * (size_t)NQKV + coff;
#pragma unroll
        for (int i = 0; i < 4; i++) {
            int c = c0 + i;
            uint32_t d = (uint32_t)(r0 << 7) + (((uint32_t)(c ^ (r0 & 7))) << 4);
            cpasync16(sb + Q_HI + d, qkvhi + g + (c << 3));
            cpasync16(sb + Q_LO + d, qkvlo + g + (c << 3));
        }
        asm volatile("cp.async.commit_group;\n\tcp.async.wait_group 0;" ::: "memory");
    }
    __syncthreads();
    uint32_t qh[4][4], ql[4][4];
    {
        int aRow = (w << 4) + (lane & 15);
#pragma unroll
        for (int ks = 0; ks < 4; ks++) {
            int cl = (ks << 1) + kc;
            uint32_t ad = (uint32_t)(aRow << 7) + (((uint32_t)(cl ^ (aRow & 7))) << 4);
            ldsm4(qh[ks], sb + Q_HI + ad);
            ldsm4(ql[ks], sb + Q_LO + ad);
        }
    }

    // K/VS loads for kv-tile kt2 into buffer buf
    auto loadKV = [&](int kt2, int buf) {
        if (kt2 <= qt) {
            int r0 = tid >> 1;
            int c0 = (tid & 1) << 2;
            size_t kb = (size_t)(bb * T_ + (kt2 << 6));
            size_t gk = (kb + r0) * (size_t)NQKV + E_ + coff;
            size_t gv = (kb + r0) * (size_t)NQKV + 2 * E_ + coff;
            uint32_t boff = (uint32_t)buf << 13;
#pragma unroll
            for (int i = 0; i < 4; i++) {
                int c = c0 + i;
                uint32_t d = (uint32_t)(r0 << 7) + (((uint32_t)(c ^ (r0 & 7))) << 4);
                cpasync16(sb + K_HI + boff + d,  qkvhi + gk + (c << 3));
                cpasync16(sb + VS_HI + boff + d, qkvhi + gv + (c << 3));
            }
        }
        asm volatile("cp.async.commit_group;" ::: "memory");
    };

    float oacc[8][4] = {};
    float m1 = -INFINITY, m2 = -INFINITY, l1 = 0.f, l2 = 0.f;
    int r1 = lane >> 2;
    int rowg1 = (qt << 6) + (w << 4) + r1;
    int rowg2 = rowg1 + 8;

    loadKV(0, 0);

    for (int kt = 0; kt <= qt; kt++) {
        int buf = kt & 1;
        uint32_t boff = (uint32_t)buf << 13;
        asm volatile("cp.async.wait_group 0;" ::: "memory");
        __syncthreads();   // loads(kt) visible; prior iter's VT reads done
        loadKV(kt + 1, buf ^ 1);   // overlap next loads with everything below

        // transpose VS(buf) -> VT
        {
            int kvp = tid & 31;
            int dg0 = tid >> 5;
            int kv = kvp << 1;
#pragma unroll
            for (int t = 0; t < 2; t++) {
                int ch = dg0 + (t << 2);
                int d0 = ch << 3;
                uint32_t a0 = (uint32_t)(kv << 7) + (((uint32_t)ch ^ (uint32_t)(kv & 7)) << 4);
                uint32_t a1 = (uint32_t)((kv + 1) << 7) + (((uint32_t)ch ^ (uint32_t)((kv + 1) & 7)) << 4);
                uint4 h0 = *(const uint4*)(smem + VS_HI + boff + a0);
                uint4 h1 = *(const uint4*)(smem + VS_HI + boff + a1);
                const __half* ph0 = (const __half*)&h0;
                const __half* ph1 = (const __half*)&h1;
#pragma unroll
                for (int j = 0; j < 8; j++) {
                    int d = d0 + j;
                    uint32_t ad = (uint32_t)(d << 7) +
                                  ((((uint32_t)(kvp >> 2) ^ (uint32_t)(d & 7)) << 4)) +
                                  ((uint32_t)(kvp & 3) << 2);
                    __half2 hw; hw.x = ph0[j]; hw.y = ph1[j];
                    *(__half2*)(smem + VT_HI + ad) = hw;
                }
            }
        }
        __syncthreads();

        // ---- S = Q K^T (2-sweep fp16) ----
        float sacc[8][4] = {};
#pragma unroll
        for (int ks = 0; ks < 4; ks++) {
            int cl = (ks << 1) + kc;
            uint32_t kh[4][4];
#pragma unroll
            for (int g = 0; g < 4; g++) {
                int bRow = (g << 4) + (lane & 7) + (((lane >> 3) & 1) << 3);
                uint32_t bd = (uint32_t)(bRow << 7) + (((uint32_t)(cl ^ (bRow & 7))) << 4);
                ldsm4(kh[g], sb + K_HI + boff + bd);
            }
#pragma unroll
            for (int g = 0; g < 4; g++)
#pragma unroll
                for (int nfp = 0; nfp < 2; nfp++)
                    mma16816h(sacc[2 * g + nfp], qh[ks], kh[g][nfp], kh[g][nfp + 2]);
#pragma unroll
            for (int g = 0; g < 4; g++)
#pragma unroll
                for (int nfp = 0; nfp < 2; nfp++)
                    mma16816h(sacc[2 * g + nfp], ql[ks], kh[g][nfp], kh[g][nfp + 2]);
        }
#pragma unroll
        for (int nf = 0; nf < 8; nf++) {
            sacc[nf][0] *= 0.125f; sacc[nf][1] *= 0.125f;
            sacc[nf][2] *= 0.125f; sacc[nf][3] *= 0.125f;
        }
        if (kt == qt) {
#pragma unroll
            for (int nf = 0; nf < 8; nf++) {
                int colb = (kt << 6) + (nf << 3) + ((lane & 3) << 1);
                if (colb > rowg1)     sacc[nf][0] = -INFINITY;
                if (colb + 1 > rowg1) sacc[nf][1] = -INFINITY;
                if (colb > rowg2)     sacc[nf][2] = -INFINITY;
                if (colb + 1 > rowg2) sacc[nf][3] = -INFINITY;
            }
        }
        // ---- online softmax ----
        float t1 = -INFINITY, t2 = -INFINITY;
#pragma unroll
        for (int nf = 0; nf < 8; nf++) {
            t1 = fmaxf(t1, fmaxf(sacc[nf][0], sacc[nf][1]));
            t2 = fmaxf(t2, fmaxf(sacc[nf][2], sacc[nf][3]));
        }
        t1 = fmaxf(t1, __shfl_xor_sync(0xffffffffu, t1, 1));
        t1 = fmaxf(t1, __shfl_xor_sync(0xffffffffu, t1, 2));
        t2 = fmaxf(t2, __shfl_xor_sync(0xffffffffu, t2, 1));
        t2 = fmaxf(t2, __shfl_xor_sync(0xffffffffu, t2, 2));
        float mn1 = fmaxf(m1, t1), mn2 = fmaxf(m2, t2);
        float a1 = __expf(m1 - mn1), a2 = __expf(m2 - mn2);
        float ps1 = 0.f, ps2 = 0.f;
#pragma unroll
        for (int nf = 0; nf < 8; nf++) {
            sacc[nf][0] = __expf(sacc[nf][0] - mn1);
            sacc[nf][1] = __expf(sacc[nf][1] - mn1);
            sacc[nf][2] = __expf(sacc[nf][2] - mn2);
            sacc[nf][3] = __expf(sacc[nf][3] - mn2);
            ps1 += sacc[nf][0] + sacc[nf][1];
            ps2 += sacc[nf][2] + sacc[nf][3];
        }
        ps1 += __shfl_xor_sync(0xffffffffu, ps1, 1);
        ps1 += __shfl_xor_sync(0xffffffffu, ps1, 2);
        ps2 += __shfl_xor_sync(0xffffffffu, ps2, 1);
        ps2 += __shfl_xor_sync(0xffffffffu, ps2, 2);
        l1 = l1 * a1 + ps1;
        l2 = l2 * a2 + ps2;
        m1 = mn1; m2 = mn2;
#pragma unroll
        for (int nf = 0; nf < 8; nf++) {
            oacc[nf][0] *= a1; oacc[nf][1] *= a1;
            oacc[nf][2] *= a2; oacc[nf][3] *= a2;
        }
        // ---- O += P V (2-sweep) ----
#pragma unroll
        for (int j = 0; j < 4; j++) {
            uint32_t pah[4], pal[4];
#pragma unroll
            for (int half = 0; half < 2; half++) {
                float x0 = sacc[2 * j + half][0], x1 = sacc[2 * j + half][1];
                float x2 = sacc[2 * j + half][2], x3 = sacc[2 * j + half][3];
                __half2 h01 = __floats2half2_rn(x0, x1);
                __half2 h23 = __floats2half2_rn(x2, x3);
                float2 f01 = __half22float2(h01), f23 = __half22float2(h23);
                __half2 lo01 = __floats2half2_rn(x0 - f01.x, x1 - f01.y);
                __half2 lo23 = __floats2half2_rn(x2 - f23.x, x3 - f23.y);
                pah[2 * half + 0] = *(uint32_t*)&h01;
                pah[2 * half + 1] = *(uint32_t*)&h23;
                pal[2 * half + 0] = *(uint32_t*)&lo01;
                pal[2 * half + 1] = *(uint32_t*)&lo23;
            }
            int cl = (j << 1) + kc;
            uint32_t vh[4][4];
#pragma unroll
            for (int g = 0; g < 4; g++) {
                int bRow = (g << 4) + (lane & 7) + (((lane >> 3) & 1) << 3);
                uint32_t bd = (uint32_t)(bRow << 7) + (((uint32_t)(cl ^ (bRow & 7))) << 4);
                ldsm4(vh[g], sb + VT_HI + bd);
            }
#pragma unroll
            for (int g = 0; g < 4; g++)
#pragma unroll
                for (int nfp = 0; nfp < 2; nfp++)
                    mma16816h(oacc[2 * g + nfp], pah, vh[g][nfp], vh[g][nfp + 2]);
#pragma unroll
            for (int g = 0; g < 4; g++)
#pragma unroll
                for (int nfp = 0; nfp < 2; nfp++)
                    mma16816h(oacc[2 * g + nfp], pal, vh[g][nfp], vh[g][nfp + 2]);
        }
    }

    // ---- output (fp16 hi/lo) ----
    float li1 = 1.f / l1, li2 = 1.f / l2;
    size_t ob1 = (qrowbase + (w << 4) + r1) * (size_t)E_ + coff;
    size_t ob2 = ob1 + (size_t)8 * E_;
#pragma unroll
    for (int nf = 0; nf < 8; nf++) {
        int d = (nf << 3) + ((lane & 3) << 1);
        float v0 = oacc[nf][0] * li1, v1 = oacc[nf][1] * li1;
        __half2 h = __floats2half2_rn(v0, v1);
        float2 hf = __half22float2(h);
        __half2 lo = __floats2half2_rn(v0 - hf.x, v1 - hf.y);
        *(__half2*)(ohi + ob1 + d) = h;
        *(__half2*)(olo + ob1 + d) = lo;
        float v2 = oacc[nf][2] * li2, v3 = oacc[nf][3] * li2;
        __half2 h2 = __floats2half2_rn(v2, v3);
        float2 hf2 = __half22float2(h2);
        __half2 lo2 = __floats2half2_rn(v2 - hf2.x, v3 - hf2.y);
        *(__half2*)(ohi + ob2 + d) = h2;
        *(__half2*)(olo + ob2 + d) = lo2;
    }
}

// ---------------- loss ------------------------------------------------------
__global__ __launch_bounds__(256) void row_lse_kernel(const float* __restrict__ logits,
                                                      const int* __restrict__ targets,
                                                      float* __restrict__ rowloss) {
    int row = blockIdx.x, tid = threadIdx.x;
    const float* lr = logits + (size_t)row * V_;
    float mx = -INFINITY;
    for (int i = tid; i < V_; i += 256) mx = fmaxf(mx, lr[i]);
#pragma unroll
    for (int o = 16; o > 0; o >>= 1) mx = fmaxf(mx, __shfl_xor_sync(0xffffffffu, mx, o));
    __shared__ float sm[8];
    if ((tid & 31) == 0) sm[tid >> 5] = mx;
    __syncthreads();
    float m2 = -INFINITY;
#pragma unroll
    for (int i = 0; i < 8; i++) m2 = fmaxf(m2, sm[i]);
    float se = 0.f;
    for (int i = tid; i < V_; i += 256) se += __expf(lr[i] - m2);
#pragma unroll
    for (int o = 16; o > 0; o >>= 1) se += __shfl_xor_sync(0xffffffffu, se, o);
    __shared__ float ssum[8];
    if ((tid & 31) == 0) ssum[tid >> 5] = se;
    __syncthreads();
    if (tid == 0) {
        float tot = 0.f;
#pragma unroll
        for (int i = 0; i < 8; i++) tot += ssum[i];
        rowloss[row] = (logf(tot) + m2) - lr[targets[row]];
    }
}

__global__ __launch_bounds__(256) void loss_reduce_kernel(const float* __restrict__ rowloss,
                                                          float* __restrict__ out) {
    int tid = threadIdx.x;
    float s = 0.f;
    for (int i = tid; i < BT; i += 256) s += rowloss[i];
#pragma unroll
    for (int o = 16; o > 0; o >>= 1) s += __shfl_xor_sync(0xffffffffu, s, o);
    __shared__ float sm[8];
    if ((tid & 31) == 0) sm[tid >> 5] = s;
    __syncthreads();
    if (tid == 0) {
        float t = 0.f;
#pragma unroll
        for (int i = 0; i < 8; i++) t += sm[i];
        out[0] = t * (1.f / BT);
    }
}

// ---------------- launch ----------------------------------------------------
extern "C" void kernel_launch(void* const* d_in, const int* in_sizes, int n_in,
                              void* d_out, int out_size) {
    const int*   idx     = (const int*)d_in[0];
    const int*   targets = (const int*)d_in[1];
    const float* tok_emb = (const float*)d_in[2];
    const float* pos_emb = (const float*)d_in[3];
    const float* Wq  = (const float*)d_in[4];
    const float* bq  = (const float*)d_in[5];
    const float* Wk  = (const float*)d_in[6];
    const float* bk  = (const float*)d_in[7];
    const float* Wv  = (const float*)d_in[8];
    const float* bv  = (const float*)d_in[9];
    const float* Wo  = (const float*)d_in[10];
    const float* bo  = (const float*)d_in[11];
    const float* ln1g = (const float*)d_in[12];
    const float* ln1b = (const float*)d_in[13];
    const float* W1  = (const float*)d_in[14];
    const float* b1  = (const float*)d_in[15];
    const float* W2  = (const float*)d_in[16];
    const float* b2  = (const float*)d_in[17];
    const float* ln2g = (const float*)d_in[18];
    const float* ln2b = (const float*)d_in[19];
    const float* lnfg = (const float*)d_in[20];
    const float* lnfb = (const float*)d_in[21];
    const float* Wlm = (const float*)d_in[22];
    const float* blm = (const float*)d_in[23];
    float* out = (float*)d_out;

    float *px, *pbqkv, *ppart, *prl, *plg;
    __half *pqkvhi, *pqkvlo, *phhi, *phlo, *pohi, *polo, *pffhi, *pwth, *pwlmh;
    cudaGetSymbolAddress((void**)&px,     g_x);
    cudaGetSymbolAddress((void**)&pqkvhi, g_qkvhi);
    cudaGetSymbolAddress((void**)&pqkvlo, g_qkvlo);
    cudaGetSymbolAddress((void**)&phhi,   g_hhi);
    cudaGetSymbolAddress((void**)&phlo,   g_hlo);
    cudaGetSymbolAddress((void**)&pohi,   g_ohi);
    cudaGetSymbolAddress((void**)&polo,   g_olo);
    cudaGetSymbolAddress((void**)&pffhi,  g_ffhi);
    cudaGetSymbolAddress((void**)&pbqkv,  g_bqkv);
    cudaGetSymbolAddress((void**)&ppart,  g_part);
    cudaGetSymbolAddress((void**)&pwth,   g_wth);
    cudaGetSymbolAddress((void**)&pwlmh,  g_wlmh);
    cudaGetSymbolAddress((void**)&prl,    g_rowloss);
    cudaGetSymbolAddress((void**)&plg,    g_logits_scratch);

    cudaFuncSetAttribute(gemm_h_kernel, cudaFuncAttributeMaxDynamicSharedMemorySize, GEMM_H_SMEM);
    cudaFuncSetAttribute(attn_kernel,   cudaFuncAttributeMaxDynamicSharedMemorySize, ATT_SMEM);

    const long long NLOG = (long long)BT * V_;
    float* logits = (out_size >= NLOG) ? out : plg;

    dim3 cb(32, 8);
    dim3 gQKVw(E_ / 32, NQKV / 32);
    dim3 gQKV(NQKV / 128, BT / 128);
    dim3 gWo(E_ / 128, BT / 128, 3);
    dim3 gW1(FF / 128, BT / 128);        // un-split: direct relu+fp16 epilogue
    dim3 gW2(E_ / 128, BT / 128, 3);
    dim3 gVd(V_ / 128, BT / 128);
    dim3 gAttn(T_ / 64, B_ * H_);

    for (int l = 0; l < L_; l++) {
        if (l == 0)
            embed_ln_kernel<<<BT, 256>>>(idx, tok_emb, pos_emb, ln1g, ln1b, px, phhi, phlo); // 0
        wconv_qkv_kernel<<<gQKVw, cb>>>(Wq, Wk, Wv, bq, bk, bv,
                                        pwth + OFF_QKV(l), pbqkv, l);                        // 1
        gemm_h_kernel<<<gQKV, 256, GEMM_H_SMEM>>>(phhi, phlo, pwth + OFF_QKV(l),             // 2
            pbqkv + l * NQKV, nullptr, pqkvhi, pqkvlo, nullptr, NQKV, E_, E_, 2, 0);
        attn_kernel<<<gAttn, 128, ATT_SMEM>>>(pqkvhi, pqkvlo, pohi, polo);                   // 3 (= global 5)
        wconvt_h_kernel<<<dim3(E_ / 32, E_ / 32), cb>>>(Wo + (size_t)l * E_ * E_,
            pwth + OFF_O(l), E_, E_);
        gemm_h_kernel<<<gWo, 256, GEMM_H_SMEM>>>(pohi, polo, pwth + OFF_O(l),
            nullptr, nullptr, nullptr, nullptr, ppart, E_, E_, 256, 2, 0);
        reduce_ln_kernel<0><<<BT, 256>>>(ppart, 3, bo + l * E_, px,
                                         ln2g + l * E_, ln2b + l * E_, phhi, nullptr);
        wconvt_h_kernel<<<dim3(FF / 32, E_ / 32), cb>>>(W1 + (size_t)l * E_ * FF,
            pwth + OFF_W1(l), E_, FF);
        gemm_h_kernel<<<gW1, 256, GEMM_H_SMEM>>>(phhi, nullptr, pwth + OFF_W1(l),
            b1 + l * FF, nullptr, pffhi, nullptr, nullptr, FF, E_, E_, 1, 1);
        wconvt_h_kernel<<<dim3(E_ / 32, FF / 32), cb>>>(W2 + (size_t)l * FF * E_,
            pwth + OFF_W2(l), FF, E_);
        gemm_h_kernel<<<gW2, 256, GEMM_H_SMEM>>>(pffhi, nullptr, pwth + OFF_W2(l),
            nullptr, nullptr, nullptr, nullptr, ppart, E_, FF, 1024, 1, 0);
        if (l < L_ - 1)
            reduce_ln_kernel<1><<<BT, 256>>>(ppart, 3, b2 + l * E_, px,
                                             ln1g + (l + 1) * E_, ln1b + (l + 1) * E_, phhi, phlo);
        else
            reduce_ln_kernel<0><<<BT, 256>>>(ppart, 3, b2 + l * E_, px,
                                             lnfg, lnfb, phhi, nullptr);
    }
    wconvt_h_kernel<<<dim3(V_ / 32, E_ / 32), cb>>>(Wlm, pwlmh, E_, V_);
    gemm_h_kernel<<<gVd, 256, GEMM_H_SMEM>>>(phhi, nullptr, pwlmh, blm,
                                             logits, nullptr, nullptr, nullptr, V_, E_, E_, 1, 0);

    // --- loss ---
    float* loss_dst = nullptr;
    if (out_size == 1)        loss_dst = out;
    else if (out_size > NLOG) loss_dst = out + NLOG;
    if (loss_dst) {
        row_lse_kernel<<<BT, 256>>>(logits, targets, prl);
        loss_reduce_kernel<<<1, 256>>>(prl, loss_dst);
    }
}